// round 12
// baseline (speedup 1.0000x reference)
#include <cuda_runtime.h>

#define B_ 8
#define C_ 256
#define L_ 4096
#define NH_ 4
#define D_ 64
#define NB_ 64   // number of query/key blocks (L/64)
#define T_ 6     // top-k blocks
#define BH_ 32   // B*NH

// ---------------- scratch (device globals; no allocs) ----------------
__device__ float g_xth[(size_t)B_*C_*L_];  // x^T hi split: [b][l][c]
__device__ float g_xtl[(size_t)B_*C_*L_];  // x^T lo split
__device__ float g_wqh[768*256], g_wql[768*256];
__device__ float g_w2h[256*256], g_w2l[256*256];
__device__ float g_q [BH_*L_*D_];
__device__ float g_k [BH_*L_*D_];
__device__ float g_v [BH_*L_*D_];
__device__ float g_cq[BH_*L_*D_];
__device__ float g_ck[BH_*L_*D_];
__device__ float g_qb[BH_*NB_*D_];
__device__ float g_kb[BH_*NB_*D_];
__device__ int   g_lut[BH_*NB_*T_];
__device__ float g_kvb[(size_t)BH_*NB_*D_*D_];
__device__ float g_ksum[BH_*NB_*D_];
__device__ float g_kvt[BH_*D_*D_];
__device__ float g_kst[BH_*D_];
__device__ float g_obuf[BH_*L_*D_];   // o_s from sattn (fp32)
__device__ float g_olin[BH_*L_*D_];   // o_l + bias from k_lin (fp32)

// ---------------- tf32 mma helpers ----------------
__device__ __forceinline__ unsigned f2tf(float f) {
    unsigned u; asm("cvt.rna.tf32.f32 %0, %1;" : "=r"(u) : "f"(f)); return u;
}
__device__ __forceinline__ void mma8(float d[4], const unsigned a[4], const unsigned b[2]) {
    asm("mma.sync.aligned.m16n8k8.row.col.f32.tf32.tf32.f32 "
        "{%0,%1,%2,%3}, {%4,%5,%6,%7}, {%8,%9}, {%0,%1,%2,%3};"
        : "+f"(d[0]), "+f"(d[1]), "+f"(d[2]), "+f"(d[3])
        : "r"(a[0]), "r"(a[1]), "r"(a[2]), "r"(a[3]), "r"(b[0]), "r"(b[1]));
}
__device__ __forceinline__ void split2(float x, float& hi, float& lo) {
    hi = __uint_as_float(f2tf(x));
    lo = __uint_as_float(f2tf(x - hi));
}
__device__ __forceinline__ float tfb(float x) {   // tf32 bits stored as float
    return __uint_as_float(f2tf(x));
}

// ---------------- K0a: transpose + split x -> g_xth/g_xtl [b][l][c] ----------------
__global__ void k_xT(const float* __restrict__ x) {
    __shared__ float t[32][33];
    const int b = blockIdx.z, l0 = blockIdx.x * 32, c0 = blockIdx.y * 32;
    const int tx = threadIdx.x, ty = threadIdx.y;
    const float* xb = x + (size_t)b * C_ * L_;
#pragma unroll
    for (int i = 0; i < 32; i += 8)
        t[ty + i][tx] = xb[(size_t)(c0 + ty + i) * L_ + l0 + tx];
    __syncthreads();
    float* dh = g_xth + (size_t)b * L_ * C_;
    float* dl = g_xtl + (size_t)b * L_ * C_;
#pragma unroll
    for (int i = 0; i < 32; i += 8) {
        float h, lo; split2(t[tx][ty + i], h, lo);
        dh[(size_t)(l0 + ty + i) * C_ + c0 + tx] = h;
        dl[(size_t)(l0 + ty + i) * C_ + c0 + tx] = lo;
    }
}

// ---------------- K0b: split the weights once ----------------
__global__ void k_wsplit(const float* __restrict__ qkv_w, const float* __restrict__ out_w) {
    const int i = blockIdx.x * 256 + threadIdx.x;   // grid covers 262144
    float h, lo;
    if (i < 768 * 256) {
        split2(qkv_w[i], h, lo); g_wqh[i] = h; g_wql[i] = lo;
    } else {
        const int j = i - 768 * 256;
        split2(out_w[j], h, lo); g_w2h[j] = h; g_w2l[j] = lo;
    }
}

// ---------------- K1: fused qkv for ONE head: 3 output tiles share the A tile ----------------
#define GSTR 36
#define QAH 0
#define QAL (64*GSTR)
#define QBH(p) (2*64*GSTR + (p)*64*GSTR)   // p = 0,1,2
#define QBL(p) (5*64*GSTR + (p)*64*GSTR)   // p = 0,1
#define QRED  (7*64*GSTR)
#define QREDS (QRED + 128)
#define QWSUM (QREDS + 128)
#define QKV_SMEM_FLOATS (QWSUM + 512)      // 16896 floats = 67584 B

__global__ void __launch_bounds__(256) k_qkv_tc() {
    extern __shared__ float qs[];
    float* Ah = qs + QAH;
    float* Al = qs + QAL;
    float* redm = qs + QRED;
    float* reds = qs + QREDS;
    float (*wsum)[64] = reinterpret_cast<float(*)[64]>(qs + QWSUM);
    const int b = blockIdx.z, l0 = blockIdx.x * 64, hh = blockIdx.y;
    const int tid = threadIdx.x, w8 = tid >> 5, lane = tid & 31;
    const int gid = lane >> 2, tig = lane & 3;
    const int m0 = (w8 >> 1) * 16, ch = w8 & 1, n0c = ch * 32;
    const int lrow = tid >> 3, cq = (tid & 7) * 4;
    const float* ahs = g_xth + (size_t)b * L_ * C_;
    const float* als = g_xtl + (size_t)b * L_ * C_;
    float acc[3][4][4] = {};
    const int ra = m0 + gid, rb = ra + 8;

    for (int c0 = 0; c0 < C_; c0 += 32) {
#pragma unroll
        for (int r = lrow; r < 64; r += 32) {
            *reinterpret_cast<float4*>(&Ah[r*GSTR+cq]) =
                *reinterpret_cast<const float4*>(&ahs[(size_t)(l0 + r) * C_ + c0 + cq]);
            *reinterpret_cast<float4*>(&Al[r*GSTR+cq]) =
                *reinterpret_cast<const float4*>(&als[(size_t)(l0 + r) * C_ + c0 + cq]);
        }
#pragma unroll
        for (int p = 0; p < 3; p++) {
            const float* wh = g_wqh + (size_t)(p * 256 + hh * 64) * C_;
            float* Bp = qs + QBH(p);
#pragma unroll
            for (int r = lrow; r < 64; r += 32)
                *reinterpret_cast<float4*>(&Bp[r*GSTR+cq]) =
                    *reinterpret_cast<const float4*>(&wh[(size_t)r * C_ + c0 + cq]);
        }
#pragma unroll
        for (int p = 0; p < 2; p++) {
            const float* wl = g_wql + (size_t)(p * 256 + hh * 64) * C_;
            float* Bp = qs + QBL(p);
#pragma unroll
            for (int r = lrow; r < 64; r += 32)
                *reinterpret_cast<float4*>(&Bp[r*GSTR+cq]) =
                    *reinterpret_cast<const float4*>(&wl[(size_t)r * C_ + c0 + cq]);
        }
        __syncthreads();
#pragma unroll
        for (int kk = 0; kk < 32; kk += 8) {
            unsigned ah[4], al[4];
            ah[0] = __float_as_uint(Ah[ra*GSTR + kk + tig]);
            ah[1] = __float_as_uint(Ah[rb*GSTR + kk + tig]);
            ah[2] = __float_as_uint(Ah[ra*GSTR + kk + tig + 4]);
            ah[3] = __float_as_uint(Ah[rb*GSTR + kk + tig + 4]);
            al[0] = __float_as_uint(Al[ra*GSTR + kk + tig]);
            al[1] = __float_as_uint(Al[rb*GSTR + kk + tig]);
            al[2] = __float_as_uint(Al[ra*GSTR + kk + tig + 4]);
            al[3] = __float_as_uint(Al[rb*GSTR + kk + tig + 4]);
#pragma unroll
            for (int p = 0; p < 2; p++) {
                const float* Bh = qs + QBH(p);
                const float* Bl = qs + QBL(p);
#pragma unroll
                for (int j = 0; j < 4; j++) {
                    const int br = (n0c + 8*j + gid) * GSTR + kk + tig;
                    unsigned bh2[2], bl2[2];
                    bh2[0] = __float_as_uint(Bh[br]); bh2[1] = __float_as_uint(Bh[br + 4]);
                    bl2[0] = __float_as_uint(Bl[br]); bl2[1] = __float_as_uint(Bl[br + 4]);
                    mma8(acc[p][j], ah, bh2);
                    mma8(acc[p][j], ah, bl2);
                    mma8(acc[p][j], al, bh2);
                }
            }
            {
                const float* Bh = qs + QBH(2);
#pragma unroll
                for (int j = 0; j < 4; j++) {
                    const int br = (n0c + 8*j + gid) * GSTR + kk + tig;
                    unsigned bh2[2];
                    bh2[0] = __float_as_uint(Bh[br]); bh2[1] = __float_as_uint(Bh[br + 4]);
                    mma8(acc[2][j], ah, bh2);
                }
            }
        }
        __syncthreads();
    }

    // ---- store q, k, v tiles ----
#pragma unroll
    for (int p = 0; p < 3; p++) {
        float* dst = ((p == 0) ? g_q : (p == 1) ? g_k : g_v) + (size_t)(b * NH_ + hh) * L_ * D_;
#pragma unroll
        for (int j = 0; j < 4; j++) {
            *reinterpret_cast<float2*>(&dst[(size_t)(l0 + ra) * D_ + n0c + 8*j + 2*tig]) =
                make_float2(acc[p][j][0], acc[p][j][1]);
            *reinterpret_cast<float2*>(&dst[(size_t)(l0 + rb) * D_ + n0c + 8*j + 2*tig]) =
                make_float2(acc[p][j][2], acc[p][j][3]);
        }
    }

    // ---- block means + feature map for q (p=0) and k (p=1) ----
#pragma unroll
    for (int p = 0; p < 2; p++) {
#pragma unroll
        for (int j = 0; j < 4; j++) {
            float s0 = acc[p][j][0] + acc[p][j][2];
            float s1 = acc[p][j][1] + acc[p][j][3];
            s0 += __shfl_xor_sync(0xffffffffu, s0, 4);
            s0 += __shfl_xor_sync(0xffffffffu, s0, 8);
            s0 += __shfl_xor_sync(0xffffffffu, s0, 16);
            s1 += __shfl_xor_sync(0xffffffffu, s1, 4);
            s1 += __shfl_xor_sync(0xffffffffu, s1, 8);
            s1 += __shfl_xor_sync(0xffffffffu, s1, 16);
            if (gid == 0) {
                wsum[w8][n0c + 8*j + 2*tig]     = s0;
                wsum[w8][n0c + 8*j + 2*tig + 1] = s1;
            }
        }
        __syncthreads();
        if (tid < 64) {
            const int c2 = tid >> 5;
            float s = wsum[c2][tid] + wsum[c2 + 2][tid] + wsum[c2 + 4][tid] + wsum[c2 + 6][tid];
            float* bdst = (p == 0) ? g_qb : g_kb;
            bdst[((size_t)(b * NH_ + hh) * NB_ + blockIdx.x) * D_ + tid] = s * (1.f / 64.f);
        }
        float wma = fmaxf(fmaxf(acc[p][0][0], acc[p][0][1]), fmaxf(acc[p][1][0], acc[p][1][1]));
        wma = fmaxf(wma, fmaxf(fmaxf(acc[p][2][0], acc[p][2][1]), fmaxf(acc[p][3][0], acc[p][3][1])));
        float wmb = fmaxf(fmaxf(acc[p][0][2], acc[p][0][3]), fmaxf(acc[p][1][2], acc[p][1][3]));
        wmb = fmaxf(wmb, fmaxf(fmaxf(acc[p][2][2], acc[p][2][3]), fmaxf(acc[p][3][2], acc[p][3][3])));
        wma = fmaxf(wma, __shfl_xor_sync(0xffffffffu, wma, 1));
        wma = fmaxf(wma, __shfl_xor_sync(0xffffffffu, wma, 2));
        wmb = fmaxf(wmb, __shfl_xor_sync(0xffffffffu, wmb, 1));
        wmb = fmaxf(wmb, __shfl_xor_sync(0xffffffffu, wmb, 2));
        if (tig == 0) { redm[ch * 64 + ra] = wma; redm[ch * 64 + rb] = wmb; }
        __syncthreads();
        float Ma = fmaxf(wma, redm[(ch ^ 1) * 64 + ra]);
        float Mb = fmaxf(wmb, redm[(ch ^ 1) * 64 + rb]);
        float ex[4][4];
        float sa = 0.f, sb = 0.f;
#pragma unroll
        for (int j = 0; j < 4; j++) {
            ex[j][0] = __expf(acc[p][j][0] - Ma);
            ex[j][1] = __expf(acc[p][j][1] - Ma);
            ex[j][2] = __expf(acc[p][j][2] - Mb);
            ex[j][3] = __expf(acc[p][j][3] - Mb);
            sa += ex[j][0] + ex[j][1];
            sb += ex[j][2] + ex[j][3];
        }
        sa += __shfl_xor_sync(0xffffffffu, sa, 1);
        sa += __shfl_xor_sync(0xffffffffu, sa, 2);
        sb += __shfl_xor_sync(0xffffffffu, sb, 1);
        sb += __shfl_xor_sync(0xffffffffu, sb, 2);
        if (tig == 0) { reds[ch * 64 + ra] = sa; reds[ch * 64 + rb] = sb; }
        __syncthreads();
        const float ia = 1.f / (sa + reds[(ch ^ 1) * 64 + ra]);
        const float ib = 1.f / (sb + reds[(ch ^ 1) * 64 + rb]);
        float* cdst = ((p == 0) ? g_cq : g_ck) + (size_t)(b * NH_ + hh) * L_ * D_;
#pragma unroll
        for (int j = 0; j < 4; j++) {
            *reinterpret_cast<float2*>(&cdst[(size_t)(l0 + ra) * D_ + n0c + 8*j + 2*tig]) =
                make_float2(ex[j][0] * ia, ex[j][1] * ia);
            *reinterpret_cast<float2*>(&cdst[(size_t)(l0 + rb) * D_ + n0c + 8*j + 2*tig]) =
                make_float2(ex[j][2] * ib, ex[j][3] * ib);
        }
        __syncthreads();
    }
}

// ---------------- K3: scores + top-6, one warp per query row ----------------
__global__ void __launch_bounds__(256) k_topk() {
    __shared__ float kb[64][65];
    __shared__ float qb8[8][64];
    const int bh = blockIdx.x, rg = blockIdx.y;
    const int tid = threadIdx.x, w = tid >> 5, lane = tid & 31;
    for (int i = tid; i < 4096; i += 256) kb[i >> 6][i & 63] = g_kb[(size_t)bh * 4096 + i];
    for (int i = tid; i < 512; i += 256) qb8[i >> 6][i & 63] = g_qb[(size_t)bh * 4096 + rg * 512 + i];
    __syncthreads();
    float s0 = 0.f, s1 = 0.f;
#pragma unroll 8
    for (int d = 0; d < 64; d++) {
        float qv = qb8[w][d];
        s0 += qv * kb[lane][d];
        s1 += qv * kb[lane + 32][d];
    }
    const int r = rg * 8 + w;
    int* lp = g_lut + ((size_t)bh * NB_ + r) * T_;
#pragma unroll
    for (int t = 0; t < T_; t++) {
        float v; int idx;
        if (s0 >= s1) { v = s0; idx = lane; } else { v = s1; idx = lane + 32; }
#pragma unroll
        for (int o = 16; o; o >>= 1) {
            float ov = __shfl_xor_sync(0xffffffffu, v, o);
            int   oi = __shfl_xor_sync(0xffffffffu, idx, o);
            if (ov > v || (ov == v && oi < idx)) { v = ov; idx = oi; }
        }
        if (lane == 0) lp[t] = idx;
        if (idx == lane) s0 = -3.4e38f;
        else if (idx == lane + 32) s1 = -3.4e38f;
    }
}

// ---------------- K4: sparse attention, tf32 mma, pre-converted smem ----------------
#define QS_OFF 0
#define KS_OFF (64*68)
#define VS_OFF (2*64*68)
#define RM_OFF (2*64*68 + 64*72)
#define RS_OFF (RM_OFF + 2*64)
#define SATTN_SMEM_FLOATS (RS_OFF + 2*64)

__global__ void __launch_bounds__(256, 3) k_sattn() {
    extern __shared__ float sm[];
    float* Qs = sm + QS_OFF;
    float* Ks = sm + KS_OFF;
    float* Vs = sm + VS_OFF;
    float* redm = sm + RM_OFF;
    float* reds = sm + RS_OFF;
    __shared__ int luts[8];
    const int n = blockIdx.x, bh = blockIdx.y;
    const int tid = threadIdx.x;
    const int w = tid >> 5, lane = tid & 31;
    const int gid = lane >> 2, tig = lane & 3;
    const int m0 = (w >> 1) * 16;
    const int ch = w & 1;
    const int n0c = ch * 32;

    const float* qp = g_q + ((size_t)bh * L_ + n * 64) * D_;
    for (int i = tid * 4; i < 4096; i += 1024) {
        int r = i >> 6, d = i & 63;
        float4 v = *reinterpret_cast<const float4*>(&qp[i]);
        Qs[r * 68 + d + 0] = tfb(v.x); Qs[r * 68 + d + 1] = tfb(v.y);
        Qs[r * 68 + d + 2] = tfb(v.z); Qs[r * 68 + d + 3] = tfb(v.w);
    }
    if (tid < T_) luts[tid] = g_lut[((size_t)bh * NB_ + n) * T_ + tid];
    __syncthreads();

    float oacc[4][4] = {};
    float m_a = -1e30f, m_b = -1e30f, l_a = 0.f, l_b = 0.f;
    const int ra = m0 + gid, rb = m0 + gid + 8;

    for (int t = 0; t < T_; t++) {
        const float* kp = g_k + ((size_t)bh * L_ + luts[t] * 64) * D_;
        const float* vp = g_v + ((size_t)bh * L_ + luts[t] * 64) * D_;
        for (int i = tid * 4; i < 4096; i += 1024) {
            int r = i >> 6, d = i & 63;
            float4 kv = *reinterpret_cast<const float4*>(&kp[i]);
            Ks[r * 68 + d + 0] = tfb(kv.x); Ks[r * 68 + d + 1] = tfb(kv.y);
            Ks[r * 68 + d + 2] = tfb(kv.z); Ks[r * 68 + d + 3] = tfb(kv.w);
            float4 vv = *reinterpret_cast<const float4*>(&vp[i]);
            Vs[r * 72 + d + 0] = tfb(vv.x); Vs[r * 72 + d + 1] = tfb(vv.y);
            Vs[r * 72 + d + 2] = tfb(vv.z); Vs[r * 72 + d + 3] = tfb(vv.w);
        }
        __syncthreads();

        float sacc[4][4] = {};
#pragma unroll
        for (int kk = 0; kk < 64; kk += 8) {
            unsigned a[4];
            a[0] = __float_as_uint(Qs[ra * 68 + kk + tig]);
            a[1] = __float_as_uint(Qs[rb * 68 + kk + tig]);
            a[2] = __float_as_uint(Qs[ra * 68 + kk + tig + 4]);
            a[3] = __float_as_uint(Qs[rb * 68 + kk + tig + 4]);
#pragma unroll
            for (int j = 0; j < 4; j++) {
                unsigned b[2];
                b[0] = __float_as_uint(Ks[(n0c + 8 * j + gid) * 68 + kk + tig]);
                b[1] = __float_as_uint(Ks[(n0c + 8 * j + gid) * 68 + kk + tig + 4]);
                mma8(sacc[j], a, b);
            }
        }
#pragma unroll
        for (int j = 0; j < 4; j++)
#pragma unroll
            for (int r = 0; r < 4; r++) sacc[j][r] *= 0.125f;

        float wma = fmaxf(fmaxf(sacc[0][0], sacc[0][1]), fmaxf(sacc[1][0], sacc[1][1]));
        wma = fmaxf(wma, fmaxf(fmaxf(sacc[2][0], sacc[2][1]), fmaxf(sacc[3][0], sacc[3][1])));
        float wmb = fmaxf(fmaxf(sacc[0][2], sacc[0][3]), fmaxf(sacc[1][2], sacc[1][3]));
        wmb = fmaxf(wmb, fmaxf(fmaxf(sacc[2][2], sacc[2][3]), fmaxf(sacc[3][2], sacc[3][3])));
        wma = fmaxf(wma, __shfl_xor_sync(0xffffffffu, wma, 1));
        wma = fmaxf(wma, __shfl_xor_sync(0xffffffffu, wma, 2));
        wmb = fmaxf(wmb, __shfl_xor_sync(0xffffffffu, wmb, 1));
        wmb = fmaxf(wmb, __shfl_xor_sync(0xffffffffu, wmb, 2));
        if (tig == 0) { redm[ch * 64 + ra] = wma; redm[ch * 64 + rb] = wmb; }
        __syncthreads();
        float Ma = fmaxf(wma, redm[(ch ^ 1) * 64 + ra]);
        float Mb = fmaxf(wmb, redm[(ch ^ 1) * 64 + rb]);
        float nma = fmaxf(m_a, Ma), nmb = fmaxf(m_b, Mb);
        float ca = __expf(m_a - nma), cb = __expf(m_b - nmb);
        m_a = nma; m_b = nmb;

        float sa = 0.f, sb = 0.f;
#pragma unroll
        for (int j = 0; j < 4; j++) {
            sacc[j][0] = __expf(sacc[j][0] - nma);
            sacc[j][1] = __expf(sacc[j][1] - nma);
            sacc[j][2] = __expf(sacc[j][2] - nmb);
            sacc[j][3] = __expf(sacc[j][3] - nmb);
            sa += sacc[j][0] + sacc[j][1];
            sb += sacc[j][2] + sacc[j][3];
        }
        sa += __shfl_xor_sync(0xffffffffu, sa, 1);
        sa += __shfl_xor_sync(0xffffffffu, sa, 2);
        sb += __shfl_xor_sync(0xffffffffu, sb, 1);
        sb += __shfl_xor_sync(0xffffffffu, sb, 2);

#pragma unroll
        for (int j = 0; j < 4; j++) {
            *reinterpret_cast<float2*>(&Ks[ra * 68 + n0c + 8 * j + 2 * tig]) =
                make_float2(tfb(sacc[j][0]), tfb(sacc[j][1]));
            *reinterpret_cast<float2*>(&Ks[rb * 68 + n0c + 8 * j + 2 * tig]) =
                make_float2(tfb(sacc[j][2]), tfb(sacc[j][3]));
        }
        if (tig == 0) { reds[ch * 64 + ra] = sa; reds[ch * 64 + rb] = sb; }
        __syncthreads();
        l_a = l_a * ca + sa + reds[(ch ^ 1) * 64 + ra];
        l_b = l_b * cb + sb + reds[(ch ^ 1) * 64 + rb];
#pragma unroll
        for (int j = 0; j < 4; j++) {
            oacc[j][0] *= ca; oacc[j][1] *= ca;
            oacc[j][2] *= cb; oacc[j][3] *= cb;
        }

#pragma unroll
        for (int kk = 0; kk < 64; kk += 8) {
            unsigned a[4];
            a[0] = __float_as_uint(Ks[ra * 68 + kk + tig]);
            a[1] = __float_as_uint(Ks[rb * 68 + kk + tig]);
            a[2] = __float_as_uint(Ks[ra * 68 + kk + tig + 4]);
            a[3] = __float_as_uint(Ks[rb * 68 + kk + tig + 4]);
#pragma unroll
            for (int j = 0; j < 4; j++) {
                unsigned b[2];
                b[0] = __float_as_uint(Vs[(kk + tig) * 72 + n0c + 8 * j + gid]);
                b[1] = __float_as_uint(Vs[(kk + tig + 4) * 72 + n0c + 8 * j + gid]);
                mma8(oacc[j], a, b);
            }
        }
        __syncthreads();
    }

    const float ia = 1.f / l_a, ib = 1.f / l_b;
    float* op = g_obuf + ((size_t)bh * L_ + n * 64) * D_;
#pragma unroll
    for (int j = 0; j < 4; j++) {
        *reinterpret_cast<float2*>(&op[ra * 64 + n0c + 8 * j + 2 * tig]) =
            make_float2(oacc[j][0] * ia, oacc[j][1] * ia);
        *reinterpret_cast<float2*>(&op[rb * 64 + n0c + 8 * j + 2 * tig]) =
            make_float2(oacc[j][2] * ib, oacc[j][3] * ib);
    }
}

// ---------------- K5b: kvb = cK^T @ V via tf32 MMA; ksum = colsum(cK) ----------------
__global__ void __launch_bounds__(256) k_kvb() {
    __shared__ float CKt[64*68];
    __shared__ float Vsb[64*72];
    const int m = blockIdx.x, bh = blockIdx.y;
    const int tid = threadIdx.x, w8 = tid >> 5, lane = tid & 31;
    const int gid = lane >> 2, tig = lane & 3;
    const int m0 = (w8 >> 1) * 16, ch = w8 & 1, n0c = ch * 32;
    const int lr = tid & 15, ld4 = (tid >> 4) * 4;
    const float* ckp = g_ck + ((size_t)bh * L_ + m * 64) * D_;
    const float* vp  = g_v  + ((size_t)bh * L_ + m * 64) * D_;
#pragma unroll
    for (int rep = 0; rep < 4; rep++) {
        int r = lr + rep * 16;
        float4 kv = *reinterpret_cast<const float4*>(&ckp[r * 64 + ld4]);
        CKt[(ld4 + 0) * 68 + r] = kv.x;
        CKt[(ld4 + 1) * 68 + r] = kv.y;
        CKt[(ld4 + 2) * 68 + r] = kv.z;
        CKt[(ld4 + 3) * 68 + r] = kv.w;
    }
    for (int i = tid * 4; i < 4096; i += 1024) {
        int r = i >> 6, d = i & 63;
        float4 vv = *reinterpret_cast<const float4*>(&vp[i]);
        Vsb[r * 72 + d + 0] = tfb(vv.x); Vsb[r * 72 + d + 1] = tfb(vv.y);
        Vsb[r * 72 + d + 2] = tfb(vv.z); Vsb[r * 72 + d + 3] = tfb(vv.w);
    }
    __syncthreads();
    const int ra = m0 + gid, rb = ra + 8;
    float acc[4][4] = {};
#pragma unroll
    for (int kk = 0; kk < 64; kk += 8) {
        unsigned a[4];
        a[0] = f2tf(CKt[ra * 68 + kk + tig]);
        a[1] = f2tf(CKt[rb * 68 + kk + tig]);
        a[2] = f2tf(CKt[ra * 68 + kk + tig + 4]);
        a[3] = f2tf(CKt[rb * 68 + kk + tig + 4]);
#pragma unroll
        for (int j = 0; j < 4; j++) {
            unsigned b[2];
            b[0] = __float_as_uint(Vsb[(kk + tig) * 72 + n0c + 8 * j + gid]);
            b[1] = __float_as_uint(Vsb[(kk + tig + 4) * 72 + n0c + 8 * j + gid]);
            mma8(acc[j], a, b);
        }
    }
    float* dst = g_kvb + (size_t)(bh * NB_ + m) * D_ * D_;
#pragma unroll
    for (int j = 0; j < 4; j++) {
        *reinterpret_cast<float2*>(&dst[ra * 64 + n0c + 8 * j + 2 * tig]) =
            make_float2(acc[j][0], acc[j][1]);
        *reinterpret_cast<float2*>(&dst[rb * 64 + n0c + 8 * j + 2 * tig]) =
            make_float2(acc[j][2], acc[j][3]);
    }
    if (tid < 64) {
        float s = 0.f;
#pragma unroll 8
        for (int k = 0; k < 64; k++) s += CKt[tid * 68 + k];
        g_ksum[(size_t)(bh * NB_ + m) * D_ + tid] = s;
    }
}

// ---------------- K5c: totals, parallel grid ----------------
__global__ void k_totals() {
    const int bh = blockIdx.x, ch = blockIdx.y, tid = threadIdx.x;
    if (ch < 8) {
#pragma unroll
        for (int rep = 0; rep < 2; rep++) {
            const int i = ch * 512 + rep * 256 + tid;
            const float* p = g_kvb + (size_t)bh * NB_ * 4096 + i;
            float s = 0.f;
#pragma unroll 8
            for (int m = 0; m < 64; m++) s += p[(size_t)m * 4096];
            g_kvt[(size_t)bh * 4096 + i] = s;
        }
    } else if (tid < 64) {
        const float* p = g_ksum + (size_t)bh * NB_ * 64 + tid;
        float s = 0.f;
#pragma unroll 8
        for (int m = 0; m < 64; m++) s += p[m * 64];
        g_kst[bh * 64 + tid] = s;
    }
}

// ---------------- K5d: linear path via tf32 MMA; writes o_l + bias (NO obuf dependency) ----------------
__global__ void __launch_bounds__(256) k_lin(const float* __restrict__ plw, const float* __restrict__ plb) {
    __shared__ float KVQ[64*72];
    __shared__ float CQb[64*68];
    __shared__ float ksq[64], den_s[64], plbs[64];
    __shared__ int luts[8];
    const int n = blockIdx.x, bh = blockIdx.y;
    const int tid = threadIdx.x, w8 = tid >> 5, lane = tid & 31;
    const int gid = lane >> 2, tig = lane & 3;
    const int m0 = (w8 >> 1) * 16, ch = w8 & 1, n0c = ch * 32;
    const int ra = m0 + gid, rb = ra + 8;
    if (tid < T_) luts[tid] = g_lut[((size_t)bh * NB_ + n) * T_ + tid];
    if (tid >= 64 && tid < 128) plbs[tid - 64] = plb[tid - 64];
    __syncthreads();
    for (int i = tid; i < 4096; i += 256) {
        float s = g_kvt[(size_t)bh * 4096 + i];
#pragma unroll
        for (int t = 0; t < T_; t++) s -= g_kvb[(size_t)(bh * NB_ + luts[t]) * 4096 + i];
        KVQ[(i >> 6) * 72 + (i & 63)] = s;
    }
    if (tid < 64) {
        float s = g_kst[bh * 64 + tid];
#pragma unroll
        for (int t = 0; t < T_; t++) s -= g_ksum[(size_t)(bh * NB_ + luts[t]) * 64 + tid];
        ksq[tid] = s;
    }
    const float* cqp = g_cq + ((size_t)bh * L_ + n * 64) * D_;
    for (int i = tid * 4; i < 4096; i += 1024) {
        int r = i >> 6, d = i & 63;
        *reinterpret_cast<float4*>(&CQb[r * 68 + d]) = *reinterpret_cast<const float4*>(&cqp[i]);
    }
    __syncthreads();
    if (tid < 64) {
        float s = 0.f;
#pragma unroll 8
        for (int d = 0; d < 64; d++) s += CQb[tid * 68 + d] * ksq[d];
        den_s[tid] = s;
    }
    float acc[4][4] = {};
#pragma unroll
    for (int kk = 0; kk < 64; kk += 8) {
        unsigned a[4];
        a[0] = f2tf(CQb[ra * 68 + kk + tig]);
        a[1] = f2tf(CQb[rb * 68 + kk + tig]);
        a[2] = f2tf(CQb[ra * 68 + kk + tig + 4]);
        a[3] = f2tf(CQb[rb * 68 + kk + tig + 4]);
#pragma unroll
        for (int j = 0; j < 4; j++) {
            unsigned b[2];
            b[0] = f2tf(KVQ[(kk + tig) * 72 + n0c + 8 * j + gid]);
            b[1] = f2tf(KVQ[(kk + tig + 4) * 72 + n0c + 8 * j + gid]);
            mma8(acc[j], a, b);
        }
    }
    __syncthreads();
    const float ia = 1.f / (den_s[ra] + 1e-6f);
    const float ib = 1.f / (den_s[rb] + 1e-6f);
#pragma unroll
    for (int j = 0; j < 4; j++) {
        *reinterpret_cast<float2*>(&CQb[ra * 68 + n0c + 8 * j + 2 * tig]) =
            make_float2(acc[j][0] * ia, acc[j][1] * ia);
        *reinterpret_cast<float2*>(&CQb[rb * 68 + n0c + 8 * j + 2 * tig]) =
            make_float2(acc[j][2] * ib, acc[j][3] * ib);
    }
    for (int i = tid * 4; i < 4096; i += 1024) {
        int e2 = i >> 6, e = i & 63;
        float4 v = *reinterpret_cast<const float4*>(&plw[i]);
        *reinterpret_cast<float4*>(&KVQ[e2 * 68 + e]) = v;
    }
    __syncthreads();
    float acc2[4][4] = {};
#pragma unroll
    for (int kk = 0; kk < 64; kk += 8) {
        unsigned a[4];
        a[0] = f2tf(CQb[ra * 68 + kk + tig]);
        a[1] = f2tf(CQb[rb * 68 + kk + tig]);
        a[2] = f2tf(CQb[ra * 68 + kk + tig + 4]);
        a[3] = f2tf(CQb[rb * 68 + kk + tig + 4]);
#pragma unroll
        for (int j = 0; j < 4; j++) {
            unsigned b[2];
            b[0] = f2tf(KVQ[(n0c + 8 * j + gid) * 68 + kk + tig]);
            b[1] = f2tf(KVQ[(n0c + 8 * j + gid) * 68 + kk + tig + 4]);
            mma8(acc2[j], a, b);
        }
    }
    // epilogue: o_l + bias -> g_olin (fp32)
    float* op = g_olin + ((size_t)bh * L_ + n * 64) * D_;
#pragma unroll
    for (int j = 0; j < 4; j++) {
        const int col = n0c + 8 * j + 2 * tig;
        *reinterpret_cast<float2*>(&op[ra * 64 + col]) =
            make_float2(acc2[j][0] + plbs[col], acc2[j][1] + plbs[col + 1]);
        *reinterpret_cast<float2*>(&op[rb * 64 + col]) =
            make_float2(acc2[j][2] + plbs[col], acc2[j][3] + plbs[col + 1]);
    }
}

// ---------------- K6: out_proj via tf32x3 MMA; B = split(obuf + olin) at STS ----------------
__global__ void __launch_bounds__(256) k_outproj_tc(float* __restrict__ out) {
    __shared__ float Ah[64*GSTR], Al[64*GSTR], Bh[64*GSTR], Bl[64*GSTR];
    const int b = blockIdx.z, l0 = blockIdx.x * 64, co0 = blockIdx.y * 64;
    const int tid = threadIdx.x, w8 = tid >> 5, lane = tid & 31;
    const int gid = lane >> 2, tig = lane & 3;
    const int m0 = (w8 >> 1) * 16, ch = w8 & 1, n0c = ch * 32;
    const int lrow = tid >> 3, cq = (tid & 7) * 4;
    const int ra = m0 + gid, rb = ra + 8;
    float acc[4][4] = {};

    for (int c0 = 0; c0 < C_; c0 += 32) {
        const int hh = c0 >> 6, d0 = c0 & 63;
        const size_t bbase = ((size_t)(b * NH_ + hh) * L_ + l0) * D_ + d0;
#pragma unroll
        for (int r = lrow; r < 64; r += 32) {
            *reinterpret_cast<float4*>(&Ah[r*GSTR+cq]) =
                *reinterpret_cast<const float4*>(&g_w2h[(size_t)(co0 + r) * C_ + c0 + cq]);
            *reinterpret_cast<float4*>(&Al[r*GSTR+cq]) =
                *reinterpret_cast<const float4*>(&g_w2l[(size_t)(co0 + r) * C_ + c0 + cq]);
            float4 v = *reinterpret_cast<const float4*>(&g_obuf[bbase + (size_t)r * D_ + cq]);
            float4 u = *reinterpret_cast<const float4*>(&g_olin[bbase + (size_t)r * D_ + cq]);
            float h, lo;
            split2(v.x + u.x, h, lo); Bh[r*GSTR+cq+0] = h; Bl[r*GSTR+cq+0] = lo;
            split2(v.y + u.y, h, lo); Bh[r*GSTR+cq+1] = h; Bl[r*GSTR+cq+1] = lo;
            split2(v.z + u.z, h, lo); Bh[r*GSTR+cq+2] = h; Bl[r*GSTR+cq+2] = lo;
            split2(v.w + u.w, h, lo); Bh[r*GSTR+cq+3] = h; Bl[r*GSTR+cq+3] = lo;
        }
        __syncthreads();
#pragma unroll
        for (int kk = 0; kk < 32; kk += 8) {
            unsigned ah[4], al[4];
            ah[0] = __float_as_uint(Ah[ra*GSTR + kk + tig]);
            ah[1] = __float_as_uint(Ah[rb*GSTR + kk + tig]);
            ah[2] = __float_as_uint(Ah[ra*GSTR + kk + tig + 4]);
            ah[3] = __float_as_uint(Ah[rb*GSTR + kk + tig + 4]);
            al[0] = __float_as_uint(Al[ra*GSTR + kk + tig]);
            al[1] = __float_as_uint(Al[rb*GSTR + kk + tig]);
            al[2] = __float_as_uint(Al[ra*GSTR + kk + tig + 4]);
            al[3] = __float_as_uint(Al[rb*GSTR + kk + tig + 4]);
#pragma unroll
            for (int j = 0; j < 4; j++) {
                const int br = (n0c + 8*j + gid) * GSTR + kk + tig;
                unsigned bh2[2], bl2[2];
                bh2[0] = __float_as_uint(Bh[br]); bh2[1] = __float_as_uint(Bh[br + 4]);
                bl2[0] = __float_as_uint(Bl[br]); bl2[1] = __float_as_uint(Bl[br + 4]);
                mma8(acc[j], ah, bh2);
                mma8(acc[j], ah, bl2);
                mma8(acc[j], al, bh2);
            }
        }
        __syncthreads();
    }
    float* ob = out + (size_t)b * C_ * L_;
#pragma unroll
    for (int j = 0; j < 4; j++) {
        *reinterpret_cast<float2*>(&ob[(size_t)(co0 + ra) * L_ + l0 + n0c + 8*j + 2*tig]) =
            make_float2(acc[j][0], acc[j][1]);
        *reinterpret_cast<float2*>(&ob[(size_t)(co0 + rb) * L_ + l0 + n0c + 8*j + 2*tig]) =
            make_float2(acc[j][2], acc[j][3]);
    }
}

// ---------------- launch: two-branch stream fork inside graph capture ----------------
extern "C" void kernel_launch(void* const* d_in, const int* in_sizes, int n_in,
                              void* d_out, int out_size) {
    const float* x     = (const float*)d_in[0];
    const float* qkv_w = (const float*)d_in[1];
    const float* out_w = (const float*)d_in[2];
    const float* plw   = (const float*)d_in[3];
    const float* plb   = (const float*)d_in[4];
    float* out = (float*)d_out;

    static cudaStream_t s2 = nullptr;
    static cudaEvent_t evFork = nullptr, evW = nullptr, evQ = nullptr, evJoin = nullptr;
    if (s2 == nullptr) {
        cudaStreamCreateWithFlags(&s2, cudaStreamNonBlocking);
        cudaEventCreateWithFlags(&evFork, cudaEventDisableTiming);
        cudaEventCreateWithFlags(&evW,    cudaEventDisableTiming);
        cudaEventCreateWithFlags(&evQ,    cudaEventDisableTiming);
        cudaEventCreateWithFlags(&evJoin, cudaEventDisableTiming);
        cudaFuncSetAttribute(k_sattn, cudaFuncAttributeMaxDynamicSharedMemorySize,
                             SATTN_SMEM_FLOATS * (int)sizeof(float));
        cudaFuncSetAttribute(k_qkv_tc, cudaFuncAttributeMaxDynamicSharedMemorySize,
                             QKV_SMEM_FLOATS * (int)sizeof(float));
    }
    const int sattn_smem = SATTN_SMEM_FLOATS * (int)sizeof(float); // 54272 B
    const int qkv_smem   = QKV_SMEM_FLOATS * (int)sizeof(float);   // 67584 B

    cudaEventRecord(evFork, 0);
    cudaStreamWaitEvent(s2, evFork, 0);

    // branch B: weight split (independent of xT)
    k_wsplit<<<1024, 256, 0, s2>>>(qkv_w, out_w);
    cudaEventRecord(evW, s2);

    // branch A: x transpose+split
    k_xT<<<dim3(L_ / 32, C_ / 32, B_), dim3(32, 8)>>>(x);
    cudaStreamWaitEvent(0, evW, 0);
    k_qkv_tc<<<dim3(L_ / 64, NH_, B_), 256, qkv_smem>>>();
    cudaEventRecord(evQ, 0);

    // branch B: kvb + totals + LIN (o_l path), all overlapped with topk+sattn
    cudaStreamWaitEvent(s2, evQ, 0);
    k_kvb   <<<dim3(NB_, BH_), 256, 0, s2>>>();
    k_totals<<<dim3(BH_, 9), 256, 0, s2>>>();
    k_lin   <<<dim3(NB_, BH_), 256, 0, s2>>>(plw, plb);
    cudaEventRecord(evJoin, s2);

    // branch A: topk + sattn
    k_topk <<<dim3(BH_, 8), 256>>>();
    k_sattn<<<dim3(NB_, BH_), 256, sattn_smem>>>();

    // join, then out_proj (reads obuf + olin, splits at STS)
    cudaStreamWaitEvent(0, evJoin, 0);
    k_outproj_tc<<<dim3(L_ / 64, C_ / 64, B_), 256>>>(out);
}

// round 13
// speedup vs baseline: 1.1107x; 1.1107x over previous
#include <cuda_runtime.h>

#define B_ 8
#define C_ 256
#define L_ 4096
#define NH_ 4
#define D_ 64
#define NB_ 64   // number of query/key blocks (L/64)
#define T_ 6     // top-k blocks
#define BH_ 32   // B*NH

// ---------------- scratch (device globals; no allocs) ----------------
__device__ float g_xth[(size_t)B_*C_*L_];  // x^T hi split: [b][l][c]
__device__ float g_xtl[(size_t)B_*C_*L_];  // x^T lo split
__device__ float g_wqh[768*256], g_wql[768*256];
__device__ float g_q [BH_*L_*D_];
__device__ float g_k [BH_*L_*D_];
__device__ float g_v [BH_*L_*D_];
__device__ float g_cq[BH_*L_*D_];
__device__ float g_ck[BH_*L_*D_];
__device__ float g_qb[BH_*NB_*D_];
__device__ float g_kb[BH_*NB_*D_];
__device__ int   g_lut[BH_*NB_*T_];
__device__ float g_kvb[(size_t)BH_*NB_*D_*D_];
__device__ float g_ksum[BH_*NB_*D_];
__device__ float g_kvt[BH_*D_*D_];
__device__ float g_kst[BH_*D_];
__device__ float g_obuf[BH_*L_*D_];   // o_s from sattn (fp32)
__device__ float g_olin[BH_*L_*D_];   // o_l + bias from k_lin (fp32)

// ---------------- tf32 mma helpers ----------------
__device__ __forceinline__ unsigned f2tf(float f) {
    unsigned u; asm("cvt.rna.tf32.f32 %0, %1;" : "=r"(u) : "f"(f)); return u;
}
__device__ __forceinline__ void mma8(float d[4], const unsigned a[4], const unsigned b[2]) {
    asm("mma.sync.aligned.m16n8k8.row.col.f32.tf32.tf32.f32 "
        "{%0,%1,%2,%3}, {%4,%5,%6,%7}, {%8,%9}, {%0,%1,%2,%3};"
        : "+f"(d[0]), "+f"(d[1]), "+f"(d[2]), "+f"(d[3])
        : "r"(a[0]), "r"(a[1]), "r"(a[2]), "r"(a[3]), "r"(b[0]), "r"(b[1]));
}
__device__ __forceinline__ void split2(float x, float& hi, float& lo) {
    hi = __uint_as_float(f2tf(x));
    lo = __uint_as_float(f2tf(x - hi));
}
__device__ __forceinline__ float tfb(float x) {   // tf32 bits stored as float
    return __uint_as_float(f2tf(x));
}

// ---------------- K0a: transpose + split x -> g_xth/g_xtl [b][l][c] ----------------
__global__ void k_xT(const float* __restrict__ x) {
    __shared__ float t[32][33];
    const int b = blockIdx.z, l0 = blockIdx.x * 32, c0 = blockIdx.y * 32;
    const int tx = threadIdx.x, ty = threadIdx.y;
    const float* xb = x + (size_t)b * C_ * L_;
#pragma unroll
    for (int i = 0; i < 32; i += 8)
        t[ty + i][tx] = xb[(size_t)(c0 + ty + i) * L_ + l0 + tx];
    __syncthreads();
    float* dh = g_xth + (size_t)b * L_ * C_;
    float* dl = g_xtl + (size_t)b * L_ * C_;
#pragma unroll
    for (int i = 0; i < 32; i += 8) {
        float h, lo; split2(t[tx][ty + i], h, lo);
        dh[(size_t)(l0 + ty + i) * C_ + c0 + tx] = h;
        dl[(size_t)(l0 + ty + i) * C_ + c0 + tx] = lo;
    }
}

// ---------------- K0b: split the qkv weights once ----------------
__global__ void k_wsplit(const float* __restrict__ qkv_w) {
    const int i = blockIdx.x * 256 + threadIdx.x;   // grid covers 196608
    float h, lo;
    split2(qkv_w[i], h, lo); g_wqh[i] = h; g_wql[i] = lo;
}

// ---------------- K1: fused qkv for ONE head: 3 output tiles share the A tile ----------------
#define GSTR 36
#define QAH 0
#define QAL (64*GSTR)
#define QBH(p) (2*64*GSTR + (p)*64*GSTR)   // p = 0,1,2
#define QBL(p) (5*64*GSTR + (p)*64*GSTR)   // p = 0,1
#define QRED  (7*64*GSTR)
#define QREDS (QRED + 128)
#define QWSUM (QREDS + 128)
#define QKV_SMEM_FLOATS (QWSUM + 512)      // 16896 floats = 67584 B

__global__ void __launch_bounds__(256) k_qkv_tc() {
    extern __shared__ float qs[];
    float* Ah = qs + QAH;
    float* Al = qs + QAL;
    float* redm = qs + QRED;
    float* reds = qs + QREDS;
    float (*wsum)[64] = reinterpret_cast<float(*)[64]>(qs + QWSUM);
    const int b = blockIdx.z, l0 = blockIdx.x * 64, hh = blockIdx.y;
    const int tid = threadIdx.x, w8 = tid >> 5, lane = tid & 31;
    const int gid = lane >> 2, tig = lane & 3;
    const int m0 = (w8 >> 1) * 16, ch = w8 & 1, n0c = ch * 32;
    const int lrow = tid >> 3, cq = (tid & 7) * 4;
    const float* ahs = g_xth + (size_t)b * L_ * C_;
    const float* als = g_xtl + (size_t)b * L_ * C_;
    float acc[3][4][4] = {};
    const int ra = m0 + gid, rb = ra + 8;

    for (int c0 = 0; c0 < C_; c0 += 32) {
#pragma unroll
        for (int r = lrow; r < 64; r += 32) {
            *reinterpret_cast<float4*>(&Ah[r*GSTR+cq]) =
                *reinterpret_cast<const float4*>(&ahs[(size_t)(l0 + r) * C_ + c0 + cq]);
            *reinterpret_cast<float4*>(&Al[r*GSTR+cq]) =
                *reinterpret_cast<const float4*>(&als[(size_t)(l0 + r) * C_ + c0 + cq]);
        }
#pragma unroll
        for (int p = 0; p < 3; p++) {
            const float* wh = g_wqh + (size_t)(p * 256 + hh * 64) * C_;
            float* Bp = qs + QBH(p);
#pragma unroll
            for (int r = lrow; r < 64; r += 32)
                *reinterpret_cast<float4*>(&Bp[r*GSTR+cq]) =
                    *reinterpret_cast<const float4*>(&wh[(size_t)r * C_ + c0 + cq]);
        }
#pragma unroll
        for (int p = 0; p < 2; p++) {
            const float* wl = g_wql + (size_t)(p * 256 + hh * 64) * C_;
            float* Bp = qs + QBL(p);
#pragma unroll
            for (int r = lrow; r < 64; r += 32)
                *reinterpret_cast<float4*>(&Bp[r*GSTR+cq]) =
                    *reinterpret_cast<const float4*>(&wl[(size_t)r * C_ + c0 + cq]);
        }
        __syncthreads();
#pragma unroll
        for (int kk = 0; kk < 32; kk += 8) {
            unsigned ah[4], al[4];
            ah[0] = __float_as_uint(Ah[ra*GSTR + kk + tig]);
            ah[1] = __float_as_uint(Ah[rb*GSTR + kk + tig]);
            ah[2] = __float_as_uint(Ah[ra*GSTR + kk + tig + 4]);
            ah[3] = __float_as_uint(Ah[rb*GSTR + kk + tig + 4]);
            al[0] = __float_as_uint(Al[ra*GSTR + kk + tig]);
            al[1] = __float_as_uint(Al[rb*GSTR + kk + tig]);
            al[2] = __float_as_uint(Al[ra*GSTR + kk + tig + 4]);
            al[3] = __float_as_uint(Al[rb*GSTR + kk + tig + 4]);
#pragma unroll
            for (int p = 0; p < 2; p++) {
                const float* Bh = qs + QBH(p);
                const float* Bl = qs + QBL(p);
#pragma unroll
                for (int j = 0; j < 4; j++) {
                    const int br = (n0c + 8*j + gid) * GSTR + kk + tig;
                    unsigned bh2[2], bl2[2];
                    bh2[0] = __float_as_uint(Bh[br]); bh2[1] = __float_as_uint(Bh[br + 4]);
                    bl2[0] = __float_as_uint(Bl[br]); bl2[1] = __float_as_uint(Bl[br + 4]);
                    mma8(acc[p][j], ah, bh2);
                    mma8(acc[p][j], ah, bl2);
                    mma8(acc[p][j], al, bh2);
                }
            }
            {
                const float* Bh = qs + QBH(2);
#pragma unroll
                for (int j = 0; j < 4; j++) {
                    const int br = (n0c + 8*j + gid) * GSTR + kk + tig;
                    unsigned bh2[2];
                    bh2[0] = __float_as_uint(Bh[br]); bh2[1] = __float_as_uint(Bh[br + 4]);
                    mma8(acc[2][j], ah, bh2);
                }
            }
        }
        __syncthreads();
    }

    // ---- store q, k, v tiles ----
#pragma unroll
    for (int p = 0; p < 3; p++) {
        float* dst = ((p == 0) ? g_q : (p == 1) ? g_k : g_v) + (size_t)(b * NH_ + hh) * L_ * D_;
#pragma unroll
        for (int j = 0; j < 4; j++) {
            *reinterpret_cast<float2*>(&dst[(size_t)(l0 + ra) * D_ + n0c + 8*j + 2*tig]) =
                make_float2(acc[p][j][0], acc[p][j][1]);
            *reinterpret_cast<float2*>(&dst[(size_t)(l0 + rb) * D_ + n0c + 8*j + 2*tig]) =
                make_float2(acc[p][j][2], acc[p][j][3]);
        }
    }

    // ---- block means + feature map for q (p=0) and k (p=1) ----
#pragma unroll
    for (int p = 0; p < 2; p++) {
#pragma unroll
        for (int j = 0; j < 4; j++) {
            float s0 = acc[p][j][0] + acc[p][j][2];
            float s1 = acc[p][j][1] + acc[p][j][3];
            s0 += __shfl_xor_sync(0xffffffffu, s0, 4);
            s0 += __shfl_xor_sync(0xffffffffu, s0, 8);
            s0 += __shfl_xor_sync(0xffffffffu, s0, 16);
            s1 += __shfl_xor_sync(0xffffffffu, s1, 4);
            s1 += __shfl_xor_sync(0xffffffffu, s1, 8);
            s1 += __shfl_xor_sync(0xffffffffu, s1, 16);
            if (gid == 0) {
                wsum[w8][n0c + 8*j + 2*tig]     = s0;
                wsum[w8][n0c + 8*j + 2*tig + 1] = s1;
            }
        }
        __syncthreads();
        if (tid < 64) {
            const int c2 = tid >> 5;
            float s = wsum[c2][tid] + wsum[c2 + 2][tid] + wsum[c2 + 4][tid] + wsum[c2 + 6][tid];
            float* bdst = (p == 0) ? g_qb : g_kb;
            bdst[((size_t)(b * NH_ + hh) * NB_ + blockIdx.x) * D_ + tid] = s * (1.f / 64.f);
        }
        float wma = fmaxf(fmaxf(acc[p][0][0], acc[p][0][1]), fmaxf(acc[p][1][0], acc[p][1][1]));
        wma = fmaxf(wma, fmaxf(fmaxf(acc[p][2][0], acc[p][2][1]), fmaxf(acc[p][3][0], acc[p][3][1])));
        float wmb = fmaxf(fmaxf(acc[p][0][2], acc[p][0][3]), fmaxf(acc[p][1][2], acc[p][1][3]));
        wmb = fmaxf(wmb, fmaxf(fmaxf(acc[p][2][2], acc[p][2][3]), fmaxf(acc[p][3][2], acc[p][3][3])));
        wma = fmaxf(wma, __shfl_xor_sync(0xffffffffu, wma, 1));
        wma = fmaxf(wma, __shfl_xor_sync(0xffffffffu, wma, 2));
        wmb = fmaxf(wmb, __shfl_xor_sync(0xffffffffu, wmb, 1));
        wmb = fmaxf(wmb, __shfl_xor_sync(0xffffffffu, wmb, 2));
        if (tig == 0) { redm[ch * 64 + ra] = wma; redm[ch * 64 + rb] = wmb; }
        __syncthreads();
        float Ma = fmaxf(wma, redm[(ch ^ 1) * 64 + ra]);
        float Mb = fmaxf(wmb, redm[(ch ^ 1) * 64 + rb]);
        float ex[4][4];
        float sa = 0.f, sb = 0.f;
#pragma unroll
        for (int j = 0; j < 4; j++) {
            ex[j][0] = __expf(acc[p][j][0] - Ma);
            ex[j][1] = __expf(acc[p][j][1] - Ma);
            ex[j][2] = __expf(acc[p][j][2] - Mb);
            ex[j][3] = __expf(acc[p][j][3] - Mb);
            sa += ex[j][0] + ex[j][1];
            sb += ex[j][2] + ex[j][3];
        }
        sa += __shfl_xor_sync(0xffffffffu, sa, 1);
        sa += __shfl_xor_sync(0xffffffffu, sa, 2);
        sb += __shfl_xor_sync(0xffffffffu, sb, 1);
        sb += __shfl_xor_sync(0xffffffffu, sb, 2);
        if (tig == 0) { reds[ch * 64 + ra] = sa; reds[ch * 64 + rb] = sb; }
        __syncthreads();
        const float ia = 1.f / (sa + reds[(ch ^ 1) * 64 + ra]);
        const float ib = 1.f / (sb + reds[(ch ^ 1) * 64 + rb]);
        float* cdst = ((p == 0) ? g_cq : g_ck) + (size_t)(b * NH_ + hh) * L_ * D_;
#pragma unroll
        for (int j = 0; j < 4; j++) {
            *reinterpret_cast<float2*>(&cdst[(size_t)(l0 + ra) * D_ + n0c + 8*j + 2*tig]) =
                make_float2(ex[j][0] * ia, ex[j][1] * ia);
            *reinterpret_cast<float2*>(&cdst[(size_t)(l0 + rb) * D_ + n0c + 8*j + 2*tig]) =
                make_float2(ex[j][2] * ib, ex[j][3] * ib);
        }
        __syncthreads();
    }
}

// ---------------- K3: scores + top-6, one warp per query row ----------------
__global__ void __launch_bounds__(256) k_topk() {
    __shared__ float kb[64][65];
    __shared__ float qb8[8][64];
    const int bh = blockIdx.x, rg = blockIdx.y;
    const int tid = threadIdx.x, w = tid >> 5, lane = tid & 31;
    for (int i = tid; i < 4096; i += 256) kb[i >> 6][i & 63] = g_kb[(size_t)bh * 4096 + i];
    for (int i = tid; i < 512; i += 256) qb8[i >> 6][i & 63] = g_qb[(size_t)bh * 4096 + rg * 512 + i];
    __syncthreads();
    float s0 = 0.f, s1 = 0.f;
#pragma unroll 8
    for (int d = 0; d < 64; d++) {
        float qv = qb8[w][d];
        s0 += qv * kb[lane][d];
        s1 += qv * kb[lane + 32][d];
    }
    const int r = rg * 8 + w;
    int* lp = g_lut + ((size_t)bh * NB_ + r) * T_;
#pragma unroll
    for (int t = 0; t < T_; t++) {
        float v; int idx;
        if (s0 >= s1) { v = s0; idx = lane; } else { v = s1; idx = lane + 32; }
#pragma unroll
        for (int o = 16; o; o >>= 1) {
            float ov = __shfl_xor_sync(0xffffffffu, v, o);
            int   oi = __shfl_xor_sync(0xffffffffu, idx, o);
            if (ov > v || (ov == v && oi < idx)) { v = ov; idx = oi; }
        }
        if (lane == 0) lp[t] = idx;
        if (idx == lane) s0 = -3.4e38f;
        else if (idx == lane + 32) s1 = -3.4e38f;
    }
}

// ---------------- K4: sparse attention, tf32 mma, pre-converted smem ----------------
#define QS_OFF 0
#define KS_OFF (64*68)
#define VS_OFF (2*64*68)
#define RM_OFF (2*64*68 + 64*72)
#define RS_OFF (RM_OFF + 2*64)
#define SATTN_SMEM_FLOATS (RS_OFF + 2*64)

__global__ void __launch_bounds__(256, 3) k_sattn() {
    extern __shared__ float sm[];
    float* Qs = sm + QS_OFF;
    float* Ks = sm + KS_OFF;
    float* Vs = sm + VS_OFF;
    float* redm = sm + RM_OFF;
    float* reds = sm + RS_OFF;
    __shared__ int luts[8];
    const int n = blockIdx.x, bh = blockIdx.y;
    const int tid = threadIdx.x;
    const int w = tid >> 5, lane = tid & 31;
    const int gid = lane >> 2, tig = lane & 3;
    const int m0 = (w >> 1) * 16;
    const int ch = w & 1;
    const int n0c = ch * 32;

    const float* qp = g_q + ((size_t)bh * L_ + n * 64) * D_;
    for (int i = tid * 4; i < 4096; i += 1024) {
        int r = i >> 6, d = i & 63;
        float4 v = *reinterpret_cast<const float4*>(&qp[i]);
        Qs[r * 68 + d + 0] = tfb(v.x); Qs[r * 68 + d + 1] = tfb(v.y);
        Qs[r * 68 + d + 2] = tfb(v.z); Qs[r * 68 + d + 3] = tfb(v.w);
    }
    if (tid < T_) luts[tid] = g_lut[((size_t)bh * NB_ + n) * T_ + tid];
    __syncthreads();

    float oacc[4][4] = {};
    float m_a = -1e30f, m_b = -1e30f, l_a = 0.f, l_b = 0.f;
    const int ra = m0 + gid, rb = m0 + gid + 8;

    for (int t = 0; t < T_; t++) {
        const float* kp = g_k + ((size_t)bh * L_ + luts[t] * 64) * D_;
        const float* vp = g_v + ((size_t)bh * L_ + luts[t] * 64) * D_;
        for (int i = tid * 4; i < 4096; i += 1024) {
            int r = i >> 6, d = i & 63;
            float4 kv = *reinterpret_cast<const float4*>(&kp[i]);
            Ks[r * 68 + d + 0] = tfb(kv.x); Ks[r * 68 + d + 1] = tfb(kv.y);
            Ks[r * 68 + d + 2] = tfb(kv.z); Ks[r * 68 + d + 3] = tfb(kv.w);
            float4 vv = *reinterpret_cast<const float4*>(&vp[i]);
            Vs[r * 72 + d + 0] = tfb(vv.x); Vs[r * 72 + d + 1] = tfb(vv.y);
            Vs[r * 72 + d + 2] = tfb(vv.z); Vs[r * 72 + d + 3] = tfb(vv.w);
        }
        __syncthreads();

        float sacc[4][4] = {};
#pragma unroll
        for (int kk = 0; kk < 64; kk += 8) {
            unsigned a[4];
            a[0] = __float_as_uint(Qs[ra * 68 + kk + tig]);
            a[1] = __float_as_uint(Qs[rb * 68 + kk + tig]);
            a[2] = __float_as_uint(Qs[ra * 68 + kk + tig + 4]);
            a[3] = __float_as_uint(Qs[rb * 68 + kk + tig + 4]);
#pragma unroll
            for (int j = 0; j < 4; j++) {
                unsigned b[2];
                b[0] = __float_as_uint(Ks[(n0c + 8 * j + gid) * 68 + kk + tig]);
                b[1] = __float_as_uint(Ks[(n0c + 8 * j + gid) * 68 + kk + tig + 4]);
                mma8(sacc[j], a, b);
            }
        }
#pragma unroll
        for (int j = 0; j < 4; j++)
#pragma unroll
            for (int r = 0; r < 4; r++) sacc[j][r] *= 0.125f;

        float wma = fmaxf(fmaxf(sacc[0][0], sacc[0][1]), fmaxf(sacc[1][0], sacc[1][1]));
        wma = fmaxf(wma, fmaxf(fmaxf(sacc[2][0], sacc[2][1]), fmaxf(sacc[3][0], sacc[3][1])));
        float wmb = fmaxf(fmaxf(sacc[0][2], sacc[0][3]), fmaxf(sacc[1][2], sacc[1][3]));
        wmb = fmaxf(wmb, fmaxf(fmaxf(sacc[2][2], sacc[2][3]), fmaxf(sacc[3][2], sacc[3][3])));
        wma = fmaxf(wma, __shfl_xor_sync(0xffffffffu, wma, 1));
        wma = fmaxf(wma, __shfl_xor_sync(0xffffffffu, wma, 2));
        wmb = fmaxf(wmb, __shfl_xor_sync(0xffffffffu, wmb, 1));
        wmb = fmaxf(wmb, __shfl_xor_sync(0xffffffffu, wmb, 2));
        if (tig == 0) { redm[ch * 64 + ra] = wma; redm[ch * 64 + rb] = wmb; }
        __syncthreads();
        float Ma = fmaxf(wma, redm[(ch ^ 1) * 64 + ra]);
        float Mb = fmaxf(wmb, redm[(ch ^ 1) * 64 + rb]);
        float nma = fmaxf(m_a, Ma), nmb = fmaxf(m_b, Mb);
        float ca = __expf(m_a - nma), cb = __expf(m_b - nmb);
        m_a = nma; m_b = nmb;

        float sa = 0.f, sb = 0.f;
#pragma unroll
        for (int j = 0; j < 4; j++) {
            sacc[j][0] = __expf(sacc[j][0] - nma);
            sacc[j][1] = __expf(sacc[j][1] - nma);
            sacc[j][2] = __expf(sacc[j][2] - nmb);
            sacc[j][3] = __expf(sacc[j][3] - nmb);
            sa += sacc[j][0] + sacc[j][1];
            sb += sacc[j][2] + sacc[j][3];
        }
        sa += __shfl_xor_sync(0xffffffffu, sa, 1);
        sa += __shfl_xor_sync(0xffffffffu, sa, 2);
        sb += __shfl_xor_sync(0xffffffffu, sb, 1);
        sb += __shfl_xor_sync(0xffffffffu, sb, 2);

#pragma unroll
        for (int j = 0; j < 4; j++) {
            *reinterpret_cast<float2*>(&Ks[ra * 68 + n0c + 8 * j + 2 * tig]) =
                make_float2(tfb(sacc[j][0]), tfb(sacc[j][1]));
            *reinterpret_cast<float2*>(&Ks[rb * 68 + n0c + 8 * j + 2 * tig]) =
                make_float2(tfb(sacc[j][2]), tfb(sacc[j][3]));
        }
        if (tig == 0) { reds[ch * 64 + ra] = sa; reds[ch * 64 + rb] = sb; }
        __syncthreads();
        l_a = l_a * ca + sa + reds[(ch ^ 1) * 64 + ra];
        l_b = l_b * cb + sb + reds[(ch ^ 1) * 64 + rb];
#pragma unroll
        for (int j = 0; j < 4; j++) {
            oacc[j][0] *= ca; oacc[j][1] *= ca;
            oacc[j][2] *= cb; oacc[j][3] *= cb;
        }

#pragma unroll
        for (int kk = 0; kk < 64; kk += 8) {
            unsigned a[4];
            a[0] = __float_as_uint(Ks[ra * 68 + kk + tig]);
            a[1] = __float_as_uint(Ks[rb * 68 + kk + tig]);
            a[2] = __float_as_uint(Ks[ra * 68 + kk + tig + 4]);
            a[3] = __float_as_uint(Ks[rb * 68 + kk + tig + 4]);
#pragma unroll
            for (int j = 0; j < 4; j++) {
                unsigned b[2];
                b[0] = __float_as_uint(Vs[(kk + tig) * 72 + n0c + 8 * j + gid]);
                b[1] = __float_as_uint(Vs[(kk + tig + 4) * 72 + n0c + 8 * j + gid]);
                mma8(oacc[j], a, b);
            }
        }
        __syncthreads();
    }

    const float ia = 1.f / l_a, ib = 1.f / l_b;
    float* op = g_obuf + ((size_t)bh * L_ + n * 64) * D_;
#pragma unroll
    for (int j = 0; j < 4; j++) {
        *reinterpret_cast<float2*>(&op[ra * 64 + n0c + 8 * j + 2 * tig]) =
            make_float2(oacc[j][0] * ia, oacc[j][1] * ia);
        *reinterpret_cast<float2*>(&op[rb * 64 + n0c + 8 * j + 2 * tig]) =
            make_float2(oacc[j][2] * ib, oacc[j][3] * ib);
    }
}

// ---------------- K5b: kvb = cK^T @ V via tf32 MMA; ksum = colsum(cK) ----------------
__global__ void __launch_bounds__(256) k_kvb() {
    __shared__ float CKt[64*68];
    __shared__ float Vsb[64*72];
    const int m = blockIdx.x, bh = blockIdx.y;
    const int tid = threadIdx.x, w8 = tid >> 5, lane = tid & 31;
    const int gid = lane >> 2, tig = lane & 3;
    const int m0 = (w8 >> 1) * 16, ch = w8 & 1, n0c = ch * 32;
    const int lr = tid & 15, ld4 = (tid >> 4) * 4;
    const float* ckp = g_ck + ((size_t)bh * L_ + m * 64) * D_;
    const float* vp  = g_v  + ((size_t)bh * L_ + m * 64) * D_;
#pragma unroll
    for (int rep = 0; rep < 4; rep++) {
        int r = lr + rep * 16;
        float4 kv = *reinterpret_cast<const float4*>(&ckp[r * 64 + ld4]);
        CKt[(ld4 + 0) * 68 + r] = kv.x;
        CKt[(ld4 + 1) * 68 + r] = kv.y;
        CKt[(ld4 + 2) * 68 + r] = kv.z;
        CKt[(ld4 + 3) * 68 + r] = kv.w;
    }
    for (int i = tid * 4; i < 4096; i += 1024) {
        int r = i >> 6, d = i & 63;
        float4 vv = *reinterpret_cast<const float4*>(&vp[i]);
        Vsb[r * 72 + d + 0] = tfb(vv.x); Vsb[r * 72 + d + 1] = tfb(vv.y);
        Vsb[r * 72 + d + 2] = tfb(vv.z); Vsb[r * 72 + d + 3] = tfb(vv.w);
    }
    __syncthreads();
    const int ra = m0 + gid, rb = ra + 8;
    float acc[4][4] = {};
#pragma unroll
    for (int kk = 0; kk < 64; kk += 8) {
        unsigned a[4];
        a[0] = f2tf(CKt[ra * 68 + kk + tig]);
        a[1] = f2tf(CKt[rb * 68 + kk + tig]);
        a[2] = f2tf(CKt[ra * 68 + kk + tig + 4]);
        a[3] = f2tf(CKt[rb * 68 + kk + tig + 4]);
#pragma unroll
        for (int j = 0; j < 4; j++) {
            unsigned b[2];
            b[0] = __float_as_uint(Vsb[(kk + tig) * 72 + n0c + 8 * j + gid]);
            b[1] = __float_as_uint(Vsb[(kk + tig + 4) * 72 + n0c + 8 * j + gid]);
            mma8(acc[j], a, b);
        }
    }
    float* dst = g_kvb + (size_t)(bh * NB_ + m) * D_ * D_;
#pragma unroll
    for (int j = 0; j < 4; j++) {
        *reinterpret_cast<float2*>(&dst[ra * 64 + n0c + 8 * j + 2 * tig]) =
            make_float2(acc[j][0], acc[j][1]);
        *reinterpret_cast<float2*>(&dst[rb * 64 + n0c + 8 * j + 2 * tig]) =
            make_float2(acc[j][2], acc[j][3]);
    }
    if (tid < 64) {
        float s = 0.f;
#pragma unroll 8
        for (int k = 0; k < 64; k++) s += CKt[tid * 68 + k];
        g_ksum[(size_t)(bh * NB_ + m) * D_ + tid] = s;
    }
}

// ---------------- K5c: totals, parallel grid ----------------
__global__ void k_totals() {
    const int bh = blockIdx.x, ch = blockIdx.y, tid = threadIdx.x;
    if (ch < 8) {
#pragma unroll
        for (int rep = 0; rep < 2; rep++) {
            const int i = ch * 512 + rep * 256 + tid;
            const float* p = g_kvb + (size_t)bh * NB_ * 4096 + i;
            float s = 0.f;
#pragma unroll 8
            for (int m = 0; m < 64; m++) s += p[(size_t)m * 4096];
            g_kvt[(size_t)bh * 4096 + i] = s;
        }
    } else if (tid < 64) {
        const float* p = g_ksum + (size_t)bh * NB_ * 64 + tid;
        float s = 0.f;
#pragma unroll 8
        for (int m = 0; m < 64; m++) s += p[m * 64];
        g_kst[bh * 64 + tid] = s;
    }
}

// ---------------- K5d: linear path via tf32 MMA; writes o_l + bias ----------------
__global__ void __launch_bounds__(256) k_lin(const float* __restrict__ plw, const float* __restrict__ plb) {
    __shared__ float KVQ[64*72];
    __shared__ float CQb[64*68];
    __shared__ float ksq[64], den_s[64], plbs[64];
    __shared__ int luts[8];
    const int n = blockIdx.x, bh = blockIdx.y;
    const int tid = threadIdx.x, w8 = tid >> 5, lane = tid & 31;
    const int gid = lane >> 2, tig = lane & 3;
    const int m0 = (w8 >> 1) * 16, ch = w8 & 1, n0c = ch * 32;
    const int ra = m0 + gid, rb = ra + 8;
    if (tid < T_) luts[tid] = g_lut[((size_t)bh * NB_ + n) * T_ + tid];
    if (tid >= 64 && tid < 128) plbs[tid - 64] = plb[tid - 64];
    __syncthreads();
    for (int i = tid; i < 4096; i += 256) {
        float s = g_kvt[(size_t)bh * 4096 + i];
#pragma unroll
        for (int t = 0; t < T_; t++) s -= g_kvb[(size_t)(bh * NB_ + luts[t]) * 4096 + i];
        KVQ[(i >> 6) * 72 + (i & 63)] = s;
    }
    if (tid < 64) {
        float s = g_kst[bh * 64 + tid];
#pragma unroll
        for (int t = 0; t < T_; t++) s -= g_ksum[(size_t)(bh * NB_ + luts[t]) * 64 + tid];
        ksq[tid] = s;
    }
    const float* cqp = g_cq + ((size_t)bh * L_ + n * 64) * D_;
    for (int i = tid * 4; i < 4096; i += 1024) {
        int r = i >> 6, d = i & 63;
        *reinterpret_cast<float4*>(&CQb[r * 68 + d]) = *reinterpret_cast<const float4*>(&cqp[i]);
    }
    __syncthreads();
    if (tid < 64) {
        float s = 0.f;
#pragma unroll 8
        for (int d = 0; d < 64; d++) s += CQb[tid * 68 + d] * ksq[d];
        den_s[tid] = s;
    }
    float acc[4][4] = {};
#pragma unroll
    for (int kk = 0; kk < 64; kk += 8) {
        unsigned a[4];
        a[0] = f2tf(CQb[ra * 68 + kk + tig]);
        a[1] = f2tf(CQb[rb * 68 + kk + tig]);
        a[2] = f2tf(CQb[ra * 68 + kk + tig + 4]);
        a[3] = f2tf(CQb[rb * 68 + kk + tig + 4]);
#pragma unroll
        for (int j = 0; j < 4; j++) {
            unsigned b[2];
            b[0] = f2tf(KVQ[(kk + tig) * 72 + n0c + 8 * j + gid]);
            b[1] = f2tf(KVQ[(kk + tig + 4) * 72 + n0c + 8 * j + gid]);
            mma8(acc[j], a, b);
        }
    }
    __syncthreads();
    const float ia = 1.f / (den_s[ra] + 1e-6f);
    const float ib = 1.f / (den_s[rb] + 1e-6f);
#pragma unroll
    for (int j = 0; j < 4; j++) {
        *reinterpret_cast<float2*>(&CQb[ra * 68 + n0c + 8 * j + 2 * tig]) =
            make_float2(acc[j][0] * ia, acc[j][1] * ia);
        *reinterpret_cast<float2*>(&CQb[rb * 68 + n0c + 8 * j + 2 * tig]) =
            make_float2(acc[j][2] * ib, acc[j][3] * ib);
    }
    for (int i = tid * 4; i < 4096; i += 1024) {
        int e2 = i >> 6, e = i & 63;
        float4 v = *reinterpret_cast<const float4*>(&plw[i]);
        *reinterpret_cast<float4*>(&KVQ[e2 * 68 + e]) = v;
    }
    __syncthreads();
    float acc2[4][4] = {};
#pragma unroll
    for (int kk = 0; kk < 64; kk += 8) {
        unsigned a[4];
        a[0] = f2tf(CQb[ra * 68 + kk + tig]);
        a[1] = f2tf(CQb[rb * 68 + kk + tig]);
        a[2] = f2tf(CQb[ra * 68 + kk + tig + 4]);
        a[3] = f2tf(CQb[rb * 68 + kk + tig + 4]);
#pragma unroll
        for (int j = 0; j < 4; j++) {
            unsigned b[2];
            b[0] = f2tf(KVQ[(n0c + 8 * j + gid) * 68 + kk + tig]);
            b[1] = f2tf(KVQ[(n0c + 8 * j + gid) * 68 + kk + tig + 4]);
            mma8(acc2[j], a, b);
        }
    }
    float* op = g_olin + ((size_t)bh * L_ + n * 64) * D_;
#pragma unroll
    for (int j = 0; j < 4; j++) {
        const int col = n0c + 8 * j + 2 * tig;
        *reinterpret_cast<float2*>(&op[ra * 64 + col]) =
            make_float2(acc2[j][0] + plbs[col], acc2[j][1] + plbs[col + 1]);
        *reinterpret_cast<float2*>(&op[rb * 64 + col]) =
            make_float2(acc2[j][2] + plbs[col], acc2[j][3] + plbs[col + 1]);
    }
}

// ---------------- K6: out_proj via PLAIN tf32 MMA; B = tfb(obuf + olin) at STS ----------------
__global__ void __launch_bounds__(256) k_outproj_tc(const float* __restrict__ w2, float* __restrict__ out) {
    __shared__ float Ah[64*GSTR], Bh[64*GSTR];
    const int b = blockIdx.z, l0 = blockIdx.x * 64, co0 = blockIdx.y * 64;
    const int tid = threadIdx.x, w8 = tid >> 5, lane = tid & 31;
    const int gid = lane >> 2, tig = lane & 3;
    const int m0 = (w8 >> 1) * 16, ch = w8 & 1, n0c = ch * 32;
    const int lrow = tid >> 3, cq = (tid & 7) * 4;
    const int ra = m0 + gid, rb = ra + 8;
    float acc[4][4] = {};

    for (int c0 = 0; c0 < C_; c0 += 32) {
        const int hh = c0 >> 6, d0 = c0 & 63;
        const size_t bbase = ((size_t)(b * NH_ + hh) * L_ + l0) * D_ + d0;
#pragma unroll
        for (int r = lrow; r < 64; r += 32) {
            float4 wv = *reinterpret_cast<const float4*>(&w2[(size_t)(co0 + r) * C_ + c0 + cq]);
            Ah[r*GSTR+cq+0] = tfb(wv.x); Ah[r*GSTR+cq+1] = tfb(wv.y);
            Ah[r*GSTR+cq+2] = tfb(wv.z); Ah[r*GSTR+cq+3] = tfb(wv.w);
            float4 v = *reinterpret_cast<const float4*>(&g_obuf[bbase + (size_t)r * D_ + cq]);
            float4 u = *reinterpret_cast<const float4*>(&g_olin[bbase + (size_t)r * D_ + cq]);
            Bh[r*GSTR+cq+0] = tfb(v.x + u.x); Bh[r*GSTR+cq+1] = tfb(v.y + u.y);
            Bh[r*GSTR+cq+2] = tfb(v.z + u.z); Bh[r*GSTR+cq+3] = tfb(v.w + u.w);
        }
        __syncthreads();
#pragma unroll
        for (int kk = 0; kk < 32; kk += 8) {
            unsigned ah[4];
            ah[0] = __float_as_uint(Ah[ra*GSTR + kk + tig]);
            ah[1] = __float_as_uint(Ah[rb*GSTR + kk + tig]);
            ah[2] = __float_as_uint(Ah[ra*GSTR + kk + tig + 4]);
            ah[3] = __float_as_uint(Ah[rb*GSTR + kk + tig + 4]);
#pragma unroll
            for (int j = 0; j < 4; j++) {
                const int br = (n0c + 8*j + gid) * GSTR + kk + tig;
                unsigned bh2[2];
                bh2[0] = __float_as_uint(Bh[br]); bh2[1] = __float_as_uint(Bh[br + 4]);
                mma8(acc[j], ah, bh2);
            }
        }
        __syncthreads();
    }
    float* ob = out + (size_t)b * C_ * L_;
#pragma unroll
    for (int j = 0; j < 4; j++) {
        *reinterpret_cast<float2*>(&ob[(size_t)(co0 + ra) * L_ + l0 + n0c + 8*j + 2*tig]) =
            make_float2(acc[j][0], acc[j][1]);
        *reinterpret_cast<float2*>(&ob[(size_t)(co0 + rb) * L_ + l0 + n0c + 8*j + 2*tig]) =
            make_float2(acc[j][2], acc[j][3]);
    }
}

// ---------------- launch: two-branch stream fork inside graph capture ----------------
extern "C" void kernel_launch(void* const* d_in, const int* in_sizes, int n_in,
                              void* d_out, int out_size) {
    const float* x     = (const float*)d_in[0];
    const float* qkv_w = (const float*)d_in[1];
    const float* out_w = (const float*)d_in[2];
    const float* plw   = (const float*)d_in[3];
    const float* plb   = (const float*)d_in[4];
    float* out = (float*)d_out;

    static cudaStream_t s2 = nullptr;
    static cudaEvent_t evFork = nullptr, evW = nullptr, evQ = nullptr, evJoin = nullptr;
    if (s2 == nullptr) {
        cudaStreamCreateWithFlags(&s2, cudaStreamNonBlocking);
        cudaEventCreateWithFlags(&evFork, cudaEventDisableTiming);
        cudaEventCreateWithFlags(&evW,    cudaEventDisableTiming);
        cudaEventCreateWithFlags(&evQ,    cudaEventDisableTiming);
        cudaEventCreateWithFlags(&evJoin, cudaEventDisableTiming);
        cudaFuncSetAttribute(k_sattn, cudaFuncAttributeMaxDynamicSharedMemorySize,
                             SATTN_SMEM_FLOATS * (int)sizeof(float));
        cudaFuncSetAttribute(k_qkv_tc, cudaFuncAttributeMaxDynamicSharedMemorySize,
                             QKV_SMEM_FLOATS * (int)sizeof(float));
    }
    const int sattn_smem = SATTN_SMEM_FLOATS * (int)sizeof(float); // 54272 B
    const int qkv_smem   = QKV_SMEM_FLOATS * (int)sizeof(float);   // 67584 B

    cudaEventRecord(evFork, 0);
    cudaStreamWaitEvent(s2, evFork, 0);

    // branch B: qkv weight split (independent of xT)
    k_wsplit<<<768, 256, 0, s2>>>(qkv_w);
    cudaEventRecord(evW, s2);

    // branch A: x transpose+split
    k_xT<<<dim3(L_ / 32, C_ / 32, B_), dim3(32, 8)>>>(x);
    cudaStreamWaitEvent(0, evW, 0);
    k_qkv_tc<<<dim3(L_ / 64, NH_, B_), 256, qkv_smem>>>();
    cudaEventRecord(evQ, 0);

    // branch B: kvb + totals + lin (o_l path), overlapped with topk+sattn
    cudaStreamWaitEvent(s2, evQ, 0);
    k_kvb   <<<dim3(NB_, BH_), 256, 0, s2>>>();
    k_totals<<<dim3(BH_, 9), 256, 0, s2>>>();
    k_lin   <<<dim3(NB_, BH_), 256, 0, s2>>>(plw, plb);
    cudaEventRecord(evJoin, s2);

    // branch A: topk + sattn
    k_topk <<<dim3(BH_, 8), 256>>>();
    k_sattn<<<dim3(NB_, BH_), 256, sattn_smem>>>();

    // join, then out_proj (plain tf32)
    cudaStreamWaitEvent(0, evJoin, 0);
    k_outproj_tc<<<dim3(L_ / 64, C_ / 64, B_), 256>>>(out_w, out);
}

// round 14
// speedup vs baseline: 1.1250x; 1.0129x over previous
#include <cuda_runtime.h>

#define B_ 8
#define C_ 256
#define L_ 4096
#define NH_ 4
#define D_ 64
#define NB_ 64   // number of query/key blocks (L/64)
#define T_ 6     // top-k blocks
#define BH_ 32   // B*NH

// ---------------- scratch (device globals; no allocs) ----------------
__device__ float g_xt[(size_t)B_*C_*L_];   // x transposed: [b][l][c] (fp32)
__device__ float g_wqh[768*256], g_wql[768*256];
__device__ float g_q [BH_*L_*D_];
__device__ float g_k [BH_*L_*D_];
__device__ float g_v [BH_*L_*D_];
__device__ float g_cq[BH_*L_*D_];
__device__ float g_ck[BH_*L_*D_];
__device__ float g_qb[BH_*NB_*D_];
__device__ float g_kb[BH_*NB_*D_];
__device__ int   g_lut[BH_*NB_*T_];
__device__ float g_kvb[(size_t)BH_*NB_*D_*D_];
__device__ float g_ksum[BH_*NB_*D_];
__device__ float g_kvt[BH_*D_*D_];
__device__ float g_kst[BH_*D_];
__device__ float g_obuf[BH_*L_*D_];   // o_s from sattn (fp32)
__device__ float g_olin[BH_*L_*D_];   // o_l + bias from k_lin (fp32)

// ---------------- tf32 mma helpers ----------------
__device__ __forceinline__ unsigned f2tf(float f) {
    unsigned u; asm("cvt.rna.tf32.f32 %0, %1;" : "=r"(u) : "f"(f)); return u;
}
__device__ __forceinline__ void mma8(float d[4], const unsigned a[4], const unsigned b[2]) {
    asm("mma.sync.aligned.m16n8k8.row.col.f32.tf32.tf32.f32 "
        "{%0,%1,%2,%3}, {%4,%5,%6,%7}, {%8,%9}, {%0,%1,%2,%3};"
        : "+f"(d[0]), "+f"(d[1]), "+f"(d[2]), "+f"(d[3])
        : "r"(a[0]), "r"(a[1]), "r"(a[2]), "r"(a[3]), "r"(b[0]), "r"(b[1]));
}
__device__ __forceinline__ void split2(float x, float& hi, float& lo) {
    hi = __uint_as_float(f2tf(x));
    lo = __uint_as_float(f2tf(x - hi));
}
__device__ __forceinline__ float tfb(float x) {   // tf32 bits stored as float
    return __uint_as_float(f2tf(x));
}

// ---------------- K0a: transpose x -> g_xt[b][l][c] (fp32, no split) ----------------
__global__ void k_xT(const float* __restrict__ x) {
    __shared__ float t[32][33];
    const int b = blockIdx.z, l0 = blockIdx.x * 32, c0 = blockIdx.y * 32;
    const int tx = threadIdx.x, ty = threadIdx.y;
    const float* xb = x + (size_t)b * C_ * L_;
#pragma unroll
    for (int i = 0; i < 32; i += 8)
        t[ty + i][tx] = xb[(size_t)(c0 + ty + i) * L_ + l0 + tx];
    __syncthreads();
    float* dst = g_xt + (size_t)b * L_ * C_;
#pragma unroll
    for (int i = 0; i < 32; i += 8)
        dst[(size_t)(l0 + ty + i) * C_ + c0 + tx] = t[tx][ty + i];
}

// ---------------- K0b: split the qkv weights once ----------------
__global__ void k_wsplit(const float* __restrict__ qkv_w) {
    const int i = blockIdx.x * 256 + threadIdx.x;   // grid covers 196608
    float h, lo;
    split2(qkv_w[i], h, lo); g_wqh[i] = h; g_wql[i] = lo;
}

// ---------------- K1: fused qkv for ONE head; A split at STS (4x redundancy only) ----------------
#define GSTR 36
#define QAH 0
#define QAL (64*GSTR)
#define QBH(p) (2*64*GSTR + (p)*64*GSTR)   // p = 0,1,2
#define QBL(p) (5*64*GSTR + (p)*64*GSTR)   // p = 0,1
#define QRED  (7*64*GSTR)
#define QREDS (QRED + 128)
#define QWSUM (QREDS + 128)
#define QKV_SMEM_FLOATS (QWSUM + 512)      // 16896 floats = 67584 B

__global__ void __launch_bounds__(256) k_qkv_tc() {
    extern __shared__ float qs[];
    float* Ah = qs + QAH;
    float* Al = qs + QAL;
    float* redm = qs + QRED;
    float* reds = qs + QREDS;
    float (*wsum)[64] = reinterpret_cast<float(*)[64]>(qs + QWSUM);
    const int b = blockIdx.z, l0 = blockIdx.x * 64, hh = blockIdx.y;
    const int tid = threadIdx.x, w8 = tid >> 5, lane = tid & 31;
    const int gid = lane >> 2, tig = lane & 3;
    const int m0 = (w8 >> 1) * 16, ch = w8 & 1, n0c = ch * 32;
    const int lrow = tid >> 3, cq = (tid & 7) * 4;
    const float* xt = g_xt + (size_t)b * L_ * C_;
    float acc[3][4][4] = {};
    const int ra = m0 + gid, rb = ra + 8;

    for (int c0 = 0; c0 < C_; c0 += 32) {
#pragma unroll
        for (int r = lrow; r < 64; r += 32) {
            float4 v = *reinterpret_cast<const float4*>(&xt[(size_t)(l0 + r) * C_ + c0 + cq]);
            float h, lo;
            split2(v.x, h, lo); Ah[r*GSTR+cq+0] = h; Al[r*GSTR+cq+0] = lo;
            split2(v.y, h, lo); Ah[r*GSTR+cq+1] = h; Al[r*GSTR+cq+1] = lo;
            split2(v.z, h, lo); Ah[r*GSTR+cq+2] = h; Al[r*GSTR+cq+2] = lo;
            split2(v.w, h, lo); Ah[r*GSTR+cq+3] = h; Al[r*GSTR+cq+3] = lo;
        }
#pragma unroll
        for (int p = 0; p < 3; p++) {
            const float* wh = g_wqh + (size_t)(p * 256 + hh * 64) * C_;
            float* Bp = qs + QBH(p);
#pragma unroll
            for (int r = lrow; r < 64; r += 32)
                *reinterpret_cast<float4*>(&Bp[r*GSTR+cq]) =
                    *reinterpret_cast<const float4*>(&wh[(size_t)r * C_ + c0 + cq]);
        }
#pragma unroll
        for (int p = 0; p < 2; p++) {
            const float* wl = g_wql + (size_t)(p * 256 + hh * 64) * C_;
            float* Bp = qs + QBL(p);
#pragma unroll
            for (int r = lrow; r < 64; r += 32)
                *reinterpret_cast<float4*>(&Bp[r*GSTR+cq]) =
                    *reinterpret_cast<const float4*>(&wl[(size_t)r * C_ + c0 + cq]);
        }
        __syncthreads();
#pragma unroll
        for (int kk = 0; kk < 32; kk += 8) {
            unsigned ah[4], al[4];
            ah[0] = __float_as_uint(Ah[ra*GSTR + kk + tig]);
            ah[1] = __float_as_uint(Ah[rb*GSTR + kk + tig]);
            ah[2] = __float_as_uint(Ah[ra*GSTR + kk + tig + 4]);
            ah[3] = __float_as_uint(Ah[rb*GSTR + kk + tig + 4]);
            al[0] = __float_as_uint(Al[ra*GSTR + kk + tig]);
            al[1] = __float_as_uint(Al[rb*GSTR + kk + tig]);
            al[2] = __float_as_uint(Al[ra*GSTR + kk + tig + 4]);
            al[3] = __float_as_uint(Al[rb*GSTR + kk + tig + 4]);
#pragma unroll
            for (int p = 0; p < 2; p++) {
                const float* Bh = qs + QBH(p);
                const float* Bl = qs + QBL(p);
#pragma unroll
                for (int j = 0; j < 4; j++) {
                    const int br = (n0c + 8*j + gid) * GSTR + kk + tig;
                    unsigned bh2[2], bl2[2];
                    bh2[0] = __float_as_uint(Bh[br]); bh2[1] = __float_as_uint(Bh[br + 4]);
                    bl2[0] = __float_as_uint(Bl[br]); bl2[1] = __float_as_uint(Bl[br + 4]);
                    mma8(acc[p][j], ah, bh2);
                    mma8(acc[p][j], ah, bl2);
                    mma8(acc[p][j], al, bh2);
                }
            }
            {
                const float* Bh = qs + QBH(2);
#pragma unroll
                for (int j = 0; j < 4; j++) {
                    const int br = (n0c + 8*j + gid) * GSTR + kk + tig;
                    unsigned bh2[2];
                    bh2[0] = __float_as_uint(Bh[br]); bh2[1] = __float_as_uint(Bh[br + 4]);
                    mma8(acc[2][j], ah, bh2);
                }
            }
        }
        __syncthreads();
    }

    // ---- store q, k, v tiles ----
#pragma unroll
    for (int p = 0; p < 3; p++) {
        float* dst = ((p == 0) ? g_q : (p == 1) ? g_k : g_v) + (size_t)(b * NH_ + hh) * L_ * D_;
#pragma unroll
        for (int j = 0; j < 4; j++) {
            *reinterpret_cast<float2*>(&dst[(size_t)(l0 + ra) * D_ + n0c + 8*j + 2*tig]) =
                make_float2(acc[p][j][0], acc[p][j][1]);
            *reinterpret_cast<float2*>(&dst[(size_t)(l0 + rb) * D_ + n0c + 8*j + 2*tig]) =
                make_float2(acc[p][j][2], acc[p][j][3]);
        }
    }

    // ---- block means + feature map for q (p=0) and k (p=1) ----
#pragma unroll
    for (int p = 0; p < 2; p++) {
#pragma unroll
        for (int j = 0; j < 4; j++) {
            float s0 = acc[p][j][0] + acc[p][j][2];
            float s1 = acc[p][j][1] + acc[p][j][3];
            s0 += __shfl_xor_sync(0xffffffffu, s0, 4);
            s0 += __shfl_xor_sync(0xffffffffu, s0, 8);
            s0 += __shfl_xor_sync(0xffffffffu, s0, 16);
            s1 += __shfl_xor_sync(0xffffffffu, s1, 4);
            s1 += __shfl_xor_sync(0xffffffffu, s1, 8);
            s1 += __shfl_xor_sync(0xffffffffu, s1, 16);
            if (gid == 0) {
                wsum[w8][n0c + 8*j + 2*tig]     = s0;
                wsum[w8][n0c + 8*j + 2*tig + 1] = s1;
            }
        }
        __syncthreads();
        if (tid < 64) {
            const int c2 = tid >> 5;
            float s = wsum[c2][tid] + wsum[c2 + 2][tid] + wsum[c2 + 4][tid] + wsum[c2 + 6][tid];
            float* bdst = (p == 0) ? g_qb : g_kb;
            bdst[((size_t)(b * NH_ + hh) * NB_ + blockIdx.x) * D_ + tid] = s * (1.f / 64.f);
        }
        float wma = fmaxf(fmaxf(acc[p][0][0], acc[p][0][1]), fmaxf(acc[p][1][0], acc[p][1][1]));
        wma = fmaxf(wma, fmaxf(fmaxf(acc[p][2][0], acc[p][2][1]), fmaxf(acc[p][3][0], acc[p][3][1])));
        float wmb = fmaxf(fmaxf(acc[p][0][2], acc[p][0][3]), fmaxf(acc[p][1][2], acc[p][1][3]));
        wmb = fmaxf(wmb, fmaxf(fmaxf(acc[p][2][2], acc[p][2][3]), fmaxf(acc[p][3][2], acc[p][3][3])));
        wma = fmaxf(wma, __shfl_xor_sync(0xffffffffu, wma, 1));
        wma = fmaxf(wma, __shfl_xor_sync(0xffffffffu, wma, 2));
        wmb = fmaxf(wmb, __shfl_xor_sync(0xffffffffu, wmb, 1));
        wmb = fmaxf(wmb, __shfl_xor_sync(0xffffffffu, wmb, 2));
        if (tig == 0) { redm[ch * 64 + ra] = wma; redm[ch * 64 + rb] = wmb; }
        __syncthreads();
        float Ma = fmaxf(wma, redm[(ch ^ 1) * 64 + ra]);
        float Mb = fmaxf(wmb, redm[(ch ^ 1) * 64 + rb]);
        float ex[4][4];
        float sa = 0.f, sb = 0.f;
#pragma unroll
        for (int j = 0; j < 4; j++) {
            ex[j][0] = __expf(acc[p][j][0] - Ma);
            ex[j][1] = __expf(acc[p][j][1] - Ma);
            ex[j][2] = __expf(acc[p][j][2] - Mb);
            ex[j][3] = __expf(acc[p][j][3] - Mb);
            sa += ex[j][0] + ex[j][1];
            sb += ex[j][2] + ex[j][3];
        }
        sa += __shfl_xor_sync(0xffffffffu, sa, 1);
        sa += __shfl_xor_sync(0xffffffffu, sa, 2);
        sb += __shfl_xor_sync(0xffffffffu, sb, 1);
        sb += __shfl_xor_sync(0xffffffffu, sb, 2);
        if (tig == 0) { reds[ch * 64 + ra] = sa; reds[ch * 64 + rb] = sb; }
        __syncthreads();
        const float ia = 1.f / (sa + reds[(ch ^ 1) * 64 + ra]);
        const float ib = 1.f / (sb + reds[(ch ^ 1) * 64 + rb]);
        float* cdst = ((p == 0) ? g_cq : g_ck) + (size_t)(b * NH_ + hh) * L_ * D_;
#pragma unroll
        for (int j = 0; j < 4; j++) {
            *reinterpret_cast<float2*>(&cdst[(size_t)(l0 + ra) * D_ + n0c + 8*j + 2*tig]) =
                make_float2(ex[j][0] * ia, ex[j][1] * ia);
            *reinterpret_cast<float2*>(&cdst[(size_t)(l0 + rb) * D_ + n0c + 8*j + 2*tig]) =
                make_float2(ex[j][2] * ib, ex[j][3] * ib);
        }
        __syncthreads();
    }
}

// ---------------- K3: scores + top-6, one warp per query row ----------------
__global__ void __launch_bounds__(256) k_topk() {
    __shared__ float kb[64][65];
    __shared__ float qb8[8][64];
    const int bh = blockIdx.x, rg = blockIdx.y;
    const int tid = threadIdx.x, w = tid >> 5, lane = tid & 31;
    for (int i = tid; i < 4096; i += 256) kb[i >> 6][i & 63] = g_kb[(size_t)bh * 4096 + i];
    for (int i = tid; i < 512; i += 256) qb8[i >> 6][i & 63] = g_qb[(size_t)bh * 4096 + rg * 512 + i];
    __syncthreads();
    float s0 = 0.f, s1 = 0.f;
#pragma unroll 8
    for (int d = 0; d < 64; d++) {
        float qv = qb8[w][d];
        s0 += qv * kb[lane][d];
        s1 += qv * kb[lane + 32][d];
    }
    const int r = rg * 8 + w;
    int* lp = g_lut + ((size_t)bh * NB_ + r) * T_;
#pragma unroll
    for (int t = 0; t < T_; t++) {
        float v; int idx;
        if (s0 >= s1) { v = s0; idx = lane; } else { v = s1; idx = lane + 32; }
#pragma unroll
        for (int o = 16; o; o >>= 1) {
            float ov = __shfl_xor_sync(0xffffffffu, v, o);
            int   oi = __shfl_xor_sync(0xffffffffu, idx, o);
            if (ov > v || (ov == v && oi < idx)) { v = ov; idx = oi; }
        }
        if (lane == 0) lp[t] = idx;
        if (idx == lane) s0 = -3.4e38f;
        else if (idx == lane + 32) s1 = -3.4e38f;
    }
}

// ---------------- K4: sparse attention, tf32 mma, pre-converted smem ----------------
#define QS_OFF 0
#define KS_OFF (64*68)
#define VS_OFF (2*64*68)
#define RM_OFF (2*64*68 + 64*72)
#define RS_OFF (RM_OFF + 2*64)
#define SATTN_SMEM_FLOATS (RS_OFF + 2*64)

__global__ void __launch_bounds__(256, 3) k_sattn() {
    extern __shared__ float sm[];
    float* Qs = sm + QS_OFF;
    float* Ks = sm + KS_OFF;
    float* Vs = sm + VS_OFF;
    float* redm = sm + RM_OFF;
    float* reds = sm + RS_OFF;
    __shared__ int luts[8];
    const int n = blockIdx.x, bh = blockIdx.y;
    const int tid = threadIdx.x;
    const int w = tid >> 5, lane = tid & 31;
    const int gid = lane >> 2, tig = lane & 3;
    const int m0 = (w >> 1) * 16;
    const int ch = w & 1;
    const int n0c = ch * 32;

    const float* qp = g_q + ((size_t)bh * L_ + n * 64) * D_;
    for (int i = tid * 4; i < 4096; i += 1024) {
        int r = i >> 6, d = i & 63;
        float4 v = *reinterpret_cast<const float4*>(&qp[i]);
        Qs[r * 68 + d + 0] = tfb(v.x); Qs[r * 68 + d + 1] = tfb(v.y);
        Qs[r * 68 + d + 2] = tfb(v.z); Qs[r * 68 + d + 3] = tfb(v.w);
    }
    if (tid < T_) luts[tid] = g_lut[((size_t)bh * NB_ + n) * T_ + tid];
    __syncthreads();

    float oacc[4][4] = {};
    float m_a = -1e30f, m_b = -1e30f, l_a = 0.f, l_b = 0.f;
    const int ra = m0 + gid, rb = m0 + gid + 8;

    for (int t = 0; t < T_; t++) {
        const float* kp = g_k + ((size_t)bh * L_ + luts[t] * 64) * D_;
        const float* vp = g_v + ((size_t)bh * L_ + luts[t] * 64) * D_;
        for (int i = tid * 4; i < 4096; i += 1024) {
            int r = i >> 6, d = i & 63;
            float4 kv = *reinterpret_cast<const float4*>(&kp[i]);
            Ks[r * 68 + d + 0] = tfb(kv.x); Ks[r * 68 + d + 1] = tfb(kv.y);
            Ks[r * 68 + d + 2] = tfb(kv.z); Ks[r * 68 + d + 3] = tfb(kv.w);
            float4 vv = *reinterpret_cast<const float4*>(&vp[i]);
            Vs[r * 72 + d + 0] = tfb(vv.x); Vs[r * 72 + d + 1] = tfb(vv.y);
            Vs[r * 72 + d + 2] = tfb(vv.z); Vs[r * 72 + d + 3] = tfb(vv.w);
        }
        __syncthreads();

        float sacc[4][4] = {};
#pragma unroll
        for (int kk = 0; kk < 64; kk += 8) {
            unsigned a[4];
            a[0] = __float_as_uint(Qs[ra * 68 + kk + tig]);
            a[1] = __float_as_uint(Qs[rb * 68 + kk + tig]);
            a[2] = __float_as_uint(Qs[ra * 68 + kk + tig + 4]);
            a[3] = __float_as_uint(Qs[rb * 68 + kk + tig + 4]);
#pragma unroll
            for (int j = 0; j < 4; j++) {
                unsigned b[2];
                b[0] = __float_as_uint(Ks[(n0c + 8 * j + gid) * 68 + kk + tig]);
                b[1] = __float_as_uint(Ks[(n0c + 8 * j + gid) * 68 + kk + tig + 4]);
                mma8(sacc[j], a, b);
            }
        }
#pragma unroll
        for (int j = 0; j < 4; j++)
#pragma unroll
            for (int r = 0; r < 4; r++) sacc[j][r] *= 0.125f;

        float wma = fmaxf(fmaxf(sacc[0][0], sacc[0][1]), fmaxf(sacc[1][0], sacc[1][1]));
        wma = fmaxf(wma, fmaxf(fmaxf(sacc[2][0], sacc[2][1]), fmaxf(sacc[3][0], sacc[3][1])));
        float wmb = fmaxf(fmaxf(sacc[0][2], sacc[0][3]), fmaxf(sacc[1][2], sacc[1][3]));
        wmb = fmaxf(wmb, fmaxf(fmaxf(sacc[2][2], sacc[2][3]), fmaxf(sacc[3][2], sacc[3][3])));
        wma = fmaxf(wma, __shfl_xor_sync(0xffffffffu, wma, 1));
        wma = fmaxf(wma, __shfl_xor_sync(0xffffffffu, wma, 2));
        wmb = fmaxf(wmb, __shfl_xor_sync(0xffffffffu, wmb, 1));
        wmb = fmaxf(wmb, __shfl_xor_sync(0xffffffffu, wmb, 2));
        if (tig == 0) { redm[ch * 64 + ra] = wma; redm[ch * 64 + rb] = wmb; }
        __syncthreads();
        float Ma = fmaxf(wma, redm[(ch ^ 1) * 64 + ra]);
        float Mb = fmaxf(wmb, redm[(ch ^ 1) * 64 + rb]);
        float nma = fmaxf(m_a, Ma), nmb = fmaxf(m_b, Mb);
        float ca = __expf(m_a - nma), cb = __expf(m_b - nmb);
        m_a = nma; m_b = nmb;

        float sa = 0.f, sb = 0.f;
#pragma unroll
        for (int j = 0; j < 4; j++) {
            sacc[j][0] = __expf(sacc[j][0] - nma);
            sacc[j][1] = __expf(sacc[j][1] - nma);
            sacc[j][2] = __expf(sacc[j][2] - nmb);
            sacc[j][3] = __expf(sacc[j][3] - nmb);
            sa += sacc[j][0] + sacc[j][1];
            sb += sacc[j][2] + sacc[j][3];
        }
        sa += __shfl_xor_sync(0xffffffffu, sa, 1);
        sa += __shfl_xor_sync(0xffffffffu, sa, 2);
        sb += __shfl_xor_sync(0xffffffffu, sb, 1);
        sb += __shfl_xor_sync(0xffffffffu, sb, 2);

#pragma unroll
        for (int j = 0; j < 4; j++) {
            *reinterpret_cast<float2*>(&Ks[ra * 68 + n0c + 8 * j + 2 * tig]) =
                make_float2(tfb(sacc[j][0]), tfb(sacc[j][1]));
            *reinterpret_cast<float2*>(&Ks[rb * 68 + n0c + 8 * j + 2 * tig]) =
                make_float2(tfb(sacc[j][2]), tfb(sacc[j][3]));
        }
        if (tig == 0) { reds[ch * 64 + ra] = sa; reds[ch * 64 + rb] = sb; }
        __syncthreads();
        l_a = l_a * ca + sa + reds[(ch ^ 1) * 64 + ra];
        l_b = l_b * cb + sb + reds[(ch ^ 1) * 64 + rb];
#pragma unroll
        for (int j = 0; j < 4; j++) {
            oacc[j][0] *= ca; oacc[j][1] *= ca;
            oacc[j][2] *= cb; oacc[j][3] *= cb;
        }

#pragma unroll
        for (int kk = 0; kk < 64; kk += 8) {
            unsigned a[4];
            a[0] = __float_as_uint(Ks[ra * 68 + kk + tig]);
            a[1] = __float_as_uint(Ks[rb * 68 + kk + tig]);
            a[2] = __float_as_uint(Ks[ra * 68 + kk + tig + 4]);
            a[3] = __float_as_uint(Ks[rb * 68 + kk + tig + 4]);
#pragma unroll
            for (int j = 0; j < 4; j++) {
                unsigned b[2];
                b[0] = __float_as_uint(Vs[(kk + tig) * 72 + n0c + 8 * j + gid]);
                b[1] = __float_as_uint(Vs[(kk + tig + 4) * 72 + n0c + 8 * j + gid]);
                mma8(oacc[j], a, b);
            }
        }
        __syncthreads();
    }

    const float ia = 1.f / l_a, ib = 1.f / l_b;
    float* op = g_obuf + ((size_t)bh * L_ + n * 64) * D_;
#pragma unroll
    for (int j = 0; j < 4; j++) {
        *reinterpret_cast<float2*>(&op[ra * 64 + n0c + 8 * j + 2 * tig]) =
            make_float2(oacc[j][0] * ia, oacc[j][1] * ia);
        *reinterpret_cast<float2*>(&op[rb * 64 + n0c + 8 * j + 2 * tig]) =
            make_float2(oacc[j][2] * ib, oacc[j][3] * ib);
    }
}

// ---------------- K5b: kvb = cK^T @ V via tf32 MMA; ksum = colsum(cK) ----------------
__global__ void __launch_bounds__(256) k_kvb() {
    __shared__ float CKt[64*68];
    __shared__ float Vsb[64*72];
    const int m = blockIdx.x, bh = blockIdx.y;
    const int tid = threadIdx.x, w8 = tid >> 5, lane = tid & 31;
    const int gid = lane >> 2, tig = lane & 3;
    const int m0 = (w8 >> 1) * 16, ch = w8 & 1, n0c = ch * 32;
    const int lr = tid & 15, ld4 = (tid >> 4) * 4;
    const float* ckp = g_ck + ((size_t)bh * L_ + m * 64) * D_;
    const float* vp  = g_v  + ((size_t)bh * L_ + m * 64) * D_;
#pragma unroll
    for (int rep = 0; rep < 4; rep++) {
        int r = lr + rep * 16;
        float4 kv = *reinterpret_cast<const float4*>(&ckp[r * 64 + ld4]);
        CKt[(ld4 + 0) * 68 + r] = kv.x;
        CKt[(ld4 + 1) * 68 + r] = kv.y;
        CKt[(ld4 + 2) * 68 + r] = kv.z;
        CKt[(ld4 + 3) * 68 + r] = kv.w;
    }
    for (int i = tid * 4; i < 4096; i += 1024) {
        int r = i >> 6, d = i & 63;
        float4 vv = *reinterpret_cast<const float4*>(&vp[i]);
        Vsb[r * 72 + d + 0] = tfb(vv.x); Vsb[r * 72 + d + 1] = tfb(vv.y);
        Vsb[r * 72 + d + 2] = tfb(vv.z); Vsb[r * 72 + d + 3] = tfb(vv.w);
    }
    __syncthreads();
    const int ra = m0 + gid, rb = ra + 8;
    float acc[4][4] = {};
#pragma unroll
    for (int kk = 0; kk < 64; kk += 8) {
        unsigned a[4];
        a[0] = f2tf(CKt[ra * 68 + kk + tig]);
        a[1] = f2tf(CKt[rb * 68 + kk + tig]);
        a[2] = f2tf(CKt[ra * 68 + kk + tig + 4]);
        a[3] = f2tf(CKt[rb * 68 + kk + tig + 4]);
#pragma unroll
        for (int j = 0; j < 4; j++) {
            unsigned b[2];
            b[0] = __float_as_uint(Vsb[(kk + tig) * 72 + n0c + 8 * j + gid]);
            b[1] = __float_as_uint(Vsb[(kk + tig + 4) * 72 + n0c + 8 * j + gid]);
            mma8(acc[j], a, b);
        }
    }
    float* dst = g_kvb + (size_t)(bh * NB_ + m) * D_ * D_;
#pragma unroll
    for (int j = 0; j < 4; j++) {
        *reinterpret_cast<float2*>(&dst[ra * 64 + n0c + 8 * j + 2 * tig]) =
            make_float2(acc[j][0], acc[j][1]);
        *reinterpret_cast<float2*>(&dst[rb * 64 + n0c + 8 * j + 2 * tig]) =
            make_float2(acc[j][2], acc[j][3]);
    }
    if (tid < 64) {
        float s = 0.f;
#pragma unroll 8
        for (int k = 0; k < 64; k++) s += CKt[tid * 68 + k];
        g_ksum[(size_t)(bh * NB_ + m) * D_ + tid] = s;
    }
}

// ---------------- K5c: totals, parallel grid ----------------
__global__ void k_totals() {
    const int bh = blockIdx.x, ch = blockIdx.y, tid = threadIdx.x;
    if (ch < 8) {
#pragma unroll
        for (int rep = 0; rep < 2; rep++) {
            const int i = ch * 512 + rep * 256 + tid;
            const float* p = g_kvb + (size_t)bh * NB_ * 4096 + i;
            float s = 0.f;
#pragma unroll 8
            for (int m = 0; m < 64; m++) s += p[(size_t)m * 4096];
            g_kvt[(size_t)bh * 4096 + i] = s;
        }
    } else if (tid < 64) {
        const float* p = g_ksum + (size_t)bh * NB_ * 64 + tid;
        float s = 0.f;
#pragma unroll 8
        for (int m = 0; m < 64; m++) s += p[m * 64];
        g_kst[bh * 64 + tid] = s;
    }
}

// ---------------- K5d: linear path via tf32 MMA; writes o_l + bias ----------------
__global__ void __launch_bounds__(256) k_lin(const float* __restrict__ plw, const float* __restrict__ plb) {
    __shared__ float KVQ[64*72];
    __shared__ float CQb[64*68];
    __shared__ float ksq[64], den_s[64], plbs[64];
    __shared__ int luts[8];
    const int n = blockIdx.x, bh = blockIdx.y;
    const int tid = threadIdx.x, w8 = tid >> 5, lane = tid & 31;
    const int gid = lane >> 2, tig = lane & 3;
    const int m0 = (w8 >> 1) * 16, ch = w8 & 1, n0c = ch * 32;
    const int ra = m0 + gid, rb = ra + 8;
    if (tid < T_) luts[tid] = g_lut[((size_t)bh * NB_ + n) * T_ + tid];
    if (tid >= 64 && tid < 128) plbs[tid - 64] = plb[tid - 64];
    __syncthreads();
    for (int i = tid; i < 4096; i += 256) {
        float s = g_kvt[(size_t)bh * 4096 + i];
#pragma unroll
        for (int t = 0; t < T_; t++) s -= g_kvb[(size_t)(bh * NB_ + luts[t]) * 4096 + i];
        KVQ[(i >> 6) * 72 + (i & 63)] = s;
    }
    if (tid < 64) {
        float s = g_kst[bh * 64 + tid];
#pragma unroll
        for (int t = 0; t < T_; t++) s -= g_ksum[(size_t)(bh * NB_ + luts[t]) * 64 + tid];
        ksq[tid] = s;
    }
    const float* cqp = g_cq + ((size_t)bh * L_ + n * 64) * D_;
    for (int i = tid * 4; i < 4096; i += 1024) {
        int r = i >> 6, d = i & 63;
        *reinterpret_cast<float4*>(&CQb[r * 68 + d]) = *reinterpret_cast<const float4*>(&cqp[i]);
    }
    __syncthreads();
    if (tid < 64) {
        float s = 0.f;
#pragma unroll 8
        for (int d = 0; d < 64; d++) s += CQb[tid * 68 + d] * ksq[d];
        den_s[tid] = s;
    }
    float acc[4][4] = {};
#pragma unroll
    for (int kk = 0; kk < 64; kk += 8) {
        unsigned a[4];
        a[0] = f2tf(CQb[ra * 68 + kk + tig]);
        a[1] = f2tf(CQb[rb * 68 + kk + tig]);
        a[2] = f2tf(CQb[ra * 68 + kk + tig + 4]);
        a[3] = f2tf(CQb[rb * 68 + kk + tig + 4]);
#pragma unroll
        for (int j = 0; j < 4; j++) {
            unsigned b[2];
            b[0] = f2tf(KVQ[(kk + tig) * 72 + n0c + 8 * j + gid]);
            b[1] = f2tf(KVQ[(kk + tig + 4) * 72 + n0c + 8 * j + gid]);
            mma8(acc[j], a, b);
        }
    }
    __syncthreads();
    const float ia = 1.f / (den_s[ra] + 1e-6f);
    const float ib = 1.f / (den_s[rb] + 1e-6f);
#pragma unroll
    for (int j = 0; j < 4; j++) {
        *reinterpret_cast<float2*>(&CQb[ra * 68 + n0c + 8 * j + 2 * tig]) =
            make_float2(acc[j][0] * ia, acc[j][1] * ia);
        *reinterpret_cast<float2*>(&CQb[rb * 68 + n0c + 8 * j + 2 * tig]) =
            make_float2(acc[j][2] * ib, acc[j][3] * ib);
    }
    for (int i = tid * 4; i < 4096; i += 1024) {
        int e2 = i >> 6, e = i & 63;
        float4 v = *reinterpret_cast<const float4*>(&plw[i]);
        *reinterpret_cast<float4*>(&KVQ[e2 * 68 + e]) = v;
    }
    __syncthreads();
    float acc2[4][4] = {};
#pragma unroll
    for (int kk = 0; kk < 64; kk += 8) {
        unsigned a[4];
        a[0] = f2tf(CQb[ra * 68 + kk + tig]);
        a[1] = f2tf(CQb[rb * 68 + kk + tig]);
        a[2] = f2tf(CQb[ra * 68 + kk + tig + 4]);
        a[3] = f2tf(CQb[rb * 68 + kk + tig + 4]);
#pragma unroll
        for (int j = 0; j < 4; j++) {
            unsigned b[2];
            b[0] = f2tf(KVQ[(n0c + 8 * j + gid) * 68 + kk + tig]);
            b[1] = f2tf(KVQ[(n0c + 8 * j + gid) * 68 + kk + tig + 4]);
            mma8(acc2[j], a, b);
        }
    }
    float* op = g_olin + ((size_t)bh * L_ + n * 64) * D_;
#pragma unroll
    for (int j = 0; j < 4; j++) {
        const int col = n0c + 8 * j + 2 * tig;
        *reinterpret_cast<float2*>(&op[ra * 64 + col]) =
            make_float2(acc2[j][0] + plbs[col], acc2[j][1] + plbs[col + 1]);
        *reinterpret_cast<float2*>(&op[rb * 64 + col]) =
            make_float2(acc2[j][2] + plbs[col], acc2[j][3] + plbs[col + 1]);
    }
}

// ---------------- K6: out_proj via PLAIN tf32 MMA; B = tfb(obuf + olin) at STS ----------------
__global__ void __launch_bounds__(256) k_outproj_tc(const float* __restrict__ w2, float* __restrict__ out) {
    __shared__ float Ah[64*GSTR], Bh[64*GSTR];
    const int b = blockIdx.z, l0 = blockIdx.x * 64, co0 = blockIdx.y * 64;
    const int tid = threadIdx.x, w8 = tid >> 5, lane = tid & 31;
    const int gid = lane >> 2, tig = lane & 3;
    const int m0 = (w8 >> 1) * 16, ch = w8 & 1, n0c = ch * 32;
    const int lrow = tid >> 3, cq = (tid & 7) * 4;
    const int ra = m0 + gid, rb = ra + 8;
    float acc[4][4] = {};

    for (int c0 = 0; c0 < C_; c0 += 32) {
        const int hh = c0 >> 6, d0 = c0 & 63;
        const size_t bbase = ((size_t)(b * NH_ + hh) * L_ + l0) * D_ + d0;
#pragma unroll
        for (int r = lrow; r < 64; r += 32) {
            float4 wv = *reinterpret_cast<const float4*>(&w2[(size_t)(co0 + r) * C_ + c0 + cq]);
            Ah[r*GSTR+cq+0] = tfb(wv.x); Ah[r*GSTR+cq+1] = tfb(wv.y);
            Ah[r*GSTR+cq+2] = tfb(wv.z); Ah[r*GSTR+cq+3] = tfb(wv.w);
            float4 v = *reinterpret_cast<const float4*>(&g_obuf[bbase + (size_t)r * D_ + cq]);
            float4 u = *reinterpret_cast<const float4*>(&g_olin[bbase + (size_t)r * D_ + cq]);
            Bh[r*GSTR+cq+0] = tfb(v.x + u.x); Bh[r*GSTR+cq+1] = tfb(v.y + u.y);
            Bh[r*GSTR+cq+2] = tfb(v.z + u.z); Bh[r*GSTR+cq+3] = tfb(v.w + u.w);
        }
        __syncthreads();
#pragma unroll
        for (int kk = 0; kk < 32; kk += 8) {
            unsigned ah[4];
            ah[0] = __float_as_uint(Ah[ra*GSTR + kk + tig]);
            ah[1] = __float_as_uint(Ah[rb*GSTR + kk + tig]);
            ah[2] = __float_as_uint(Ah[ra*GSTR + kk + tig + 4]);
            ah[3] = __float_as_uint(Ah[rb*GSTR + kk + tig + 4]);
#pragma unroll
            for (int j = 0; j < 4; j++) {
                const int br = (n0c + 8*j + gid) * GSTR + kk + tig;
                unsigned bh2[2];
                bh2[0] = __float_as_uint(Bh[br]); bh2[1] = __float_as_uint(Bh[br + 4]);
                mma8(acc[j], ah, bh2);
            }
        }
        __syncthreads();
    }
    float* ob = out + (size_t)b * C_ * L_;
#pragma unroll
    for (int j = 0; j < 4; j++) {
        *reinterpret_cast<float2*>(&ob[(size_t)(co0 + ra) * L_ + l0 + n0c + 8*j + 2*tig]) =
            make_float2(acc[j][0], acc[j][1]);
        *reinterpret_cast<float2*>(&ob[(size_t)(co0 + rb) * L_ + l0 + n0c + 8*j + 2*tig]) =
            make_float2(acc[j][2], acc[j][3]);
    }
}

// ---------------- launch: two-branch stream fork inside graph capture ----------------
extern "C" void kernel_launch(void* const* d_in, const int* in_sizes, int n_in,
                              void* d_out, int out_size) {
    const float* x     = (const float*)d_in[0];
    const float* qkv_w = (const float*)d_in[1];
    const float* out_w = (const float*)d_in[2];
    const float* plw   = (const float*)d_in[3];
    const float* plb   = (const float*)d_in[4];
    float* out = (float*)d_out;

    static cudaStream_t s2 = nullptr;
    static cudaEvent_t evFork = nullptr, evW = nullptr, evQ = nullptr, evJoin = nullptr;
    if (s2 == nullptr) {
        cudaStreamCreateWithFlags(&s2, cudaStreamNonBlocking);
        cudaEventCreateWithFlags(&evFork, cudaEventDisableTiming);
        cudaEventCreateWithFlags(&evW,    cudaEventDisableTiming);
        cudaEventCreateWithFlags(&evQ,    cudaEventDisableTiming);
        cudaEventCreateWithFlags(&evJoin, cudaEventDisableTiming);
        cudaFuncSetAttribute(k_sattn, cudaFuncAttributeMaxDynamicSharedMemorySize,
                             SATTN_SMEM_FLOATS * (int)sizeof(float));
        cudaFuncSetAttribute(k_qkv_tc, cudaFuncAttributeMaxDynamicSharedMemorySize,
                             QKV_SMEM_FLOATS * (int)sizeof(float));
    }
    const int sattn_smem = SATTN_SMEM_FLOATS * (int)sizeof(float); // 54272 B
    const int qkv_smem   = QKV_SMEM_FLOATS * (int)sizeof(float);   // 67584 B

    cudaEventRecord(evFork, 0);
    cudaStreamWaitEvent(s2, evFork, 0);

    // branch B: qkv weight split (independent of xT)
    k_wsplit<<<768, 256, 0, s2>>>(qkv_w);
    cudaEventRecord(evW, s2);

    // branch A: x transpose (plain fp32)
    k_xT<<<dim3(L_ / 32, C_ / 32, B_), dim3(32, 8)>>>(x);
    cudaStreamWaitEvent(0, evW, 0);
    k_qkv_tc<<<dim3(L_ / 64, NH_, B_), 256, qkv_smem>>>();
    cudaEventRecord(evQ, 0);

    // branch B: kvb + totals + lin (o_l path), overlapped with topk+sattn
    cudaStreamWaitEvent(s2, evQ, 0);
    k_kvb   <<<dim3(NB_, BH_), 256, 0, s2>>>();
    k_totals<<<dim3(BH_, 9), 256, 0, s2>>>();
    k_lin   <<<dim3(NB_, BH_), 256, 0, s2>>>(plw, plb);
    cudaEventRecord(evJoin, s2);

    // branch A: topk + sattn
    k_topk <<<dim3(BH_, 8), 256>>>();
    k_sattn<<<dim3(NB_, BH_), 256, sattn_smem>>>();

    // join, then out_proj (plain tf32)
    cudaStreamWaitEvent(0, evJoin, 0);
    k_outproj_tc<<<dim3(L_ / 64, C_ / 64, B_), 256>>>(out_w, out);
}

// round 15
// speedup vs baseline: 1.2454x; 1.1070x over previous
#include <cuda_runtime.h>

#define B_ 8
#define C_ 256
#define L_ 4096
#define NH_ 4
#define D_ 64
#define NB_ 64   // number of query/key blocks (L/64)
#define T_ 6     // top-k blocks
#define BH_ 32   // B*NH

// ---------------- scratch (device globals; no allocs) ----------------
__device__ float g_xt[(size_t)B_*C_*L_];   // x transposed: [b][l][c] (fp32)
__device__ float g_xbar[B_*NB_*C_];        // per-block mean of x: [b][n][c]
__device__ float g_q [BH_*L_*D_];
__device__ float g_k [BH_*L_*D_];
__device__ float g_v [BH_*L_*D_];
__device__ float g_cq[BH_*L_*D_];
__device__ float g_ck[BH_*L_*D_];
__device__ float g_qb[BH_*NB_*D_];
__device__ float g_kb[BH_*NB_*D_];
__device__ int   g_lut[BH_*NB_*T_];
__device__ float g_kvb[(size_t)BH_*NB_*D_*D_];
__device__ float g_ksum[BH_*NB_*D_];
__device__ float g_kvt[BH_*D_*D_];
__device__ float g_kst[BH_*D_];
__device__ float g_obuf[BH_*L_*D_];   // o_s from sattn (fp32)
__device__ float g_olin[BH_*L_*D_];   // o_l + bias from k_lin (fp32)

// ---------------- tf32 mma helpers ----------------
__device__ __forceinline__ unsigned f2tf(float f) {
    unsigned u; asm("cvt.rna.tf32.f32 %0, %1;" : "=r"(u) : "f"(f)); return u;
}
__device__ __forceinline__ void mma8(float d[4], const unsigned a[4], const unsigned b[2]) {
    asm("mma.sync.aligned.m16n8k8.row.col.f32.tf32.tf32.f32 "
        "{%0,%1,%2,%3}, {%4,%5,%6,%7}, {%8,%9}, {%0,%1,%2,%3};"
        : "+f"(d[0]), "+f"(d[1]), "+f"(d[2]), "+f"(d[3])
        : "r"(a[0]), "r"(a[1]), "r"(a[2]), "r"(a[3]), "r"(b[0]), "r"(b[1]));
}
__device__ __forceinline__ float tfb(float x) {   // tf32 bits stored as float
    return __uint_as_float(f2tf(x));
}

// ---------------- K0a: transpose x -> g_xt[b][l][c] (fp32) ----------------
__global__ void k_xT(const float* __restrict__ x) {
    __shared__ float t[32][33];
    const int b = blockIdx.z, l0 = blockIdx.x * 32, c0 = blockIdx.y * 32;
    const int tx = threadIdx.x, ty = threadIdx.y;
    const float* xb = x + (size_t)b * C_ * L_;
#pragma unroll
    for (int i = 0; i < 32; i += 8)
        t[ty + i][tx] = xb[(size_t)(c0 + ty + i) * L_ + l0 + tx];
    __syncthreads();
    float* dst = g_xt + (size_t)b * L_ * C_;
#pragma unroll
    for (int i = 0; i < 32; i += 8)
        dst[(size_t)(l0 + ty + i) * C_ + c0 + tx] = t[tx][ty + i];
}

// ---------------- K0b: per-block mean of x (exact fp32) ----------------
// xbar[b][n][c] = (1/64) sum_l x[b][c][n*64+l]
__global__ void k_xbar(const float* __restrict__ x) {
    const int b = blockIdx.x, n = blockIdx.y, c = threadIdx.x;
    const float* p = x + (size_t)b * C_ * L_ + (size_t)c * L_ + n * 64;
    float s = 0.f;
#pragma unroll 8
    for (int l = 0; l < 64; l++) s += p[l];
    g_xbar[(b * NB_ + n) * C_ + c] = s * (1.f / 64.f);
}

// ---------------- K0c: qb/kb = W_{q,k} @ xbar (exact fp32, tiny GEMM) ----------------
// grid (8, 1, B_): o-tile of 64 outputs (o in [0,512): q rows then k rows)
__global__ void k_qbkb(const float* __restrict__ qkv_w) {
    __shared__ float As[16][65];   // xbar [c][n]
    __shared__ float Ws[16][65];   // w    [c][o]
    const int b = blockIdx.z, o0 = blockIdx.x * 64;
    const int tid = threadIdx.x, ty = tid >> 4, tx = tid & 15;
    float acc[4][4] = {};
    const float* xb = g_xbar + (size_t)b * NB_ * C_;
    for (int c0 = 0; c0 < C_; c0 += 16) {
        {   // A: xbar rows n, store transposed As[c][n]
            int i = tid * 4, r = i >> 4, c = i & 15;   // r = n row, c = k-offset
            float4 v = *reinterpret_cast<const float4*>(&xb[(size_t)r * C_ + c0 + c]);
            As[c + 0][r] = v.x; As[c + 1][r] = v.y; As[c + 2][r] = v.z; As[c + 3][r] = v.w;
        }
        {   // W rows o, store transposed Ws[c][o]
            int i = tid * 4, r = i >> 4, c = i & 15;
            float4 v = *reinterpret_cast<const float4*>(&qkv_w[(size_t)(o0 + r) * C_ + c0 + c]);
            Ws[c + 0][r] = v.x; Ws[c + 1][r] = v.y; Ws[c + 2][r] = v.z; Ws[c + 3][r] = v.w;
        }
        __syncthreads();
#pragma unroll
        for (int c = 0; c < 16; c++) {
            float a[4], bb[4];
#pragma unroll
            for (int i = 0; i < 4; i++) a[i] = As[c][ty * 4 + i];     // n
#pragma unroll
            for (int j = 0; j < 4; j++) bb[j] = Ws[c][tx * 4 + j];    // o
#pragma unroll
            for (int i = 0; i < 4; i++)
#pragma unroll
                for (int j = 0; j < 4; j++) acc[i][j] += a[i] * bb[j];
        }
        __syncthreads();
    }
#pragma unroll
    for (int i = 0; i < 4; i++) {
        const int n = ty * 4 + i;
#pragma unroll
        for (int j = 0; j < 4; j++) {
            const int o = o0 + tx * 4 + j;
            const int p = o >> 8, h = (o >> 6) & 3, d = o & 63;
            float* dst = p ? g_kb : g_qb;
            dst[((size_t)(b * NH_ + h) * NB_ + n) * D_ + d] = acc[i][j];
        }
    }
}

// ---------------- K1: fused qkv for ONE head, plain tf32 (means computed exactly elsewhere) ----------------
#define GSTR 36
#define QA 0
#define QB(p) (64*GSTR + (p)*64*GSTR)   // p = 0,1,2
#define QRED  (4*64*GSTR)
#define QREDS (QRED + 128)
#define QKV_SMEM_FLOATS (QREDS + 128)   // 9472 floats = 37888 B

__global__ void __launch_bounds__(256) k_qkv_tc(const float* __restrict__ w) {
    extern __shared__ float qs[];
    float* At = qs + QA;                // tf32 bits
    float* redm = qs + QRED;
    float* reds = qs + QREDS;
    const int b = blockIdx.z, l0 = blockIdx.x * 64, hh = blockIdx.y;
    const int tid = threadIdx.x, w8 = tid >> 5, lane = tid & 31;
    const int gid = lane >> 2, tig = lane & 3;
    const int m0 = (w8 >> 1) * 16, ch = w8 & 1, n0c = ch * 32;
    const int lrow = tid >> 3, cq = (tid & 7) * 4;
    const float* xt = g_xt + (size_t)b * L_ * C_;
    float acc[3][4][4] = {};
    const int ra = m0 + gid, rb = ra + 8;

    for (int c0 = 0; c0 < C_; c0 += 32) {
#pragma unroll
        for (int r = lrow; r < 64; r += 32) {
            float4 v = *reinterpret_cast<const float4*>(&xt[(size_t)(l0 + r) * C_ + c0 + cq]);
            At[r*GSTR+cq+0] = tfb(v.x); At[r*GSTR+cq+1] = tfb(v.y);
            At[r*GSTR+cq+2] = tfb(v.z); At[r*GSTR+cq+3] = tfb(v.w);
        }
#pragma unroll
        for (int p = 0; p < 3; p++) {
            const float* wp = w + (size_t)(p * 256 + hh * 64) * C_;
            float* Bp = qs + QB(p);
#pragma unroll
            for (int r = lrow; r < 64; r += 32) {
                float4 v = *reinterpret_cast<const float4*>(&wp[(size_t)r * C_ + c0 + cq]);
                Bp[r*GSTR+cq+0] = tfb(v.x); Bp[r*GSTR+cq+1] = tfb(v.y);
                Bp[r*GSTR+cq+2] = tfb(v.z); Bp[r*GSTR+cq+3] = tfb(v.w);
            }
        }
        __syncthreads();
#pragma unroll
        for (int kk = 0; kk < 32; kk += 8) {
            unsigned a[4];
            a[0] = __float_as_uint(At[ra*GSTR + kk + tig]);
            a[1] = __float_as_uint(At[rb*GSTR + kk + tig]);
            a[2] = __float_as_uint(At[ra*GSTR + kk + tig + 4]);
            a[3] = __float_as_uint(At[rb*GSTR + kk + tig + 4]);
#pragma unroll
            for (int p = 0; p < 3; p++) {
                const float* Bp = qs + QB(p);
#pragma unroll
                for (int j = 0; j < 4; j++) {
                    const int br = (n0c + 8*j + gid) * GSTR + kk + tig;
                    unsigned b2[2];
                    b2[0] = __float_as_uint(Bp[br]); b2[1] = __float_as_uint(Bp[br + 4]);
                    mma8(acc[p][j], a, b2);
                }
            }
        }
        __syncthreads();
    }

    // ---- store q, k, v tiles ----
#pragma unroll
    for (int p = 0; p < 3; p++) {
        float* dst = ((p == 0) ? g_q : (p == 1) ? g_k : g_v) + (size_t)(b * NH_ + hh) * L_ * D_;
#pragma unroll
        for (int j = 0; j < 4; j++) {
            *reinterpret_cast<float2*>(&dst[(size_t)(l0 + ra) * D_ + n0c + 8*j + 2*tig]) =
                make_float2(acc[p][j][0], acc[p][j][1]);
            *reinterpret_cast<float2*>(&dst[(size_t)(l0 + rb) * D_ + n0c + 8*j + 2*tig]) =
                make_float2(acc[p][j][2], acc[p][j][3]);
        }
    }

    // ---- feature map softmax over d for q (p=0) and k (p=1) ----
#pragma unroll
    for (int p = 0; p < 2; p++) {
        float wma = fmaxf(fmaxf(acc[p][0][0], acc[p][0][1]), fmaxf(acc[p][1][0], acc[p][1][1]));
        wma = fmaxf(wma, fmaxf(fmaxf(acc[p][2][0], acc[p][2][1]), fmaxf(acc[p][3][0], acc[p][3][1])));
        float wmb = fmaxf(fmaxf(acc[p][0][2], acc[p][0][3]), fmaxf(acc[p][1][2], acc[p][1][3]));
        wmb = fmaxf(wmb, fmaxf(fmaxf(acc[p][2][2], acc[p][2][3]), fmaxf(acc[p][3][2], acc[p][3][3])));
        wma = fmaxf(wma, __shfl_xor_sync(0xffffffffu, wma, 1));
        wma = fmaxf(wma, __shfl_xor_sync(0xffffffffu, wma, 2));
        wmb = fmaxf(wmb, __shfl_xor_sync(0xffffffffu, wmb, 1));
        wmb = fmaxf(wmb, __shfl_xor_sync(0xffffffffu, wmb, 2));
        if (tig == 0) { redm[ch * 64 + ra] = wma; redm[ch * 64 + rb] = wmb; }
        __syncthreads();
        float Ma = fmaxf(wma, redm[(ch ^ 1) * 64 + ra]);
        float Mb = fmaxf(wmb, redm[(ch ^ 1) * 64 + rb]);
        float ex[4][4];
        float sa = 0.f, sb = 0.f;
#pragma unroll
        for (int j = 0; j < 4; j++) {
            ex[j][0] = __expf(acc[p][j][0] - Ma);
            ex[j][1] = __expf(acc[p][j][1] - Ma);
            ex[j][2] = __expf(acc[p][j][2] - Mb);
            ex[j][3] = __expf(acc[p][j][3] - Mb);
            sa += ex[j][0] + ex[j][1];
            sb += ex[j][2] + ex[j][3];
        }
        sa += __shfl_xor_sync(0xffffffffu, sa, 1);
        sa += __shfl_xor_sync(0xffffffffu, sa, 2);
        sb += __shfl_xor_sync(0xffffffffu, sb, 1);
        sb += __shfl_xor_sync(0xffffffffu, sb, 2);
        if (tig == 0) { reds[ch * 64 + ra] = sa; reds[ch * 64 + rb] = sb; }
        __syncthreads();
        const float ia = 1.f / (sa + reds[(ch ^ 1) * 64 + ra]);
        const float ib = 1.f / (sb + reds[(ch ^ 1) * 64 + rb]);
        float* cdst = ((p == 0) ? g_cq : g_ck) + (size_t)(b * NH_ + hh) * L_ * D_;
#pragma unroll
        for (int j = 0; j < 4; j++) {
            *reinterpret_cast<float2*>(&cdst[(size_t)(l0 + ra) * D_ + n0c + 8*j + 2*tig]) =
                make_float2(ex[j][0] * ia, ex[j][1] * ia);
            *reinterpret_cast<float2*>(&cdst[(size_t)(l0 + rb) * D_ + n0c + 8*j + 2*tig]) =
                make_float2(ex[j][2] * ib, ex[j][3] * ib);
        }
        __syncthreads();
    }
}

// ---------------- K3: scores + top-6, one warp per query row ----------------
__global__ void __launch_bounds__(256) k_topk() {
    __shared__ float kb[64][65];
    __shared__ float qb8[8][64];
    const int bh = blockIdx.x, rg = blockIdx.y;
    const int tid = threadIdx.x, w = tid >> 5, lane = tid & 31;
    for (int i = tid; i < 4096; i += 256) kb[i >> 6][i & 63] = g_kb[(size_t)bh * 4096 + i];
    for (int i = tid; i < 512; i += 256) qb8[i >> 6][i & 63] = g_qb[(size_t)bh * 4096 + rg * 512 + i];
    __syncthreads();
    float s0 = 0.f, s1 = 0.f;
#pragma unroll 8
    for (int d = 0; d < 64; d++) {
        float qv = qb8[w][d];
        s0 += qv * kb[lane][d];
        s1 += qv * kb[lane + 32][d];
    }
    const int r = rg * 8 + w;
    int* lp = g_lut + ((size_t)bh * NB_ + r) * T_;
#pragma unroll
    for (int t = 0; t < T_; t++) {
        float v; int idx;
        if (s0 >= s1) { v = s0; idx = lane; } else { v = s1; idx = lane + 32; }
#pragma unroll
        for (int o = 16; o; o >>= 1) {
            float ov = __shfl_xor_sync(0xffffffffu, v, o);
            int   oi = __shfl_xor_sync(0xffffffffu, idx, o);
            if (ov > v || (ov == v && oi < idx)) { v = ov; idx = oi; }
        }
        if (lane == 0) lp[t] = idx;
        if (idx == lane) s0 = -3.4e38f;
        else if (idx == lane + 32) s1 = -3.4e38f;
    }
}

// ---------------- K4: sparse attention, tf32 mma, pre-converted smem ----------------
#define QS_OFF 0
#define KS_OFF (64*68)
#define VS_OFF (2*64*68)
#define RM_OFF (2*64*68 + 64*72)
#define RS_OFF (RM_OFF + 2*64)
#define SATTN_SMEM_FLOATS (RS_OFF + 2*64)

__global__ void __launch_bounds__(256, 3) k_sattn() {
    extern __shared__ float sm[];
    float* Qs = sm + QS_OFF;
    float* Ks = sm + KS_OFF;
    float* Vs = sm + VS_OFF;
    float* redm = sm + RM_OFF;
    float* reds = sm + RS_OFF;
    __shared__ int luts[8];
    const int n = blockIdx.x, bh = blockIdx.y;
    const int tid = threadIdx.x;
    const int w = tid >> 5, lane = tid & 31;
    const int gid = lane >> 2, tig = lane & 3;
    const int m0 = (w >> 1) * 16;
    const int ch = w & 1;
    const int n0c = ch * 32;

    const float* qp = g_q + ((size_t)bh * L_ + n * 64) * D_;
    for (int i = tid * 4; i < 4096; i += 1024) {
        int r = i >> 6, d = i & 63;
        float4 v = *reinterpret_cast<const float4*>(&qp[i]);
        Qs[r * 68 + d + 0] = tfb(v.x); Qs[r * 68 + d + 1] = tfb(v.y);
        Qs[r * 68 + d + 2] = tfb(v.z); Qs[r * 68 + d + 3] = tfb(v.w);
    }
    if (tid < T_) luts[tid] = g_lut[((size_t)bh * NB_ + n) * T_ + tid];
    __syncthreads();

    float oacc[4][4] = {};
    float m_a = -1e30f, m_b = -1e30f, l_a = 0.f, l_b = 0.f;
    const int ra = m0 + gid, rb = m0 + gid + 8;

    for (int t = 0; t < T_; t++) {
        const float* kp = g_k + ((size_t)bh * L_ + luts[t] * 64) * D_;
        const float* vp = g_v + ((size_t)bh * L_ + luts[t] * 64) * D_;
        for (int i = tid * 4; i < 4096; i += 1024) {
            int r = i >> 6, d = i & 63;
            float4 kv = *reinterpret_cast<const float4*>(&kp[i]);
            Ks[r * 68 + d + 0] = tfb(kv.x); Ks[r * 68 + d + 1] = tfb(kv.y);
            Ks[r * 68 + d + 2] = tfb(kv.z); Ks[r * 68 + d + 3] = tfb(kv.w);
            float4 vv = *reinterpret_cast<const float4*>(&vp[i]);
            Vs[r * 72 + d + 0] = tfb(vv.x); Vs[r * 72 + d + 1] = tfb(vv.y);
            Vs[r * 72 + d + 2] = tfb(vv.z); Vs[r * 72 + d + 3] = tfb(vv.w);
        }
        __syncthreads();

        float sacc[4][4] = {};
#pragma unroll
        for (int kk = 0; kk < 64; kk += 8) {
            unsigned a[4];
            a[0] = __float_as_uint(Qs[ra * 68 + kk + tig]);
            a[1] = __float_as_uint(Qs[rb * 68 + kk + tig]);
            a[2] = __float_as_uint(Qs[ra * 68 + kk + tig + 4]);
            a[3] = __float_as_uint(Qs[rb * 68 + kk + tig + 4]);
#pragma unroll
            for (int j = 0; j < 4; j++) {
                unsigned b[2];
                b[0] = __float_as_uint(Ks[(n0c + 8 * j + gid) * 68 + kk + tig]);
                b[1] = __float_as_uint(Ks[(n0c + 8 * j + gid) * 68 + kk + tig + 4]);
                mma8(sacc[j], a, b);
            }
        }
#pragma unroll
        for (int j = 0; j < 4; j++)
#pragma unroll
            for (int r = 0; r < 4; r++) sacc[j][r] *= 0.125f;

        float wma = fmaxf(fmaxf(sacc[0][0], sacc[0][1]), fmaxf(sacc[1][0], sacc[1][1]));
        wma = fmaxf(wma, fmaxf(fmaxf(sacc[2][0], sacc[2][1]), fmaxf(sacc[3][0], sacc[3][1])));
        float wmb = fmaxf(fmaxf(sacc[0][2], sacc[0][3]), fmaxf(sacc[1][2], sacc[1][3]));
        wmb = fmaxf(wmb, fmaxf(fmaxf(sacc[2][2], sacc[2][3]), fmaxf(sacc[3][2], sacc[3][3])));
        wma = fmaxf(wma, __shfl_xor_sync(0xffffffffu, wma, 1));
        wma = fmaxf(wma, __shfl_xor_sync(0xffffffffu, wma, 2));
        wmb = fmaxf(wmb, __shfl_xor_sync(0xffffffffu, wmb, 1));
        wmb = fmaxf(wmb, __shfl_xor_sync(0xffffffffu, wmb, 2));
        if (tig == 0) { redm[ch * 64 + ra] = wma; redm[ch * 64 + rb] = wmb; }
        __syncthreads();
        float Ma = fmaxf(wma, redm[(ch ^ 1) * 64 + ra]);
        float Mb = fmaxf(wmb, redm[(ch ^ 1) * 64 + rb]);
        float nma = fmaxf(m_a, Ma), nmb = fmaxf(m_b, Mb);
        float ca = __expf(m_a - nma), cb = __expf(m_b - nmb);
        m_a = nma; m_b = nmb;

        float sa = 0.f, sb = 0.f;
#pragma unroll
        for (int j = 0; j < 4; j++) {
            sacc[j][0] = __expf(sacc[j][0] - nma);
            sacc[j][1] = __expf(sacc[j][1] - nma);
            sacc[j][2] = __expf(sacc[j][2] - nmb);
            sacc[j][3] = __expf(sacc[j][3] - nmb);
            sa += sacc[j][0] + sacc[j][1];
            sb += sacc[j][2] + sacc[j][3];
        }
        sa += __shfl_xor_sync(0xffffffffu, sa, 1);
        sa += __shfl_xor_sync(0xffffffffu, sa, 2);
        sb += __shfl_xor_sync(0xffffffffu, sb, 1);
        sb += __shfl_xor_sync(0xffffffffu, sb, 2);

#pragma unroll
        for (int j = 0; j < 4; j++) {
            *reinterpret_cast<float2*>(&Ks[ra * 68 + n0c + 8 * j + 2 * tig]) =
                make_float2(tfb(sacc[j][0]), tfb(sacc[j][1]));
            *reinterpret_cast<float2*>(&Ks[rb * 68 + n0c + 8 * j + 2 * tig]) =
                make_float2(tfb(sacc[j][2]), tfb(sacc[j][3]));
        }
        if (tig == 0) { reds[ch * 64 + ra] = sa; reds[ch * 64 + rb] = sb; }
        __syncthreads();
        l_a = l_a * ca + sa + reds[(ch ^ 1) * 64 + ra];
        l_b = l_b * cb + sb + reds[(ch ^ 1) * 64 + rb];
#pragma unroll
        for (int j = 0; j < 4; j++) {
            oacc[j][0] *= ca; oacc[j][1] *= ca;
            oacc[j][2] *= cb; oacc[j][3] *= cb;
        }

#pragma unroll
        for (int kk = 0; kk < 64; kk += 8) {
            unsigned a[4];
            a[0] = __float_as_uint(Ks[ra * 68 + kk + tig]);
            a[1] = __float_as_uint(Ks[rb * 68 + kk + tig]);
            a[2] = __float_as_uint(Ks[ra * 68 + kk + tig + 4]);
            a[3] = __float_as_uint(Ks[rb * 68 + kk + tig + 4]);
#pragma unroll
            for (int j = 0; j < 4; j++) {
                unsigned b[2];
                b[0] = __float_as_uint(Vs[(kk + tig) * 72 + n0c + 8 * j + gid]);
                b[1] = __float_as_uint(Vs[(kk + tig + 4) * 72 + n0c + 8 * j + gid]);
                mma8(oacc[j], a, b);
            }
        }
        __syncthreads();
    }

    const float ia = 1.f / l_a, ib = 1.f / l_b;
    float* op = g_obuf + ((size_t)bh * L_ + n * 64) * D_;
#pragma unroll
    for (int j = 0; j < 4; j++) {
        *reinterpret_cast<float2*>(&op[ra * 64 + n0c + 8 * j + 2 * tig]) =
            make_float2(oacc[j][0] * ia, oacc[j][1] * ia);
        *reinterpret_cast<float2*>(&op[rb * 64 + n0c + 8 * j + 2 * tig]) =
            make_float2(oacc[j][2] * ib, oacc[j][3] * ib);
    }
}

// ---------------- K5b: kvb = cK^T @ V via tf32 MMA; ksum = colsum(cK) ----------------
__global__ void __launch_bounds__(256) k_kvb() {
    __shared__ float CKt[64*68];
    __shared__ float Vsb[64*72];
    const int m = blockIdx.x, bh = blockIdx.y;
    const int tid = threadIdx.x, w8 = tid >> 5, lane = tid & 31;
    const int gid = lane >> 2, tig = lane & 3;
    const int m0 = (w8 >> 1) * 16, ch = w8 & 1, n0c = ch * 32;
    const int lr = tid & 15, ld4 = (tid >> 4) * 4;
    const float* ckp = g_ck + ((size_t)bh * L_ + m * 64) * D_;
    const float* vp  = g_v  + ((size_t)bh * L_ + m * 64) * D_;
#pragma unroll
    for (int rep = 0; rep < 4; rep++) {
        int r = lr + rep * 16;
        float4 kv = *reinterpret_cast<const float4*>(&ckp[r * 64 + ld4]);
        CKt[(ld4 + 0) * 68 + r] = kv.x;
        CKt[(ld4 + 1) * 68 + r] = kv.y;
        CKt[(ld4 + 2) * 68 + r] = kv.z;
        CKt[(ld4 + 3) * 68 + r] = kv.w;
    }
    for (int i = tid * 4; i < 4096; i += 1024) {
        int r = i >> 6, d = i & 63;
        float4 vv = *reinterpret_cast<const float4*>(&vp[i]);
        Vsb[r * 72 + d + 0] = tfb(vv.x); Vsb[r * 72 + d + 1] = tfb(vv.y);
        Vsb[r * 72 + d + 2] = tfb(vv.z); Vsb[r * 72 + d + 3] = tfb(vv.w);
    }
    __syncthreads();
    const int ra = m0 + gid, rb = ra + 8;
    float acc[4][4] = {};
#pragma unroll
    for (int kk = 0; kk < 64; kk += 8) {
        unsigned a[4];
        a[0] = f2tf(CKt[ra * 68 + kk + tig]);
        a[1] = f2tf(CKt[rb * 68 + kk + tig]);
        a[2] = f2tf(CKt[ra * 68 + kk + tig + 4]);
        a[3] = f2tf(CKt[rb * 68 + kk + tig + 4]);
#pragma unroll
        for (int j = 0; j < 4; j++) {
            unsigned b[2];
            b[0] = __float_as_uint(Vsb[(kk + tig) * 72 + n0c + 8 * j + gid]);
            b[1] = __float_as_uint(Vsb[(kk + tig + 4) * 72 + n0c + 8 * j + gid]);
            mma8(acc[j], a, b);
        }
    }
    float* dst = g_kvb + (size_t)(bh * NB_ + m) * D_ * D_;
#pragma unroll
    for (int j = 0; j < 4; j++) {
        *reinterpret_cast<float2*>(&dst[ra * 64 + n0c + 8 * j + 2 * tig]) =
            make_float2(acc[j][0], acc[j][1]);
        *reinterpret_cast<float2*>(&dst[rb * 64 + n0c + 8 * j + 2 * tig]) =
            make_float2(acc[j][2], acc[j][3]);
    }
    if (tid < 64) {
        float s = 0.f;
#pragma unroll 8
        for (int k = 0; k < 64; k++) s += CKt[tid * 68 + k];
        g_ksum[(size_t)(bh * NB_ + m) * D_ + tid] = s;
    }
}

// ---------------- K5c: totals, parallel grid ----------------
__global__ void k_totals() {
    const int bh = blockIdx.x, ch = blockIdx.y, tid = threadIdx.x;
    if (ch < 8) {
#pragma unroll
        for (int rep = 0; rep < 2; rep++) {
            const int i = ch * 512 + rep * 256 + tid;
            const float* p = g_kvb + (size_t)bh * NB_ * 4096 + i;
            float s = 0.f;
#pragma unroll 8
            for (int m = 0; m < 64; m++) s += p[(size_t)m * 4096];
            g_kvt[(size_t)bh * 4096 + i] = s;
        }
    } else if (tid < 64) {
        const float* p = g_ksum + (size_t)bh * NB_ * 64 + tid;
        float s = 0.f;
#pragma unroll 8
        for (int m = 0; m < 64; m++) s += p[m * 64];
        g_kst[bh * 64 + tid] = s;
    }
}

// ---------------- K5d: linear path via tf32 MMA; writes o_l + bias ----------------
__global__ void __launch_bounds__(256) k_lin(const float* __restrict__ plw, const float* __restrict__ plb) {
    __shared__ float KVQ[64*72];
    __shared__ float CQb[64*68];
    __shared__ float ksq[64], den_s[64], plbs[64];
    __shared__ int luts[8];
    const int n = blockIdx.x, bh = blockIdx.y;
    const int tid = threadIdx.x, w8 = tid >> 5, lane = tid & 31;
    const int gid = lane >> 2, tig = lane & 3;
    const int m0 = (w8 >> 1) * 16, ch = w8 & 1, n0c = ch * 32;
    const int ra = m0 + gid, rb = ra + 8;
    if (tid < T_) luts[tid] = g_lut[((size_t)bh * NB_ + n) * T_ + tid];
    if (tid >= 64 && tid < 128) plbs[tid - 64] = plb[tid - 64];
    __syncthreads();
    for (int i = tid; i < 4096; i += 256) {
        float s = g_kvt[(size_t)bh * 4096 + i];
#pragma unroll
        for (int t = 0; t < T_; t++) s -= g_kvb[(size_t)(bh * NB_ + luts[t]) * 4096 + i];
        KVQ[(i >> 6) * 72 + (i & 63)] = s;
    }
    if (tid < 64) {
        float s = g_kst[bh * 64 + tid];
#pragma unroll
        for (int t = 0; t < T_; t++) s -= g_ksum[(size_t)(bh * NB_ + luts[t]) * 64 + tid];
        ksq[tid] = s;
    }
    const float* cqp = g_cq + ((size_t)bh * L_ + n * 64) * D_;
    for (int i = tid * 4; i < 4096; i += 1024) {
        int r = i >> 6, d = i & 63;
        *reinterpret_cast<float4*>(&CQb[r * 68 + d]) = *reinterpret_cast<const float4*>(&cqp[i]);
    }
    __syncthreads();
    if (tid < 64) {
        float s = 0.f;
#pragma unroll 8
        for (int d = 0; d < 64; d++) s += CQb[tid * 68 + d] * ksq[d];
        den_s[tid] = s;
    }
    float acc[4][4] = {};
#pragma unroll
    for (int kk = 0; kk < 64; kk += 8) {
        unsigned a[4];
        a[0] = f2tf(CQb[ra * 68 + kk + tig]);
        a[1] = f2tf(CQb[rb * 68 + kk + tig]);
        a[2] = f2tf(CQb[ra * 68 + kk + tig + 4]);
        a[3] = f2tf(CQb[rb * 68 + kk + tig + 4]);
#pragma unroll
        for (int j = 0; j < 4; j++) {
            unsigned b[2];
            b[0] = f2tf(KVQ[(kk + tig) * 72 + n0c + 8 * j + gid]);
            b[1] = f2tf(KVQ[(kk + tig + 4) * 72 + n0c + 8 * j + gid]);
            mma8(acc[j], a, b);
        }
    }
    __syncthreads();
    const float ia = 1.f / (den_s[ra] + 1e-6f);
    const float ib = 1.f / (den_s[rb] + 1e-6f);
#pragma unroll
    for (int j = 0; j < 4; j++) {
        *reinterpret_cast<float2*>(&CQb[ra * 68 + n0c + 8 * j + 2 * tig]) =
            make_float2(acc[j][0] * ia, acc[j][1] * ia);
        *reinterpret_cast<float2*>(&CQb[rb * 68 + n0c + 8 * j + 2 * tig]) =
            make_float2(acc[j][2] * ib, acc[j][3] * ib);
    }
    for (int i = tid * 4; i < 4096; i += 1024) {
        int e2 = i >> 6, e = i & 63;
        float4 v = *reinterpret_cast<const float4*>(&plw[i]);
        *reinterpret_cast<float4*>(&KVQ[e2 * 68 + e]) = v;
    }
    __syncthreads();
    float acc2[4][4] = {};
#pragma unroll
    for (int kk = 0; kk < 64; kk += 8) {
        unsigned a[4];
        a[0] = f2tf(CQb[ra * 68 + kk + tig]);
        a[1] = f2tf(CQb[rb * 68 + kk + tig]);
        a[2] = f2tf(CQb[ra * 68 + kk + tig + 4]);
        a[3] = f2tf(CQb[rb * 68 + kk + tig + 4]);
#pragma unroll
        for (int j = 0; j < 4; j++) {
            unsigned b[2];
            b[0] = f2tf(KVQ[(n0c + 8 * j + gid) * 68 + kk + tig]);
            b[1] = f2tf(KVQ[(n0c + 8 * j + gid) * 68 + kk + tig + 4]);
            mma8(acc2[j], a, b);
        }
    }
    float* op = g_olin + ((size_t)bh * L_ + n * 64) * D_;
#pragma unroll
    for (int j = 0; j < 4; j++) {
        const int col = n0c + 8 * j + 2 * tig;
        *reinterpret_cast<float2*>(&op[ra * 64 + col]) =
            make_float2(acc2[j][0] + plbs[col], acc2[j][1] + plbs[col + 1]);
        *reinterpret_cast<float2*>(&op[rb * 64 + col]) =
            make_float2(acc2[j][2] + plbs[col], acc2[j][3] + plbs[col + 1]);
    }
}

// ---------------- K6: out_proj via PLAIN tf32 MMA; B = tfb(obuf + olin) at STS ----------------
__global__ void __launch_bounds__(256) k_outproj_tc(const float* __restrict__ w2, float* __restrict__ out) {
    __shared__ float Ah[64*GSTR], Bh[64*GSTR];
    const int b = blockIdx.z, l0 = blockIdx.x * 64, co0 = blockIdx.y * 64;
    const int tid = threadIdx.x, w8 = tid >> 5, lane = tid & 31;
    const int gid = lane >> 2, tig = lane & 3;
    const int m0 = (w8 >> 1) * 16, ch = w8 & 1, n0c = ch * 32;
    const int lrow = tid >> 3, cq = (tid & 7) * 4;
    const int ra = m0 + gid, rb = ra + 8;
    float acc[4][4] = {};

    for (int c0 = 0; c0 < C_; c0 += 32) {
        const int hh = c0 >> 6, d0 = c0 & 63;
        const size_t bbase = ((size_t)(b * NH_ + hh) * L_ + l0) * D_ + d0;
#pragma unroll
        for (int r = lrow; r < 64; r += 32) {
            float4 wv = *reinterpret_cast<const float4*>(&w2[(size_t)(co0 + r) * C_ + c0 + cq]);
            Ah[r*GSTR+cq+0] = tfb(wv.x); Ah[r*GSTR+cq+1] = tfb(wv.y);
            Ah[r*GSTR+cq+2] = tfb(wv.z); Ah[r*GSTR+cq+3] = tfb(wv.w);
            float4 v = *reinterpret_cast<const float4*>(&g_obuf[bbase + (size_t)r * D_ + cq]);
            float4 u = *reinterpret_cast<const float4*>(&g_olin[bbase + (size_t)r * D_ + cq]);
            Bh[r*GSTR+cq+0] = tfb(v.x + u.x); Bh[r*GSTR+cq+1] = tfb(v.y + u.y);
            Bh[r*GSTR+cq+2] = tfb(v.z + u.z); Bh[r*GSTR+cq+3] = tfb(v.w + u.w);
        }
        __syncthreads();
#pragma unroll
        for (int kk = 0; kk < 32; kk += 8) {
            unsigned ah[4];
            ah[0] = __float_as_uint(Ah[ra*GSTR + kk + tig]);
            ah[1] = __float_as_uint(Ah[rb*GSTR + kk + tig]);
            ah[2] = __float_as_uint(Ah[ra*GSTR + kk + tig + 4]);
            ah[3] = __float_as_uint(Ah[rb*GSTR + kk + tig + 4]);
#pragma unroll
            for (int j = 0; j < 4; j++) {
                const int br = (n0c + 8*j + gid) * GSTR + kk + tig;
                unsigned bh2[2];
                bh2[0] = __float_as_uint(Bh[br]); bh2[1] = __float_as_uint(Bh[br + 4]);
                mma8(acc[j], ah, bh2);
            }
        }
        __syncthreads();
    }
    float* ob = out + (size_t)b * C_ * L_;
#pragma unroll
    for (int j = 0; j < 4; j++) {
        *reinterpret_cast<float2*>(&ob[(size_t)(co0 + ra) * L_ + l0 + n0c + 8*j + 2*tig]) =
            make_float2(acc[j][0], acc[j][1]);
        *reinterpret_cast<float2*>(&ob[(size_t)(co0 + rb) * L_ + l0 + n0c + 8*j + 2*tig]) =
            make_float2(acc[j][2], acc[j][3]);
    }
}

// ---------------- launch: two-branch stream fork inside graph capture ----------------
extern "C" void kernel_launch(void* const* d_in, const int* in_sizes, int n_in,
                              void* d_out, int out_size) {
    const float* x     = (const float*)d_in[0];
    const float* qkv_w = (const float*)d_in[1];
    const float* out_w = (const float*)d_in[2];
    const float* plw   = (const float*)d_in[3];
    const float* plb   = (const float*)d_in[4];
    float* out = (float*)d_out;

    static cudaStream_t s2 = nullptr;
    static cudaEvent_t evFork = nullptr, evT = nullptr, evQ = nullptr, evJoin = nullptr;
    if (s2 == nullptr) {
        cudaStreamCreateWithFlags(&s2, cudaStreamNonBlocking);
        cudaEventCreateWithFlags(&evFork, cudaEventDisableTiming);
        cudaEventCreateWithFlags(&evT,    cudaEventDisableTiming);
        cudaEventCreateWithFlags(&evQ,    cudaEventDisableTiming);
        cudaEventCreateWithFlags(&evJoin, cudaEventDisableTiming);
        cudaFuncSetAttribute(k_sattn, cudaFuncAttributeMaxDynamicSharedMemorySize,
                             SATTN_SMEM_FLOATS * (int)sizeof(float));
        cudaFuncSetAttribute(k_qkv_tc, cudaFuncAttributeMaxDynamicSharedMemorySize,
                             QKV_SMEM_FLOATS * (int)sizeof(float));
    }
    const int sattn_smem = SATTN_SMEM_FLOATS * (int)sizeof(float); // 54272 B
    const int qkv_smem   = QKV_SMEM_FLOATS * (int)sizeof(float);   // 37888 B

    cudaEventRecord(evFork, 0);
    cudaStreamWaitEvent(s2, evFork, 0);

    // branch B: exact block-mean path -> topk (independent of qkv!)
    k_xbar<<<dim3(B_, NB_), 256, 0, s2>>>(x);
    k_qbkb<<<dim3(8, 1, B_), 256, 0, s2>>>(qkv_w);
    k_topk<<<dim3(BH_, 8), 256, 0, s2>>>();
    cudaEventRecord(evT, s2);

    // branch A: x transpose -> fused qkv (plain tf32)
    k_xT<<<dim3(L_ / 32, C_ / 32, B_), dim3(32, 8)>>>(x);
    k_qkv_tc<<<dim3(L_ / 64, NH_, B_), 256, qkv_smem>>>(qkv_w);
    cudaEventRecord(evQ, 0);

    // branch B: kvb + totals + lin (o_l path), overlapped with sattn
    cudaStreamWaitEvent(s2, evQ, 0);
    k_kvb   <<<dim3(NB_, BH_), 256, 0, s2>>>();
    k_totals<<<dim3(BH_, 9), 256, 0, s2>>>();
    k_lin   <<<dim3(NB_, BH_), 256, 0, s2>>>(plw, plb);
    cudaEventRecord(evJoin, s2);

    // branch A: sattn (needs lut from branch B + q/k/v from program order)
    cudaStreamWaitEvent(0, evT, 0);
    k_sattn<<<dim3(NB_, BH_), 256, sattn_smem>>>();

    // join, then out_proj (plain tf32)
    cudaStreamWaitEvent(0, evJoin, 0);
    k_outproj_tc<<<dim3(L_ / 64, C_ / 64, B_), 256>>>(out_w, out);
}

// round 16
// speedup vs baseline: 1.2553x; 1.0079x over previous
#include <cuda_runtime.h>

#define B_ 8
#define C_ 256
#define L_ 4096
#define NH_ 4
#define D_ 64
#define NB_ 64   // number of query/key blocks (L/64)
#define T_ 6     // top-k blocks
#define BH_ 32   // B*NH

// ---------------- scratch (device globals; no allocs) ----------------
__device__ float g_xt[(size_t)B_*C_*L_];   // x transposed: [b][l][c] (fp32)
__device__ float g_xbar[B_*NB_*C_];        // per-block mean of x: [b][n][c]
__device__ float g_q [BH_*L_*D_];          // PRE-ROUNDED tf32 values
__device__ float g_k [BH_*L_*D_];          // PRE-ROUNDED tf32 values
__device__ float g_v [BH_*L_*D_];          // PRE-ROUNDED tf32 values
__device__ float g_cq[BH_*L_*D_];
__device__ float g_ck[BH_*L_*D_];
__device__ float g_qb[BH_*NB_*D_];
__device__ float g_kb[BH_*NB_*D_];
__device__ int   g_lut[BH_*NB_*T_];
__device__ float g_kvb[(size_t)BH_*NB_*D_*D_];
__device__ float g_ksum[BH_*NB_*D_];
__device__ float g_kvt[BH_*D_*D_];
__device__ float g_kst[BH_*D_];
__device__ float g_obuf[BH_*L_*D_];   // o_s from sattn (fp32)
__device__ float g_olin[BH_*L_*D_];   // o_l + bias from k_lin (fp32)

// ---------------- tf32 mma helpers ----------------
__device__ __forceinline__ unsigned f2tf(float f) {
    unsigned u; asm("cvt.rna.tf32.f32 %0, %1;" : "=r"(u) : "f"(f)); return u;
}
__device__ __forceinline__ void mma8(float d[4], const unsigned a[4], const unsigned b[2]) {
    asm("mma.sync.aligned.m16n8k8.row.col.f32.tf32.tf32.f32 "
        "{%0,%1,%2,%3}, {%4,%5,%6,%7}, {%8,%9}, {%0,%1,%2,%3};"
        : "+f"(d[0]), "+f"(d[1]), "+f"(d[2]), "+f"(d[3])
        : "r"(a[0]), "r"(a[1]), "r"(a[2]), "r"(a[3]), "r"(b[0]), "r"(b[1]));
}
__device__ __forceinline__ float tfb(float x) {   // tf32 bits stored as float
    return __uint_as_float(f2tf(x));
}

// ---------------- K0a: transpose x -> g_xt[b][l][c] (fp32) ----------------
__global__ void k_xT(const float* __restrict__ x) {
    __shared__ float t[32][33];
    const int b = blockIdx.z, l0 = blockIdx.x * 32, c0 = blockIdx.y * 32;
    const int tx = threadIdx.x, ty = threadIdx.y;
    const float* xb = x + (size_t)b * C_ * L_;
#pragma unroll
    for (int i = 0; i < 32; i += 8)
        t[ty + i][tx] = xb[(size_t)(c0 + ty + i) * L_ + l0 + tx];
    __syncthreads();
    float* dst = g_xt + (size_t)b * L_ * C_;
#pragma unroll
    for (int i = 0; i < 32; i += 8)
        dst[(size_t)(l0 + ty + i) * C_ + c0 + tx] = t[tx][ty + i];
}

// ---------------- K0b: per-block mean of x (exact fp32) ----------------
__global__ void k_xbar(const float* __restrict__ x) {
    const int b = blockIdx.x, n = blockIdx.y, c = threadIdx.x;
    const float* p = x + (size_t)b * C_ * L_ + (size_t)c * L_ + n * 64;
    float s = 0.f;
#pragma unroll 8
    for (int l = 0; l < 64; l++) s += p[l];
    g_xbar[(b * NB_ + n) * C_ + c] = s * (1.f / 64.f);
}

// ---------------- K0c: qb/kb = W_{q,k} @ xbar (exact fp32, tiny GEMM) ----------------
__global__ void k_qbkb(const float* __restrict__ qkv_w) {
    __shared__ float As[16][65];
    __shared__ float Ws[16][65];
    const int b = blockIdx.z, o0 = blockIdx.x * 64;
    const int tid = threadIdx.x, ty = tid >> 4, tx = tid & 15;
    float acc[4][4] = {};
    const float* xb = g_xbar + (size_t)b * NB_ * C_;
    for (int c0 = 0; c0 < C_; c0 += 16) {
        {
            int i = tid * 4, r = i >> 4, c = i & 15;
            float4 v = *reinterpret_cast<const float4*>(&xb[(size_t)r * C_ + c0 + c]);
            As[c + 0][r] = v.x; As[c + 1][r] = v.y; As[c + 2][r] = v.z; As[c + 3][r] = v.w;
        }
        {
            int i = tid * 4, r = i >> 4, c = i & 15;
            float4 v = *reinterpret_cast<const float4*>(&qkv_w[(size_t)(o0 + r) * C_ + c0 + c]);
            Ws[c + 0][r] = v.x; Ws[c + 1][r] = v.y; Ws[c + 2][r] = v.z; Ws[c + 3][r] = v.w;
        }
        __syncthreads();
#pragma unroll
        for (int c = 0; c < 16; c++) {
            float a[4], bb[4];
#pragma unroll
            for (int i = 0; i < 4; i++) a[i] = As[c][ty * 4 + i];
#pragma unroll
            for (int j = 0; j < 4; j++) bb[j] = Ws[c][tx * 4 + j];
#pragma unroll
            for (int i = 0; i < 4; i++)
#pragma unroll
                for (int j = 0; j < 4; j++) acc[i][j] += a[i] * bb[j];
        }
        __syncthreads();
    }
#pragma unroll
    for (int i = 0; i < 4; i++) {
        const int n = ty * 4 + i;
#pragma unroll
        for (int j = 0; j < 4; j++) {
            const int o = o0 + tx * 4 + j;
            const int p = o >> 8, h = (o >> 6) & 3, d = o & 63;
            float* dst = p ? g_kb : g_qb;
            dst[((size_t)(b * NH_ + h) * NB_ + n) * D_ + d] = acc[i][j];
        }
    }
}

// ---------------- K1: fused qkv for ONE head, plain tf32; q/k/v stored PRE-ROUNDED ----------------
#define GSTR 36
#define QA 0
#define QB(p) (64*GSTR + (p)*64*GSTR)   // p = 0,1,2
#define QRED  (4*64*GSTR)
#define QREDS (QRED + 128)
#define QKV_SMEM_FLOATS (QREDS + 128)   // 9472 floats = 37888 B

__global__ void __launch_bounds__(256) k_qkv_tc(const float* __restrict__ w) {
    extern __shared__ float qs[];
    float* At = qs + QA;                // tf32 bits
    float* redm = qs + QRED;
    float* reds = qs + QREDS;
    const int b = blockIdx.z, l0 = blockIdx.x * 64, hh = blockIdx.y;
    const int tid = threadIdx.x, w8 = tid >> 5, lane = tid & 31;
    const int gid = lane >> 2, tig = lane & 3;
    const int m0 = (w8 >> 1) * 16, ch = w8 & 1, n0c = ch * 32;
    const int lrow = tid >> 3, cq = (tid & 7) * 4;
    const float* xt = g_xt + (size_t)b * L_ * C_;
    float acc[3][4][4] = {};
    const int ra = m0 + gid, rb = ra + 8;

    for (int c0 = 0; c0 < C_; c0 += 32) {
#pragma unroll
        for (int r = lrow; r < 64; r += 32) {
            float4 v = *reinterpret_cast<const float4*>(&xt[(size_t)(l0 + r) * C_ + c0 + cq]);
            At[r*GSTR+cq+0] = tfb(v.x); At[r*GSTR+cq+1] = tfb(v.y);
            At[r*GSTR+cq+2] = tfb(v.z); At[r*GSTR+cq+3] = tfb(v.w);
        }
#pragma unroll
        for (int p = 0; p < 3; p++) {
            const float* wp = w + (size_t)(p * 256 + hh * 64) * C_;
            float* Bp = qs + QB(p);
#pragma unroll
            for (int r = lrow; r < 64; r += 32) {
                float4 v = *reinterpret_cast<const float4*>(&wp[(size_t)r * C_ + c0 + cq]);
                Bp[r*GSTR+cq+0] = tfb(v.x); Bp[r*GSTR+cq+1] = tfb(v.y);
                Bp[r*GSTR+cq+2] = tfb(v.z); Bp[r*GSTR+cq+3] = tfb(v.w);
            }
        }
        __syncthreads();
#pragma unroll
        for (int kk = 0; kk < 32; kk += 8) {
            unsigned a[4];
            a[0] = __float_as_uint(At[ra*GSTR + kk + tig]);
            a[1] = __float_as_uint(At[rb*GSTR + kk + tig]);
            a[2] = __float_as_uint(At[ra*GSTR + kk + tig + 4]);
            a[3] = __float_as_uint(At[rb*GSTR + kk + tig + 4]);
#pragma unroll
            for (int p = 0; p < 3; p++) {
                const float* Bp = qs + QB(p);
#pragma unroll
                for (int j = 0; j < 4; j++) {
                    const int br = (n0c + 8*j + gid) * GSTR + kk + tig;
                    unsigned b2[2];
                    b2[0] = __float_as_uint(Bp[br]); b2[1] = __float_as_uint(Bp[br + 4]);
                    mma8(acc[p][j], a, b2);
                }
            }
        }
        __syncthreads();
    }

    // ---- store q, k, v tiles PRE-ROUNDED to tf32 ----
#pragma unroll
    for (int p = 0; p < 3; p++) {
        float* dst = ((p == 0) ? g_q : (p == 1) ? g_k : g_v) + (size_t)(b * NH_ + hh) * L_ * D_;
#pragma unroll
        for (int j = 0; j < 4; j++) {
            *reinterpret_cast<float2*>(&dst[(size_t)(l0 + ra) * D_ + n0c + 8*j + 2*tig]) =
                make_float2(tfb(acc[p][j][0]), tfb(acc[p][j][1]));
            *reinterpret_cast<float2*>(&dst[(size_t)(l0 + rb) * D_ + n0c + 8*j + 2*tig]) =
                make_float2(tfb(acc[p][j][2]), tfb(acc[p][j][3]));
        }
    }

    // ---- feature map softmax over d for q (p=0) and k (p=1); uses full-precision acc ----
#pragma unroll
    for (int p = 0; p < 2; p++) {
        float wma = fmaxf(fmaxf(acc[p][0][0], acc[p][0][1]), fmaxf(acc[p][1][0], acc[p][1][1]));
        wma = fmaxf(wma, fmaxf(fmaxf(acc[p][2][0], acc[p][2][1]), fmaxf(acc[p][3][0], acc[p][3][1])));
        float wmb = fmaxf(fmaxf(acc[p][0][2], acc[p][0][3]), fmaxf(acc[p][1][2], acc[p][1][3]));
        wmb = fmaxf(wmb, fmaxf(fmaxf(acc[p][2][2], acc[p][2][3]), fmaxf(acc[p][3][2], acc[p][3][3])));
        wma = fmaxf(wma, __shfl_xor_sync(0xffffffffu, wma, 1));
        wma = fmaxf(wma, __shfl_xor_sync(0xffffffffu, wma, 2));
        wmb = fmaxf(wmb, __shfl_xor_sync(0xffffffffu, wmb, 1));
        wmb = fmaxf(wmb, __shfl_xor_sync(0xffffffffu, wmb, 2));
        if (tig == 0) { redm[ch * 64 + ra] = wma; redm[ch * 64 + rb] = wmb; }
        __syncthreads();
        float Ma = fmaxf(wma, redm[(ch ^ 1) * 64 + ra]);
        float Mb = fmaxf(wmb, redm[(ch ^ 1) * 64 + rb]);
        float ex[4][4];
        float sa = 0.f, sb = 0.f;
#pragma unroll
        for (int j = 0; j < 4; j++) {
            ex[j][0] = __expf(acc[p][j][0] - Ma);
            ex[j][1] = __expf(acc[p][j][1] - Ma);
            ex[j][2] = __expf(acc[p][j][2] - Mb);
            ex[j][3] = __expf(acc[p][j][3] - Mb);
            sa += ex[j][0] + ex[j][1];
            sb += ex[j][2] + ex[j][3];
        }
        sa += __shfl_xor_sync(0xffffffffu, sa, 1);
        sa += __shfl_xor_sync(0xffffffffu, sa, 2);
        sb += __shfl_xor_sync(0xffffffffu, sb, 1);
        sb += __shfl_xor_sync(0xffffffffu, sb, 2);
        if (tig == 0) { reds[ch * 64 + ra] = sa; reds[ch * 64 + rb] = sb; }
        __syncthreads();
        const float ia = 1.f / (sa + reds[(ch ^ 1) * 64 + ra]);
        const float ib = 1.f / (sb + reds[(ch ^ 1) * 64 + rb]);
        float* cdst = ((p == 0) ? g_cq : g_ck) + (size_t)(b * NH_ + hh) * L_ * D_;
#pragma unroll
        for (int j = 0; j < 4; j++) {
            *reinterpret_cast<float2*>(&cdst[(size_t)(l0 + ra) * D_ + n0c + 8*j + 2*tig]) =
                make_float2(ex[j][0] * ia, ex[j][1] * ia);
            *reinterpret_cast<float2*>(&cdst[(size_t)(l0 + rb) * D_ + n0c + 8*j + 2*tig]) =
                make_float2(ex[j][2] * ib, ex[j][3] * ib);
        }
        __syncthreads();
    }
}

// ---------------- K3: scores + top-6, one warp per query row ----------------
__global__ void __launch_bounds__(256) k_topk() {
    __shared__ float kb[64][65];
    __shared__ float qb8[8][64];
    const int bh = blockIdx.x, rg = blockIdx.y;
    const int tid = threadIdx.x, w = tid >> 5, lane = tid & 31;
    for (int i = tid; i < 4096; i += 256) kb[i >> 6][i & 63] = g_kb[(size_t)bh * 4096 + i];
    for (int i = tid; i < 512; i += 256) qb8[i >> 6][i & 63] = g_qb[(size_t)bh * 4096 + rg * 512 + i];
    __syncthreads();
    float s0 = 0.f, s1 = 0.f;
#pragma unroll 8
    for (int d = 0; d < 64; d++) {
        float qv = qb8[w][d];
        s0 += qv * kb[lane][d];
        s1 += qv * kb[lane + 32][d];
    }
    const int r = rg * 8 + w;
    int* lp = g_lut + ((size_t)bh * NB_ + r) * T_;
#pragma unroll
    for (int t = 0; t < T_; t++) {
        float v; int idx;
        if (s0 >= s1) { v = s0; idx = lane; } else { v = s1; idx = lane + 32; }
#pragma unroll
        for (int o = 16; o; o >>= 1) {
            float ov = __shfl_xor_sync(0xffffffffu, v, o);
            int   oi = __shfl_xor_sync(0xffffffffu, idx, o);
            if (ov > v || (ov == v && oi < idx)) { v = ov; idx = oi; }
        }
        if (lane == 0) lp[t] = idx;
        if (idx == lane) s0 = -3.4e38f;
        else if (idx == lane + 32) s1 = -3.4e38f;
    }
}

// ---------------- K4: sparse attention; q/k/v pre-rounded -> raw copy staging ----------------
#define QS_OFF 0
#define KS_OFF (64*68)
#define VS_OFF (2*64*68)
#define RM_OFF (2*64*68 + 64*72)
#define RS_OFF (RM_OFF + 2*64)
#define SATTN_SMEM_FLOATS (RS_OFF + 2*64)

__global__ void __launch_bounds__(256, 3) k_sattn() {
    extern __shared__ float sm[];
    float* Qs = sm + QS_OFF;
    float* Ks = sm + KS_OFF;
    float* Vs = sm + VS_OFF;
    float* redm = sm + RM_OFF;
    float* reds = sm + RS_OFF;
    __shared__ int luts[8];
    const int n = blockIdx.x, bh = blockIdx.y;
    const int tid = threadIdx.x;
    const int w = tid >> 5, lane = tid & 31;
    const int gid = lane >> 2, tig = lane & 3;
    const int m0 = (w >> 1) * 16;
    const int ch = w & 1;
    const int n0c = ch * 32;

    const float* qp = g_q + ((size_t)bh * L_ + n * 64) * D_;
    for (int i = tid * 4; i < 4096; i += 1024) {
        int r = i >> 6, d = i & 63;
        *reinterpret_cast<float4*>(&Qs[r * 68 + d]) = *reinterpret_cast<const float4*>(&qp[i]);
    }
    if (tid < T_) luts[tid] = g_lut[((size_t)bh * NB_ + n) * T_ + tid];
    __syncthreads();

    float oacc[4][4] = {};
    float m_a = -1e30f, m_b = -1e30f, l_a = 0.f, l_b = 0.f;
    const int ra = m0 + gid, rb = m0 + gid + 8;

    for (int t = 0; t < T_; t++) {
        const float* kp = g_k + ((size_t)bh * L_ + luts[t] * 64) * D_;
        const float* vp = g_v + ((size_t)bh * L_ + luts[t] * 64) * D_;
        for (int i = tid * 4; i < 4096; i += 1024) {
            int r = i >> 6, d = i & 63;
            *reinterpret_cast<float4*>(&Ks[r * 68 + d]) = *reinterpret_cast<const float4*>(&kp[i]);
            *reinterpret_cast<float4*>(&Vs[r * 72 + d]) = *reinterpret_cast<const float4*>(&vp[i]);
        }
        __syncthreads();

        float sacc[4][4] = {};
#pragma unroll
        for (int kk = 0; kk < 64; kk += 8) {
            unsigned a[4];
            a[0] = __float_as_uint(Qs[ra * 68 + kk + tig]);
            a[1] = __float_as_uint(Qs[rb * 68 + kk + tig]);
            a[2] = __float_as_uint(Qs[ra * 68 + kk + tig + 4]);
            a[3] = __float_as_uint(Qs[rb * 68 + kk + tig + 4]);
#pragma unroll
            for (int j = 0; j < 4; j++) {
                unsigned b[2];
                b[0] = __float_as_uint(Ks[(n0c + 8 * j + gid) * 68 + kk + tig]);
                b[1] = __float_as_uint(Ks[(n0c + 8 * j + gid) * 68 + kk + tig + 4]);
                mma8(sacc[j], a, b);
            }
        }
#pragma unroll
        for (int j = 0; j < 4; j++)
#pragma unroll
            for (int r = 0; r < 4; r++) sacc[j][r] *= 0.125f;

        float wma = fmaxf(fmaxf(sacc[0][0], sacc[0][1]), fmaxf(sacc[1][0], sacc[1][1]));
        wma = fmaxf(wma, fmaxf(fmaxf(sacc[2][0], sacc[2][1]), fmaxf(sacc[3][0], sacc[3][1])));
        float wmb = fmaxf(fmaxf(sacc[0][2], sacc[0][3]), fmaxf(sacc[1][2], sacc[1][3]));
        wmb = fmaxf(wmb, fmaxf(fmaxf(sacc[2][2], sacc[2][3]), fmaxf(sacc[3][2], sacc[3][3])));
        wma = fmaxf(wma, __shfl_xor_sync(0xffffffffu, wma, 1));
        wma = fmaxf(wma, __shfl_xor_sync(0xffffffffu, wma, 2));
        wmb = fmaxf(wmb, __shfl_xor_sync(0xffffffffu, wmb, 1));
        wmb = fmaxf(wmb, __shfl_xor_sync(0xffffffffu, wmb, 2));
        if (tig == 0) { redm[ch * 64 + ra] = wma; redm[ch * 64 + rb] = wmb; }
        __syncthreads();
        float Ma = fmaxf(wma, redm[(ch ^ 1) * 64 + ra]);
        float Mb = fmaxf(wmb, redm[(ch ^ 1) * 64 + rb]);
        float nma = fmaxf(m_a, Ma), nmb = fmaxf(m_b, Mb);
        float ca = __expf(m_a - nma), cb = __expf(m_b - nmb);
        m_a = nma; m_b = nmb;

        float sa = 0.f, sb = 0.f;
#pragma unroll
        for (int j = 0; j < 4; j++) {
            sacc[j][0] = __expf(sacc[j][0] - nma);
            sacc[j][1] = __expf(sacc[j][1] - nma);
            sacc[j][2] = __expf(sacc[j][2] - nmb);
            sacc[j][3] = __expf(sacc[j][3] - nmb);
            sa += sacc[j][0] + sacc[j][1];
            sb += sacc[j][2] + sacc[j][3];
        }
        sa += __shfl_xor_sync(0xffffffffu, sa, 1);
        sa += __shfl_xor_sync(0xffffffffu, sa, 2);
        sb += __shfl_xor_sync(0xffffffffu, sb, 1);
        sb += __shfl_xor_sync(0xffffffffu, sb, 2);

#pragma unroll
        for (int j = 0; j < 4; j++) {
            *reinterpret_cast<float2*>(&Ks[ra * 68 + n0c + 8 * j + 2 * tig]) =
                make_float2(tfb(sacc[j][0]), tfb(sacc[j][1]));
            *reinterpret_cast<float2*>(&Ks[rb * 68 + n0c + 8 * j + 2 * tig]) =
                make_float2(tfb(sacc[j][2]), tfb(sacc[j][3]));
        }
        if (tig == 0) { reds[ch * 64 + ra] = sa; reds[ch * 64 + rb] = sb; }
        __syncthreads();
        l_a = l_a * ca + sa + reds[(ch ^ 1) * 64 + ra];
        l_b = l_b * cb + sb + reds[(ch ^ 1) * 64 + rb];
#pragma unroll
        for (int j = 0; j < 4; j++) {
            oacc[j][0] *= ca; oacc[j][1] *= ca;
            oacc[j][2] *= cb; oacc[j][3] *= cb;
        }

#pragma unroll
        for (int kk = 0; kk < 64; kk += 8) {
            unsigned a[4];
            a[0] = __float_as_uint(Ks[ra * 68 + kk + tig]);
            a[1] = __float_as_uint(Ks[rb * 68 + kk + tig]);
            a[2] = __float_as_uint(Ks[ra * 68 + kk + tig + 4]);
            a[3] = __float_as_uint(Ks[rb * 68 + kk + tig + 4]);
#pragma unroll
            for (int j = 0; j < 4; j++) {
                unsigned b[2];
                b[0] = __float_as_uint(Vs[(kk + tig) * 72 + n0c + 8 * j + gid]);
                b[1] = __float_as_uint(Vs[(kk + tig + 4) * 72 + n0c + 8 * j + gid]);
                mma8(oacc[j], a, b);
            }
        }
        __syncthreads();
    }

    const float ia = 1.f / l_a, ib = 1.f / l_b;
    float* op = g_obuf + ((size_t)bh * L_ + n * 64) * D_;
#pragma unroll
    for (int j = 0; j < 4; j++) {
        *reinterpret_cast<float2*>(&op[ra * 64 + n0c + 8 * j + 2 * tig]) =
            make_float2(oacc[j][0] * ia, oacc[j][1] * ia);
        *reinterpret_cast<float2*>(&op[rb * 64 + n0c + 8 * j + 2 * tig]) =
            make_float2(oacc[j][2] * ib, oacc[j][3] * ib);
    }
}

// ---------------- K5b: kvb = cK^T @ V; v pre-rounded -> raw copy staging ----------------
__global__ void __launch_bounds__(256) k_kvb() {
    __shared__ float CKt[64*68];
    __shared__ float Vsb[64*72];
    const int m = blockIdx.x, bh = blockIdx.y;
    const int tid = threadIdx.x, w8 = tid >> 5, lane = tid & 31;
    const int gid = lane >> 2, tig = lane & 3;
    const int m0 = (w8 >> 1) * 16, ch = w8 & 1, n0c = ch * 32;
    const int lr = tid & 15, ld4 = (tid >> 4) * 4;
    const float* ckp = g_ck + ((size_t)bh * L_ + m * 64) * D_;
    const float* vp  = g_v  + ((size_t)bh * L_ + m * 64) * D_;
#pragma unroll
    for (int rep = 0; rep < 4; rep++) {
        int r = lr + rep * 16;
        float4 kv = *reinterpret_cast<const float4*>(&ckp[r * 64 + ld4]);
        CKt[(ld4 + 0) * 68 + r] = kv.x;
        CKt[(ld4 + 1) * 68 + r] = kv.y;
        CKt[(ld4 + 2) * 68 + r] = kv.z;
        CKt[(ld4 + 3) * 68 + r] = kv.w;
    }
    for (int i = tid * 4; i < 4096; i += 1024) {
        int r = i >> 6, d = i & 63;
        *reinterpret_cast<float4*>(&Vsb[r * 72 + d]) = *reinterpret_cast<const float4*>(&vp[i]);
    }
    __syncthreads();
    const int ra = m0 + gid, rb = ra + 8;
    float acc[4][4] = {};
#pragma unroll
    for (int kk = 0; kk < 64; kk += 8) {
        unsigned a[4];
        a[0] = f2tf(CKt[ra * 68 + kk + tig]);
        a[1] = f2tf(CKt[rb * 68 + kk + tig]);
        a[2] = f2tf(CKt[ra * 68 + kk + tig + 4]);
        a[3] = f2tf(CKt[rb * 68 + kk + tig + 4]);
#pragma unroll
        for (int j = 0; j < 4; j++) {
            unsigned b[2];
            b[0] = __float_as_uint(Vsb[(kk + tig) * 72 + n0c + 8 * j + gid]);
            b[1] = __float_as_uint(Vsb[(kk + tig + 4) * 72 + n0c + 8 * j + gid]);
            mma8(acc[j], a, b);
        }
    }
    float* dst = g_kvb + (size_t)(bh * NB_ + m) * D_ * D_;
#pragma unroll
    for (int j = 0; j < 4; j++) {
        *reinterpret_cast<float2*>(&dst[ra * 64 + n0c + 8 * j + 2 * tig]) =
            make_float2(acc[j][0], acc[j][1]);
        *reinterpret_cast<float2*>(&dst[rb * 64 + n0c + 8 * j + 2 * tig]) =
            make_float2(acc[j][2], acc[j][3]);
    }
    if (tid < 64) {
        float s = 0.f;
#pragma unroll 8
        for (int k = 0; k < 64; k++) s += CKt[tid * 68 + k];
        g_ksum[(size_t)(bh * NB_ + m) * D_ + tid] = s;
    }
}

// ---------------- K5c: totals, parallel grid ----------------
__global__ void k_totals() {
    const int bh = blockIdx.x, ch = blockIdx.y, tid = threadIdx.x;
    if (ch < 8) {
#pragma unroll
        for (int rep = 0; rep < 2; rep++) {
            const int i = ch * 512 + rep * 256 + tid;
            const float* p = g_kvb + (size_t)bh * NB_ * 4096 + i;
            float s = 0.f;
#pragma unroll 8
            for (int m = 0; m < 64; m++) s += p[(size_t)m * 4096];
            g_kvt[(size_t)bh * 4096 + i] = s;
        }
    } else if (tid < 64) {
        const float* p = g_ksum + (size_t)bh * NB_ * 64 + tid;
        float s = 0.f;
#pragma unroll 8
        for (int m = 0; m < 64; m++) s += p[m * 64];
        g_kst[bh * 64 + tid] = s;
    }
}

// ---------------- K5d: linear path via tf32 MMA; writes o_l + bias ----------------
__global__ void __launch_bounds__(256) k_lin(const float* __restrict__ plw, const float* __restrict__ plb) {
    __shared__ float KVQ[64*72];
    __shared__ float CQb[64*68];
    __shared__ float ksq[64], den_s[64], plbs[64];
    __shared__ int luts[8];
    const int n = blockIdx.x, bh = blockIdx.y;
    const int tid = threadIdx.x, w8 = tid >> 5, lane = tid & 31;
    const int gid = lane >> 2, tig = lane & 3;
    const int m0 = (w8 >> 1) * 16, ch = w8 & 1, n0c = ch * 32;
    const int ra = m0 + gid, rb = ra + 8;
    if (tid < T_) luts[tid] = g_lut[((size_t)bh * NB_ + n) * T_ + tid];
    if (tid >= 64 && tid < 128) plbs[tid - 64] = plb[tid - 64];
    __syncthreads();
    for (int i = tid; i < 4096; i += 256) {
        float s = g_kvt[(size_t)bh * 4096 + i];
#pragma unroll
        for (int t = 0; t < T_; t++) s -= g_kvb[(size_t)(bh * NB_ + luts[t]) * 4096 + i];
        KVQ[(i >> 6) * 72 + (i & 63)] = s;
    }
    if (tid < 64) {
        float s = g_kst[bh * 64 + tid];
#pragma unroll
        for (int t = 0; t < T_; t++) s -= g_ksum[(size_t)(bh * NB_ + luts[t]) * 64 + tid];
        ksq[tid] = s;
    }
    const float* cqp = g_cq + ((size_t)bh * L_ + n * 64) * D_;
    for (int i = tid * 4; i < 4096; i += 1024) {
        int r = i >> 6, d = i & 63;
        *reinterpret_cast<float4*>(&CQb[r * 68 + d]) = *reinterpret_cast<const float4*>(&cqp[i]);
    }
    __syncthreads();
    if (tid < 64) {
        float s = 0.f;
#pragma unroll 8
        for (int d = 0; d < 64; d++) s += CQb[tid * 68 + d] * ksq[d];
        den_s[tid] = s;
    }
    float acc[4][4] = {};
#pragma unroll
    for (int kk = 0; kk < 64; kk += 8) {
        unsigned a[4];
        a[0] = f2tf(CQb[ra * 68 + kk + tig]);
        a[1] = f2tf(CQb[rb * 68 + kk + tig]);
        a[2] = f2tf(CQb[ra * 68 + kk + tig + 4]);
        a[3] = f2tf(CQb[rb * 68 + kk + tig + 4]);
#pragma unroll
        for (int j = 0; j < 4; j++) {
            unsigned b[2];
            b[0] = f2tf(KVQ[(kk + tig) * 72 + n0c + 8 * j + gid]);
            b[1] = f2tf(KVQ[(kk + tig + 4) * 72 + n0c + 8 * j + gid]);
            mma8(acc[j], a, b);
        }
    }
    __syncthreads();
    const float ia = 1.f / (den_s[ra] + 1e-6f);
    const float ib = 1.f / (den_s[rb] + 1e-6f);
#pragma unroll
    for (int j = 0; j < 4; j++) {
        *reinterpret_cast<float2*>(&CQb[ra * 68 + n0c + 8 * j + 2 * tig]) =
            make_float2(acc[j][0] * ia, acc[j][1] * ia);
        *reinterpret_cast<float2*>(&CQb[rb * 68 + n0c + 8 * j + 2 * tig]) =
            make_float2(acc[j][2] * ib, acc[j][3] * ib);
    }
    for (int i = tid * 4; i < 4096; i += 1024) {
        int e2 = i >> 6, e = i & 63;
        float4 v = *reinterpret_cast<const float4*>(&plw[i]);
        *reinterpret_cast<float4*>(&KVQ[e2 * 68 + e]) = v;
    }
    __syncthreads();
    float acc2[4][4] = {};
#pragma unroll
    for (int kk = 0; kk < 64; kk += 8) {
        unsigned a[4];
        a[0] = f2tf(CQb[ra * 68 + kk + tig]);
        a[1] = f2tf(CQb[rb * 68 + kk + tig]);
        a[2] = f2tf(CQb[ra * 68 + kk + tig + 4]);
        a[3] = f2tf(CQb[rb * 68 + kk + tig + 4]);
#pragma unroll
        for (int j = 0; j < 4; j++) {
            unsigned b[2];
            b[0] = f2tf(KVQ[(n0c + 8 * j + gid) * 68 + kk + tig]);
            b[1] = f2tf(KVQ[(n0c + 8 * j + gid) * 68 + kk + tig + 4]);
            mma8(acc2[j], a, b);
        }
    }
    float* op = g_olin + ((size_t)bh * L_ + n * 64) * D_;
#pragma unroll
    for (int j = 0; j < 4; j++) {
        const int col = n0c + 8 * j + 2 * tig;
        *reinterpret_cast<float2*>(&op[ra * 64 + col]) =
            make_float2(acc2[j][0] + plbs[col], acc2[j][1] + plbs[col + 1]);
        *reinterpret_cast<float2*>(&op[rb * 64 + col]) =
            make_float2(acc2[j][2] + plbs[col], acc2[j][3] + plbs[col + 1]);
    }
}

// ---------------- K6: out_proj via PLAIN tf32 MMA; B = tfb(obuf + olin) at STS ----------------
__global__ void __launch_bounds__(256) k_outproj_tc(const float* __restrict__ w2, float* __restrict__ out) {
    __shared__ float Ah[64*GSTR], Bh[64*GSTR];
    const int b = blockIdx.z, l0 = blockIdx.x * 64, co0 = blockIdx.y * 64;
    const int tid = threadIdx.x, w8 = tid >> 5, lane = tid & 31;
    const int gid = lane >> 2, tig = lane & 3;
    const int m0 = (w8 >> 1) * 16, ch = w8 & 1, n0c = ch * 32;
    const int lrow = tid >> 3, cq = (tid & 7) * 4;
    const int ra = m0 + gid, rb = ra + 8;
    float acc[4][4] = {};

    for (int c0 = 0; c0 < C_; c0 += 32) {
        const int hh = c0 >> 6, d0 = c0 & 63;
        const size_t bbase = ((size_t)(b * NH_ + hh) * L_ + l0) * D_ + d0;
#pragma unroll
        for (int r = lrow; r < 64; r += 32) {
            float4 wv = *reinterpret_cast<const float4*>(&w2[(size_t)(co0 + r) * C_ + c0 + cq]);
            Ah[r*GSTR+cq+0] = tfb(wv.x); Ah[r*GSTR+cq+1] = tfb(wv.y);
            Ah[r*GSTR+cq+2] = tfb(wv.z); Ah[r*GSTR+cq+3] = tfb(wv.w);
            float4 v = *reinterpret_cast<const float4*>(&g_obuf[bbase + (size_t)r * D_ + cq]);
            float4 u = *reinterpret_cast<const float4*>(&g_olin[bbase + (size_t)r * D_ + cq]);
            Bh[r*GSTR+cq+0] = tfb(v.x + u.x); Bh[r*GSTR+cq+1] = tfb(v.y + u.y);
            Bh[r*GSTR+cq+2] = tfb(v.z + u.z); Bh[r*GSTR+cq+3] = tfb(v.w + u.w);
        }
        __syncthreads();
#pragma unroll
        for (int kk = 0; kk < 32; kk += 8) {
            unsigned ah[4];
            ah[0] = __float_as_uint(Ah[ra*GSTR + kk + tig]);
            ah[1] = __float_as_uint(Ah[rb*GSTR + kk + tig]);
            ah[2] = __float_as_uint(Ah[ra*GSTR + kk + tig + 4]);
            ah[3] = __float_as_uint(Ah[rb*GSTR + kk + tig + 4]);
#pragma unroll
            for (int j = 0; j < 4; j++) {
                const int br = (n0c + 8*j + gid) * GSTR + kk + tig;
                unsigned bh2[2];
                bh2[0] = __float_as_uint(Bh[br]); bh2[1] = __float_as_uint(Bh[br + 4]);
                mma8(acc[j], ah, bh2);
            }
        }
        __syncthreads();
    }
    float* ob = out + (size_t)b * C_ * L_;
#pragma unroll
    for (int j = 0; j < 4; j++) {
        *reinterpret_cast<float2*>(&ob[(size_t)(co0 + ra) * L_ + l0 + n0c + 8*j + 2*tig]) =
            make_float2(acc[j][0], acc[j][1]);
        *reinterpret_cast<float2*>(&ob[(size_t)(co0 + rb) * L_ + l0 + n0c + 8*j + 2*tig]) =
            make_float2(acc[j][2], acc[j][3]);
    }
}

// ---------------- launch: two-branch stream fork inside graph capture ----------------
extern "C" void kernel_launch(void* const* d_in, const int* in_sizes, int n_in,
                              void* d_out, int out_size) {
    const float* x     = (const float*)d_in[0];
    const float* qkv_w = (const float*)d_in[1];
    const float* out_w = (const float*)d_in[2];
    const float* plw   = (const float*)d_in[3];
    const float* plb   = (const float*)d_in[4];
    float* out = (float*)d_out;

    static cudaStream_t s2 = nullptr;
    static cudaEvent_t evFork = nullptr, evT = nullptr, evQ = nullptr, evJoin = nullptr;
    if (s2 == nullptr) {
        cudaStreamCreateWithFlags(&s2, cudaStreamNonBlocking);
        cudaEventCreateWithFlags(&evFork, cudaEventDisableTiming);
        cudaEventCreateWithFlags(&evT,    cudaEventDisableTiming);
        cudaEventCreateWithFlags(&evQ,    cudaEventDisableTiming);
        cudaEventCreateWithFlags(&evJoin, cudaEventDisableTiming);
        cudaFuncSetAttribute(k_sattn, cudaFuncAttributeMaxDynamicSharedMemorySize,
                             SATTN_SMEM_FLOATS * (int)sizeof(float));
        cudaFuncSetAttribute(k_qkv_tc, cudaFuncAttributeMaxDynamicSharedMemorySize,
                             QKV_SMEM_FLOATS * (int)sizeof(float));
    }
    const int sattn_smem = SATTN_SMEM_FLOATS * (int)sizeof(float); // 54272 B
    const int qkv_smem   = QKV_SMEM_FLOATS * (int)sizeof(float);   // 37888 B

    cudaEventRecord(evFork, 0);
    cudaStreamWaitEvent(s2, evFork, 0);

    // branch B: exact block-mean path -> topk (independent of qkv)
    k_xbar<<<dim3(B_, NB_), 256, 0, s2>>>(x);
    k_qbkb<<<dim3(8, 1, B_), 256, 0, s2>>>(qkv_w);
    k_topk<<<dim3(BH_, 8), 256, 0, s2>>>();
    cudaEventRecord(evT, s2);

    // branch A: x transpose -> fused qkv (plain tf32, pre-rounded outputs)
    k_xT<<<dim3(L_ / 32, C_ / 32, B_), dim3(32, 8)>>>(x);
    k_qkv_tc<<<dim3(L_ / 64, NH_, B_), 256, qkv_smem>>>(qkv_w);
    cudaEventRecord(evQ, 0);

    // branch B: kvb + totals + lin (o_l path), overlapped with sattn
    cudaStreamWaitEvent(s2, evQ, 0);
    k_kvb   <<<dim3(NB_, BH_), 256, 0, s2>>>();
    k_totals<<<dim3(BH_, 9), 256, 0, s2>>>();
    k_lin   <<<dim3(NB_, BH_), 256, 0, s2>>>(plw, plb);
    cudaEventRecord(evJoin, s2);

    // branch A: sattn (needs lut from branch B + q/k/v from program order)
    cudaStreamWaitEvent(0, evT, 0);
    k_sattn<<<dim3(NB_, BH_), 256, sattn_smem>>>();

    // join, then out_proj (plain tf32)
    cudaStreamWaitEvent(0, evJoin, 0);
    k_outproj_tc<<<dim3(L_ / 64, C_ / 64, B_), 256>>>(out_w, out);
}

// round 17
// speedup vs baseline: 1.2915x; 1.0289x over previous
#include <cuda_runtime.h>

#define B_ 8
#define C_ 256
#define L_ 4096
#define NH_ 4
#define D_ 64
#define NB_ 64   // number of query/key blocks (L/64)
#define T_ 6     // top-k blocks
#define BH_ 32   // B*NH

// ---------------- scratch (device globals; no allocs) ----------------
__device__ float g_xt[(size_t)B_*C_*L_];   // x transposed: [b][l][c] (fp32)
__device__ float g_xbar[B_*NB_*C_];        // per-block mean of x: [b][n][c]
__device__ float g_q [BH_*L_*D_];          // PRE-ROUNDED tf32, PRE-SCALED by 0.125
__device__ float g_k [BH_*L_*D_];          // PRE-ROUNDED tf32 values
__device__ float g_v [BH_*L_*D_];          // PRE-ROUNDED tf32 values
__device__ float g_cq[BH_*L_*D_];
__device__ float g_ck[BH_*L_*D_];
__device__ float g_qb[BH_*NB_*D_];
__device__ float g_kb[BH_*NB_*D_];
__device__ int   g_lut[BH_*NB_*T_];
__device__ float g_kvb[(size_t)BH_*NB_*D_*D_];
__device__ float g_ksum[BH_*NB_*D_];
__device__ float g_kvt[BH_*D_*D_];
__device__ float g_kst[BH_*D_];
__device__ float g_obuf[BH_*L_*D_];   // o_s from sattn (fp32)
__device__ float g_olin[BH_*L_*D_];   // o_l + bias from k_lin (fp32)

// ---------------- tf32 mma helpers ----------------
__device__ __forceinline__ unsigned f2tf(float f) {
    unsigned u; asm("cvt.rna.tf32.f32 %0, %1;" : "=r"(u) : "f"(f)); return u;
}
__device__ __forceinline__ void mma8(float d[4], const unsigned a[4], const unsigned b[2]) {
    asm("mma.sync.aligned.m16n8k8.row.col.f32.tf32.tf32.f32 "
        "{%0,%1,%2,%3}, {%4,%5,%6,%7}, {%8,%9}, {%0,%1,%2,%3};"
        : "+f"(d[0]), "+f"(d[1]), "+f"(d[2]), "+f"(d[3])
        : "r"(a[0]), "r"(a[1]), "r"(a[2]), "r"(a[3]), "r"(b[0]), "r"(b[1]));
}
__device__ __forceinline__ float tfb(float x) {   // tf32 bits stored as float
    return __uint_as_float(f2tf(x));
}

// ---------------- K0a: transpose x -> g_xt[b][l][c] (fp32) ----------------
__global__ void k_xT(const float* __restrict__ x) {
    __shared__ float t[32][33];
    const int b = blockIdx.z, l0 = blockIdx.x * 32, c0 = blockIdx.y * 32;
    const int tx = threadIdx.x, ty = threadIdx.y;
    const float* xb = x + (size_t)b * C_ * L_;
#pragma unroll
    for (int i = 0; i < 32; i += 8)
        t[ty + i][tx] = xb[(size_t)(c0 + ty + i) * L_ + l0 + tx];
    __syncthreads();
    float* dst = g_xt + (size_t)b * L_ * C_;
#pragma unroll
    for (int i = 0; i < 32; i += 8)
        dst[(size_t)(l0 + ty + i) * C_ + c0 + tx] = t[tx][ty + i];
}

// ---------------- K0b: per-block mean of x (exact fp32) ----------------
__global__ void k_xbar(const float* __restrict__ x) {
    const int b = blockIdx.x, n = blockIdx.y, c = threadIdx.x;
    const float* p = x + (size_t)b * C_ * L_ + (size_t)c * L_ + n * 64;
    float s = 0.f;
#pragma unroll 8
    for (int l = 0; l < 64; l++) s += p[l];
    g_xbar[(b * NB_ + n) * C_ + c] = s * (1.f / 64.f);
}

// ---------------- K0c: qb/kb = W_{q,k} @ xbar (exact fp32, tiny GEMM) ----------------
__global__ void k_qbkb(const float* __restrict__ qkv_w) {
    __shared__ float As[16][65];
    __shared__ float Ws[16][65];
    const int b = blockIdx.z, o0 = blockIdx.x * 64;
    const int tid = threadIdx.x, ty = tid >> 4, tx = tid & 15;
    float acc[4][4] = {};
    const float* xb = g_xbar + (size_t)b * NB_ * C_;
    for (int c0 = 0; c0 < C_; c0 += 16) {
        {
            int i = tid * 4, r = i >> 4, c = i & 15;
            float4 v = *reinterpret_cast<const float4*>(&xb[(size_t)r * C_ + c0 + c]);
            As[c + 0][r] = v.x; As[c + 1][r] = v.y; As[c + 2][r] = v.z; As[c + 3][r] = v.w;
        }
        {
            int i = tid * 4, r = i >> 4, c = i & 15;
            float4 v = *reinterpret_cast<const float4*>(&qkv_w[(size_t)(o0 + r) * C_ + c0 + c]);
            Ws[c + 0][r] = v.x; Ws[c + 1][r] = v.y; Ws[c + 2][r] = v.z; Ws[c + 3][r] = v.w;
        }
        __syncthreads();
#pragma unroll
        for (int c = 0; c < 16; c++) {
            float a[4], bb[4];
#pragma unroll
            for (int i = 0; i < 4; i++) a[i] = As[c][ty * 4 + i];
#pragma unroll
            for (int j = 0; j < 4; j++) bb[j] = Ws[c][tx * 4 + j];
#pragma unroll
            for (int i = 0; i < 4; i++)
#pragma unroll
                for (int j = 0; j < 4; j++) acc[i][j] += a[i] * bb[j];
        }
        __syncthreads();
    }
#pragma unroll
    for (int i = 0; i < 4; i++) {
        const int n = ty * 4 + i;
#pragma unroll
        for (int j = 0; j < 4; j++) {
            const int o = o0 + tx * 4 + j;
            const int p = o >> 8, h = (o >> 6) & 3, d = o & 63;
            float* dst = p ? g_kb : g_qb;
            dst[((size_t)(b * NH_ + h) * NB_ + n) * D_ + d] = acc[i][j];
        }
    }
}

// ---------------- K1: fused qkv for ONE head, plain tf32; q pre-scaled by 0.125 ----------------
#define GSTR 36
#define QA 0
#define QB(p) (64*GSTR + (p)*64*GSTR)   // p = 0,1,2
#define QRED  (4*64*GSTR)
#define QREDS (QRED + 128)
#define QKV_SMEM_FLOATS (QREDS + 128)   // 9472 floats = 37888 B

__global__ void __launch_bounds__(256) k_qkv_tc(const float* __restrict__ w) {
    extern __shared__ float qs[];
    float* At = qs + QA;                // tf32 bits
    float* redm = qs + QRED;
    float* reds = qs + QREDS;
    const int b = blockIdx.z, l0 = blockIdx.x * 64, hh = blockIdx.y;
    const int tid = threadIdx.x, w8 = tid >> 5, lane = tid & 31;
    const int gid = lane >> 2, tig = lane & 3;
    const int m0 = (w8 >> 1) * 16, ch = w8 & 1, n0c = ch * 32;
    const int lrow = tid >> 3, cq = (tid & 7) * 4;
    const float* xt = g_xt + (size_t)b * L_ * C_;
    float acc[3][4][4] = {};
    const int ra = m0 + gid, rb = ra + 8;

    for (int c0 = 0; c0 < C_; c0 += 32) {
#pragma unroll
        for (int r = lrow; r < 64; r += 32) {
            float4 v = *reinterpret_cast<const float4*>(&xt[(size_t)(l0 + r) * C_ + c0 + cq]);
            At[r*GSTR+cq+0] = tfb(v.x); At[r*GSTR+cq+1] = tfb(v.y);
            At[r*GSTR+cq+2] = tfb(v.z); At[r*GSTR+cq+3] = tfb(v.w);
        }
#pragma unroll
        for (int p = 0; p < 3; p++) {
            const float* wp = w + (size_t)(p * 256 + hh * 64) * C_;
            float* Bp = qs + QB(p);
#pragma unroll
            for (int r = lrow; r < 64; r += 32) {
                float4 v = *reinterpret_cast<const float4*>(&wp[(size_t)r * C_ + c0 + cq]);
                Bp[r*GSTR+cq+0] = tfb(v.x); Bp[r*GSTR+cq+1] = tfb(v.y);
                Bp[r*GSTR+cq+2] = tfb(v.z); Bp[r*GSTR+cq+3] = tfb(v.w);
            }
        }
        __syncthreads();
#pragma unroll
        for (int kk = 0; kk < 32; kk += 8) {
            unsigned a[4];
            a[0] = __float_as_uint(At[ra*GSTR + kk + tig]);
            a[1] = __float_as_uint(At[rb*GSTR + kk + tig]);
            a[2] = __float_as_uint(At[ra*GSTR + kk + tig + 4]);
            a[3] = __float_as_uint(At[rb*GSTR + kk + tig + 4]);
#pragma unroll
            for (int p = 0; p < 3; p++) {
                const float* Bp = qs + QB(p);
#pragma unroll
                for (int j = 0; j < 4; j++) {
                    const int br = (n0c + 8*j + gid) * GSTR + kk + tig;
                    unsigned b2[2];
                    b2[0] = __float_as_uint(Bp[br]); b2[1] = __float_as_uint(Bp[br + 4]);
                    mma8(acc[p][j], a, b2);
                }
            }
        }
        __syncthreads();
    }

    // ---- store q (pre-rounded, pre-scaled by 0.125), k, v (pre-rounded) ----
    {
        float* dst = g_q + (size_t)(b * NH_ + hh) * L_ * D_;
#pragma unroll
        for (int j = 0; j < 4; j++) {
            *reinterpret_cast<float2*>(&dst[(size_t)(l0 + ra) * D_ + n0c + 8*j + 2*tig]) =
                make_float2(tfb(acc[0][j][0]) * 0.125f, tfb(acc[0][j][1]) * 0.125f);
            *reinterpret_cast<float2*>(&dst[(size_t)(l0 + rb) * D_ + n0c + 8*j + 2*tig]) =
                make_float2(tfb(acc[0][j][2]) * 0.125f, tfb(acc[0][j][3]) * 0.125f);
        }
    }
#pragma unroll
    for (int p = 1; p < 3; p++) {
        float* dst = ((p == 1) ? g_k : g_v) + (size_t)(b * NH_ + hh) * L_ * D_;
#pragma unroll
        for (int j = 0; j < 4; j++) {
            *reinterpret_cast<float2*>(&dst[(size_t)(l0 + ra) * D_ + n0c + 8*j + 2*tig]) =
                make_float2(tfb(acc[p][j][0]), tfb(acc[p][j][1]));
            *reinterpret_cast<float2*>(&dst[(size_t)(l0 + rb) * D_ + n0c + 8*j + 2*tig]) =
                make_float2(tfb(acc[p][j][2]), tfb(acc[p][j][3]));
        }
    }

    // ---- feature map softmax over d for q (p=0) and k (p=1); uses full-precision acc ----
#pragma unroll
    for (int p = 0; p < 2; p++) {
        float wma = fmaxf(fmaxf(acc[p][0][0], acc[p][0][1]), fmaxf(acc[p][1][0], acc[p][1][1]));
        wma = fmaxf(wma, fmaxf(fmaxf(acc[p][2][0], acc[p][2][1]), fmaxf(acc[p][3][0], acc[p][3][1])));
        float wmb = fmaxf(fmaxf(acc[p][0][2], acc[p][0][3]), fmaxf(acc[p][1][2], acc[p][1][3]));
        wmb = fmaxf(wmb, fmaxf(fmaxf(acc[p][2][2], acc[p][2][3]), fmaxf(acc[p][3][2], acc[p][3][3])));
        wma = fmaxf(wma, __shfl_xor_sync(0xffffffffu, wma, 1));
        wma = fmaxf(wma, __shfl_xor_sync(0xffffffffu, wma, 2));
        wmb = fmaxf(wmb, __shfl_xor_sync(0xffffffffu, wmb, 1));
        wmb = fmaxf(wmb, __shfl_xor_sync(0xffffffffu, wmb, 2));
        if (tig == 0) { redm[ch * 64 + ra] = wma; redm[ch * 64 + rb] = wmb; }
        __syncthreads();
        float Ma = fmaxf(wma, redm[(ch ^ 1) * 64 + ra]);
        float Mb = fmaxf(wmb, redm[(ch ^ 1) * 64 + rb]);
        float ex[4][4];
        float sa = 0.f, sb = 0.f;
#pragma unroll
        for (int j = 0; j < 4; j++) {
            ex[j][0] = __expf(acc[p][j][0] - Ma);
            ex[j][1] = __expf(acc[p][j][1] - Ma);
            ex[j][2] = __expf(acc[p][j][2] - Mb);
            ex[j][3] = __expf(acc[p][j][3] - Mb);
            sa += ex[j][0] + ex[j][1];
            sb += ex[j][2] + ex[j][3];
        }
        sa += __shfl_xor_sync(0xffffffffu, sa, 1);
        sa += __shfl_xor_sync(0xffffffffu, sa, 2);
        sb += __shfl_xor_sync(0xffffffffu, sb, 1);
        sb += __shfl_xor_sync(0xffffffffu, sb, 2);
        if (tig == 0) { reds[ch * 64 + ra] = sa; reds[ch * 64 + rb] = sb; }
        __syncthreads();
        const float ia = 1.f / (sa + reds[(ch ^ 1) * 64 + ra]);
        const float ib = 1.f / (sb + reds[(ch ^ 1) * 64 + rb]);
        float* cdst = ((p == 0) ? g_cq : g_ck) + (size_t)(b * NH_ + hh) * L_ * D_;
#pragma unroll
        for (int j = 0; j < 4; j++) {
            *reinterpret_cast<float2*>(&cdst[(size_t)(l0 + ra) * D_ + n0c + 8*j + 2*tig]) =
                make_float2(ex[j][0] * ia, ex[j][1] * ia);
            *reinterpret_cast<float2*>(&cdst[(size_t)(l0 + rb) * D_ + n0c + 8*j + 2*tig]) =
                make_float2(ex[j][2] * ib, ex[j][3] * ib);
        }
        __syncthreads();
    }
}

// ---------------- K3: scores + top-6, one warp per query row ----------------
__global__ void __launch_bounds__(256) k_topk() {
    __shared__ float kb[64][65];
    __shared__ float qb8[8][64];
    const int bh = blockIdx.x, rg = blockIdx.y;
    const int tid = threadIdx.x, w = tid >> 5, lane = tid & 31;
    for (int i = tid; i < 4096; i += 256) kb[i >> 6][i & 63] = g_kb[(size_t)bh * 4096 + i];
    for (int i = tid; i < 512; i += 256) qb8[i >> 6][i & 63] = g_qb[(size_t)bh * 4096 + rg * 512 + i];
    __syncthreads();
    float s0 = 0.f, s1 = 0.f;
#pragma unroll 8
    for (int d = 0; d < 64; d++) {
        float qv = qb8[w][d];
        s0 += qv * kb[lane][d];
        s1 += qv * kb[lane + 32][d];
    }
    const int r = rg * 8 + w;
    int* lp = g_lut + ((size_t)bh * NB_ + r) * T_;
#pragma unroll
    for (int t = 0; t < T_; t++) {
        float v; int idx;
        if (s0 >= s1) { v = s0; idx = lane; } else { v = s1; idx = lane + 32; }
#pragma unroll
        for (int o = 16; o; o >>= 1) {
            float ov = __shfl_xor_sync(0xffffffffu, v, o);
            int   oi = __shfl_xor_sync(0xffffffffu, idx, o);
            if (ov > v || (ov == v && oi < idx)) { v = ov; idx = oi; }
        }
        if (lane == 0) lp[t] = idx;
        if (idx == lane) s0 = -3.4e38f;
        else if (idx == lane + 32) s1 = -3.4e38f;
    }
}

// ---------------- K4: sparse attention; q pre-scaled -> no post-MMA scaling ----------------
#define QS_OFF 0
#define KS_OFF (64*68)
#define VS_OFF (2*64*68)
#define RM_OFF (2*64*68 + 64*72)
#define RS_OFF (RM_OFF + 2*64)
#define SATTN_SMEM_FLOATS (RS_OFF + 2*64)

__global__ void __launch_bounds__(256, 4) k_sattn() {
    extern __shared__ float sm[];
    float* Qs = sm + QS_OFF;
    float* Ks = sm + KS_OFF;
    float* Vs = sm + VS_OFF;
    float* redm = sm + RM_OFF;
    float* reds = sm + RS_OFF;
    __shared__ int luts[8];
    const int n = blockIdx.x, bh = blockIdx.y;
    const int tid = threadIdx.x;
    const int w = tid >> 5, lane = tid & 31;
    const int gid = lane >> 2, tig = lane & 3;
    const int m0 = (w >> 1) * 16;
    const int ch = w & 1;
    const int n0c = ch * 32;

    const float* qp = g_q + ((size_t)bh * L_ + n * 64) * D_;
    for (int i = tid * 4; i < 4096; i += 1024) {
        int r = i >> 6, d = i & 63;
        *reinterpret_cast<float4*>(&Qs[r * 68 + d]) = *reinterpret_cast<const float4*>(&qp[i]);
    }
    if (tid < T_) luts[tid] = g_lut[((size_t)bh * NB_ + n) * T_ + tid];
    __syncthreads();

    float oacc[4][4] = {};
    float m_a = -1e30f, m_b = -1e30f, l_a = 0.f, l_b = 0.f;
    const int ra = m0 + gid, rb = m0 + gid + 8;

    for (int t = 0; t < T_; t++) {
        const float* kp = g_k + ((size_t)bh * L_ + luts[t] * 64) * D_;
        const float* vp = g_v + ((size_t)bh * L_ + luts[t] * 64) * D_;
        for (int i = tid * 4; i < 4096; i += 1024) {
            int r = i >> 6, d = i & 63;
            *reinterpret_cast<float4*>(&Ks[r * 68 + d]) = *reinterpret_cast<const float4*>(&kp[i]);
            *reinterpret_cast<float4*>(&Vs[r * 72 + d]) = *reinterpret_cast<const float4*>(&vp[i]);
        }
        __syncthreads();

        float sacc[4][4] = {};
#pragma unroll
        for (int kk = 0; kk < 64; kk += 8) {
            unsigned a[4];
            a[0] = __float_as_uint(Qs[ra * 68 + kk + tig]);
            a[1] = __float_as_uint(Qs[rb * 68 + kk + tig]);
            a[2] = __float_as_uint(Qs[ra * 68 + kk + tig + 4]);
            a[3] = __float_as_uint(Qs[rb * 68 + kk + tig + 4]);
#pragma unroll
            for (int j = 0; j < 4; j++) {
                unsigned b[2];
                b[0] = __float_as_uint(Ks[(n0c + 8 * j + gid) * 68 + kk + tig]);
                b[1] = __float_as_uint(Ks[(n0c + 8 * j + gid) * 68 + kk + tig + 4]);
                mma8(sacc[j], a, b);
            }
        }

        float wma = fmaxf(fmaxf(sacc[0][0], sacc[0][1]), fmaxf(sacc[1][0], sacc[1][1]));
        wma = fmaxf(wma, fmaxf(fmaxf(sacc[2][0], sacc[2][1]), fmaxf(sacc[3][0], sacc[3][1])));
        float wmb = fmaxf(fmaxf(sacc[0][2], sacc[0][3]), fmaxf(sacc[1][2], sacc[1][3]));
        wmb = fmaxf(wmb, fmaxf(fmaxf(sacc[2][2], sacc[2][3]), fmaxf(sacc[3][2], sacc[3][3])));
        wma = fmaxf(wma, __shfl_xor_sync(0xffffffffu, wma, 1));
        wma = fmaxf(wma, __shfl_xor_sync(0xffffffffu, wma, 2));
        wmb = fmaxf(wmb, __shfl_xor_sync(0xffffffffu, wmb, 1));
        wmb = fmaxf(wmb, __shfl_xor_sync(0xffffffffu, wmb, 2));
        if (tig == 0) { redm[ch * 64 + ra] = wma; redm[ch * 64 + rb] = wmb; }
        __syncthreads();
        float Ma = fmaxf(wma, redm[(ch ^ 1) * 64 + ra]);
        float Mb = fmaxf(wmb, redm[(ch ^ 1) * 64 + rb]);
        float nma = fmaxf(m_a, Ma), nmb = fmaxf(m_b, Mb);
        float ca = __expf(m_a - nma), cb = __expf(m_b - nmb);
        m_a = nma; m_b = nmb;

        float sa = 0.f, sb = 0.f;
#pragma unroll
        for (int j = 0; j < 4; j++) {
            sacc[j][0] = __expf(sacc[j][0] - nma);
            sacc[j][1] = __expf(sacc[j][1] - nma);
            sacc[j][2] = __expf(sacc[j][2] - nmb);
            sacc[j][3] = __expf(sacc[j][3] - nmb);
            sa += sacc[j][0] + sacc[j][1];
            sb += sacc[j][2] + sacc[j][3];
        }
        sa += __shfl_xor_sync(0xffffffffu, sa, 1);
        sa += __shfl_xor_sync(0xffffffffu, sa, 2);
        sb += __shfl_xor_sync(0xffffffffu, sb, 1);
        sb += __shfl_xor_sync(0xffffffffu, sb, 2);

#pragma unroll
        for (int j = 0; j < 4; j++) {
            *reinterpret_cast<float2*>(&Ks[ra * 68 + n0c + 8 * j + 2 * tig]) =
                make_float2(tfb(sacc[j][0]), tfb(sacc[j][1]));
            *reinterpret_cast<float2*>(&Ks[rb * 68 + n0c + 8 * j + 2 * tig]) =
                make_float2(tfb(sacc[j][2]), tfb(sacc[j][3]));
        }
        if (tig == 0) { reds[ch * 64 + ra] = sa; reds[ch * 64 + rb] = sb; }
        __syncthreads();
        l_a = l_a * ca + sa + reds[(ch ^ 1) * 64 + ra];
        l_b = l_b * cb + sb + reds[(ch ^ 1) * 64 + rb];
#pragma unroll
        for (int j = 0; j < 4; j++) {
            oacc[j][0] *= ca; oacc[j][1] *= ca;
            oacc[j][2] *= cb; oacc[j][3] *= cb;
        }

#pragma unroll
        for (int kk = 0; kk < 64; kk += 8) {
            unsigned a[4];
            a[0] = __float_as_uint(Ks[ra * 68 + kk + tig]);
            a[1] = __float_as_uint(Ks[rb * 68 + kk + tig]);
            a[2] = __float_as_uint(Ks[ra * 68 + kk + tig + 4]);
            a[3] = __float_as_uint(Ks[rb * 68 + kk + tig + 4]);
#pragma unroll
            for (int j = 0; j < 4; j++) {
                unsigned b[2];
                b[0] = __float_as_uint(Vs[(kk + tig) * 72 + n0c + 8 * j + gid]);
                b[1] = __float_as_uint(Vs[(kk + tig + 4) * 72 + n0c + 8 * j + gid]);
                mma8(oacc[j], a, b);
            }
        }
        __syncthreads();
    }

    const float ia = 1.f / l_a, ib = 1.f / l_b;
    float* op = g_obuf + ((size_t)bh * L_ + n * 64) * D_;
#pragma unroll
    for (int j = 0; j < 4; j++) {
        *reinterpret_cast<float2*>(&op[ra * 64 + n0c + 8 * j + 2 * tig]) =
            make_float2(oacc[j][0] * ia, oacc[j][1] * ia);
        *reinterpret_cast<float2*>(&op[rb * 64 + n0c + 8 * j + 2 * tig]) =
            make_float2(oacc[j][2] * ib, oacc[j][3] * ib);
    }
}

// ---------------- K5b: kvb = cK^T @ V; v pre-rounded -> raw copy staging ----------------
__global__ void __launch_bounds__(256) k_kvb() {
    __shared__ float CKt[64*68];
    __shared__ float Vsb[64*72];
    const int m = blockIdx.x, bh = blockIdx.y;
    const int tid = threadIdx.x, w8 = tid >> 5, lane = tid & 31;
    const int gid = lane >> 2, tig = lane & 3;
    const int m0 = (w8 >> 1) * 16, ch = w8 & 1, n0c = ch * 32;
    const int lr = tid & 15, ld4 = (tid >> 4) * 4;
    const float* ckp = g_ck + ((size_t)bh * L_ + m * 64) * D_;
    const float* vp  = g_v  + ((size_t)bh * L_ + m * 64) * D_;
#pragma unroll
    for (int rep = 0; rep < 4; rep++) {
        int r = lr + rep * 16;
        float4 kv = *reinterpret_cast<const float4*>(&ckp[r * 64 + ld4]);
        CKt[(ld4 + 0) * 68 + r] = kv.x;
        CKt[(ld4 + 1) * 68 + r] = kv.y;
        CKt[(ld4 + 2) * 68 + r] = kv.z;
        CKt[(ld4 + 3) * 68 + r] = kv.w;
    }
    for (int i = tid * 4; i < 4096; i += 1024) {
        int r = i >> 6, d = i & 63;
        *reinterpret_cast<float4*>(&Vsb[r * 72 + d]) = *reinterpret_cast<const float4*>(&vp[i]);
    }
    __syncthreads();
    const int ra = m0 + gid, rb = ra + 8;
    float acc[4][4] = {};
#pragma unroll
    for (int kk = 0; kk < 64; kk += 8) {
        unsigned a[4];
        a[0] = f2tf(CKt[ra * 68 + kk + tig]);
        a[1] = f2tf(CKt[rb * 68 + kk + tig]);
        a[2] = f2tf(CKt[ra * 68 + kk + tig + 4]);
        a[3] = f2tf(CKt[rb * 68 + kk + tig + 4]);
#pragma unroll
        for (int j = 0; j < 4; j++) {
            unsigned b[2];
            b[0] = __float_as_uint(Vsb[(kk + tig) * 72 + n0c + 8 * j + gid]);
            b[1] = __float_as_uint(Vsb[(kk + tig + 4) * 72 + n0c + 8 * j + gid]);
            mma8(acc[j], a, b);
        }
    }
    float* dst = g_kvb + (size_t)(bh * NB_ + m) * D_ * D_;
#pragma unroll
    for (int j = 0; j < 4; j++) {
        *reinterpret_cast<float2*>(&dst[ra * 64 + n0c + 8 * j + 2 * tig]) =
            make_float2(acc[j][0], acc[j][1]);
        *reinterpret_cast<float2*>(&dst[rb * 64 + n0c + 8 * j + 2 * tig]) =
            make_float2(acc[j][2], acc[j][3]);
    }
    if (tid < 64) {
        float s = 0.f;
#pragma unroll 8
        for (int k = 0; k < 64; k++) s += CKt[tid * 68 + k];
        g_ksum[(size_t)(bh * NB_ + m) * D_ + tid] = s;
    }
}

// ---------------- K5c: totals, parallel grid ----------------
__global__ void k_totals() {
    const int bh = blockIdx.x, ch = blockIdx.y, tid = threadIdx.x;
    if (ch < 8) {
#pragma unroll
        for (int rep = 0; rep < 2; rep++) {
            const int i = ch * 512 + rep * 256 + tid;
            const float* p = g_kvb + (size_t)bh * NB_ * 4096 + i;
            float s = 0.f;
#pragma unroll 8
            for (int m = 0; m < 64; m++) s += p[(size_t)m * 4096];
            g_kvt[(size_t)bh * 4096 + i] = s;
        }
    } else if (tid < 64) {
        const float* p = g_ksum + (size_t)bh * NB_ * 64 + tid;
        float s = 0.f;
#pragma unroll 8
        for (int m = 0; m < 64; m++) s += p[m * 64];
        g_kst[bh * 64 + tid] = s;
    }
}

// ---------------- K5d: linear path via tf32 MMA; writes o_l + bias ----------------
__global__ void __launch_bounds__(256) k_lin(const float* __restrict__ plw, const float* __restrict__ plb) {
    __shared__ float KVQ[64*72];
    __shared__ float CQb[64*68];
    __shared__ float ksq[64], den_s[64], plbs[64];
    __shared__ int luts[8];
    const int n = blockIdx.x, bh = blockIdx.y;
    const int tid = threadIdx.x, w8 = tid >> 5, lane = tid & 31;
    const int gid = lane >> 2, tig = lane & 3;
    const int m0 = (w8 >> 1) * 16, ch = w8 & 1, n0c = ch * 32;
    const int ra = m0 + gid, rb = ra + 8;
    if (tid < T_) luts[tid] = g_lut[((size_t)bh * NB_ + n) * T_ + tid];
    if (tid >= 64 && tid < 128) plbs[tid - 64] = plb[tid - 64];
    __syncthreads();
    for (int i = tid; i < 4096; i += 256) {
        float s = g_kvt[(size_t)bh * 4096 + i];
#pragma unroll
        for (int t = 0; t < T_; t++) s -= g_kvb[(size_t)(bh * NB_ + luts[t]) * 4096 + i];
        KVQ[(i >> 6) * 72 + (i & 63)] = s;
    }
    if (tid < 64) {
        float s = g_kst[bh * 64 + tid];
#pragma unroll
        for (int t = 0; t < T_; t++) s -= g_ksum[(size_t)(bh * NB_ + luts[t]) * 64 + tid];
        ksq[tid] = s;
    }
    const float* cqp = g_cq + ((size_t)bh * L_ + n * 64) * D_;
    for (int i = tid * 4; i < 4096; i += 1024) {
        int r = i >> 6, d = i & 63;
        *reinterpret_cast<float4*>(&CQb[r * 68 + d]) = *reinterpret_cast<const float4*>(&cqp[i]);
    }
    __syncthreads();
    if (tid < 64) {
        float s = 0.f;
#pragma unroll 8
        for (int d = 0; d < 64; d++) s += CQb[tid * 68 + d] * ksq[d];
        den_s[tid] = s;
    }
    float acc[4][4] = {};
#pragma unroll
    for (int kk = 0; kk < 64; kk += 8) {
        unsigned a[4];
        a[0] = f2tf(CQb[ra * 68 + kk + tig]);
        a[1] = f2tf(CQb[rb * 68 + kk + tig]);
        a[2] = f2tf(CQb[ra * 68 + kk + tig + 4]);
        a[3] = f2tf(CQb[rb * 68 + kk + tig + 4]);
#pragma unroll
        for (int j = 0; j < 4; j++) {
            unsigned b[2];
            b[0] = f2tf(KVQ[(kk + tig) * 72 + n0c + 8 * j + gid]);
            b[1] = f2tf(KVQ[(kk + tig + 4) * 72 + n0c + 8 * j + gid]);
            mma8(acc[j], a, b);
        }
    }
    __syncthreads();
    const float ia = 1.f / (den_s[ra] + 1e-6f);
    const float ib = 1.f / (den_s[rb] + 1e-6f);
#pragma unroll
    for (int j = 0; j < 4; j++) {
        *reinterpret_cast<float2*>(&CQb[ra * 68 + n0c + 8 * j + 2 * tig]) =
            make_float2(acc[j][0] * ia, acc[j][1] * ia);
        *reinterpret_cast<float2*>(&CQb[rb * 68 + n0c + 8 * j + 2 * tig]) =
            make_float2(acc[j][2] * ib, acc[j][3] * ib);
    }
    for (int i = tid * 4; i < 4096; i += 1024) {
        int e2 = i >> 6, e = i & 63;
        float4 v = *reinterpret_cast<const float4*>(&plw[i]);
        *reinterpret_cast<float4*>(&KVQ[e2 * 68 + e]) = v;
    }
    __syncthreads();
    float acc2[4][4] = {};
#pragma unroll
    for (int kk = 0; kk < 64; kk += 8) {
        unsigned a[4];
        a[0] = f2tf(CQb[ra * 68 + kk + tig]);
        a[1] = f2tf(CQb[rb * 68 + kk + tig]);
        a[2] = f2tf(CQb[ra * 68 + kk + tig + 4]);
        a[3] = f2tf(CQb[rb * 68 + kk + tig + 4]);
#pragma unroll
        for (int j = 0; j < 4; j++) {
            unsigned b[2];
            b[0] = f2tf(KVQ[(n0c + 8 * j + gid) * 68 + kk + tig]);
            b[1] = f2tf(KVQ[(n0c + 8 * j + gid) * 68 + kk + tig + 4]);
            mma8(acc2[j], a, b);
        }
    }
    float* op = g_olin + ((size_t)bh * L_ + n * 64) * D_;
#pragma unroll
    for (int j = 0; j < 4; j++) {
        const int col = n0c + 8 * j + 2 * tig;
        *reinterpret_cast<float2*>(&op[ra * 64 + col]) =
            make_float2(acc2[j][0] + plbs[col], acc2[j][1] + plbs[col + 1]);
        *reinterpret_cast<float2*>(&op[rb * 64 + col]) =
            make_float2(acc2[j][2] + plbs[col], acc2[j][3] + plbs[col + 1]);
    }
}

// ---------------- K6: out_proj via PLAIN tf32 MMA; B = tfb(obuf + olin) at STS ----------------
__global__ void __launch_bounds__(256) k_outproj_tc(const float* __restrict__ w2, float* __restrict__ out) {
    __shared__ float Ah[64*GSTR], Bh[64*GSTR];
    const int b = blockIdx.z, l0 = blockIdx.x * 64, co0 = blockIdx.y * 64;
    const int tid = threadIdx.x, w8 = tid >> 5, lane = tid & 31;
    const int gid = lane >> 2, tig = lane & 3;
    const int m0 = (w8 >> 1) * 16, ch = w8 & 1, n0c = ch * 32;
    const int lrow = tid >> 3, cq = (tid & 7) * 4;
    const int ra = m0 + gid, rb = ra + 8;
    float acc[4][4] = {};

    for (int c0 = 0; c0 < C_; c0 += 32) {
        const int hh = c0 >> 6, d0 = c0 & 63;
        const size_t bbase = ((size_t)(b * NH_ + hh) * L_ + l0) * D_ + d0;
#pragma unroll
        for (int r = lrow; r < 64; r += 32) {
            float4 wv = *reinterpret_cast<const float4*>(&w2[(size_t)(co0 + r) * C_ + c0 + cq]);
            Ah[r*GSTR+cq+0] = tfb(wv.x); Ah[r*GSTR+cq+1] = tfb(wv.y);
            Ah[r*GSTR+cq+2] = tfb(wv.z); Ah[r*GSTR+cq+3] = tfb(wv.w);
            float4 v = *reinterpret_cast<const float4*>(&g_obuf[bbase + (size_t)r * D_ + cq]);
            float4 u = *reinterpret_cast<const float4*>(&g_olin[bbase + (size_t)r * D_ + cq]);
            Bh[r*GSTR+cq+0] = tfb(v.x + u.x); Bh[r*GSTR+cq+1] = tfb(v.y + u.y);
            Bh[r*GSTR+cq+2] = tfb(v.z + u.z); Bh[r*GSTR+cq+3] = tfb(v.w + u.w);
        }
        __syncthreads();
#pragma unroll
        for (int kk = 0; kk < 32; kk += 8) {
            unsigned ah[4];
            ah[0] = __float_as_uint(Ah[ra*GSTR + kk + tig]);
            ah[1] = __float_as_uint(Ah[rb*GSTR + kk + tig]);
            ah[2] = __float_as_uint(Ah[ra*GSTR + kk + tig + 4]);
            ah[3] = __float_as_uint(Ah[rb*GSTR + kk + tig + 4]);
#pragma unroll
            for (int j = 0; j < 4; j++) {
                const int br = (n0c + 8*j + gid) * GSTR + kk + tig;
                unsigned bh2[2];
                bh2[0] = __float_as_uint(Bh[br]); bh2[1] = __float_as_uint(Bh[br + 4]);
                mma8(acc[j], ah, bh2);
            }
        }
        __syncthreads();
    }
    float* ob = out + (size_t)b * C_ * L_;
#pragma unroll
    for (int j = 0; j < 4; j++) {
        *reinterpret_cast<float2*>(&ob[(size_t)(co0 + ra) * L_ + l0 + n0c + 8*j + 2*tig]) =
            make_float2(acc[j][0], acc[j][1]);
        *reinterpret_cast<float2*>(&ob[(size_t)(co0 + rb) * L_ + l0 + n0c + 8*j + 2*tig]) =
            make_float2(acc[j][2], acc[j][3]);
    }
}

// ---------------- launch: two-branch stream fork inside graph capture ----------------
extern "C" void kernel_launch(void* const* d_in, const int* in_sizes, int n_in,
                              void* d_out, int out_size) {
    const float* x     = (const float*)d_in[0];
    const float* qkv_w = (const float*)d_in[1];
    const float* out_w = (const float*)d_in[2];
    const float* plw   = (const float*)d_in[3];
    const float* plb   = (const float*)d_in[4];
    float* out = (float*)d_out;

    static cudaStream_t s2 = nullptr;
    static cudaEvent_t evFork = nullptr, evT = nullptr, evQ = nullptr, evJoin = nullptr;
    if (s2 == nullptr) {
        cudaStreamCreateWithFlags(&s2, cudaStreamNonBlocking);
        cudaEventCreateWithFlags(&evFork, cudaEventDisableTiming);
        cudaEventCreateWithFlags(&evT,    cudaEventDisableTiming);
        cudaEventCreateWithFlags(&evQ,    cudaEventDisableTiming);
        cudaEventCreateWithFlags(&evJoin, cudaEventDisableTiming);
        cudaFuncSetAttribute(k_sattn, cudaFuncAttributeMaxDynamicSharedMemorySize,
                             SATTN_SMEM_FLOATS * (int)sizeof(float));
        cudaFuncSetAttribute(k_qkv_tc, cudaFuncAttributeMaxDynamicSharedMemorySize,
                             QKV_SMEM_FLOATS * (int)sizeof(float));
    }
    const int sattn_smem = SATTN_SMEM_FLOATS * (int)sizeof(float); // 54272 B
    const int qkv_smem   = QKV_SMEM_FLOATS * (int)sizeof(float);   // 37888 B

    cudaEventRecord(evFork, 0);
    cudaStreamWaitEvent(s2, evFork, 0);

    // branch B: exact block-mean path -> topk (independent of qkv)
    k_xbar<<<dim3(B_, NB_), 256, 0, s2>>>(x);
    k_qbkb<<<dim3(8, 1, B_), 256, 0, s2>>>(qkv_w);
    k_topk<<<dim3(BH_, 8), 256, 0, s2>>>();
    cudaEventRecord(evT, s2);

    // branch A: x transpose -> fused qkv (plain tf32, pre-rounded/scaled outputs)
    k_xT<<<dim3(L_ / 32, C_ / 32, B_), dim3(32, 8)>>>(x);
    k_qkv_tc<<<dim3(L_ / 64, NH_, B_), 256, qkv_smem>>>(qkv_w);
    cudaEventRecord(evQ, 0);

    // branch B: kvb + totals + lin (o_l path), overlapped with sattn
    cudaStreamWaitEvent(s2, evQ, 0);
    k_kvb   <<<dim3(NB_, BH_), 256, 0, s2>>>();
    k_totals<<<dim3(BH_, 9), 256, 0, s2>>>();
    k_lin   <<<dim3(NB_, BH_), 256, 0, s2>>>(plw, plb);
    cudaEventRecord(evJoin, s2);

    // branch A: sattn (needs lut from branch B + q/k/v from program order)
    cudaStreamWaitEvent(0, evT, 0);
    k_sattn<<<dim3(NB_, BH_), 256, sattn_smem>>>();

    // join, then out_proj (plain tf32)
    cudaStreamWaitEvent(0, evJoin, 0);
    k_outproj_tc<<<dim3(L_ / 64, C_ / 64, B_), 256>>>(out_w, out);
}